// round 1
// baseline (speedup 1.0000x reference)
#include <cuda_runtime.h>

#define Q    2048
#define H    2048
#define NH   16
#define NKV  8
#define HD   128
#define PAST 2048
#define KEPS 1e-6f

// ---------------- scratch (no allocation allowed) ----------------
__device__ float g_qtmp[Q * NH * HD];    // q projection, [Q][NH*HD]
__device__ float g_ktmp[Q * NKV * HD];   // k projection, [Q][NKV*HD]
__device__ float g_q[NH * Q * HD];       // q after norm+rope, [NH][Q][HD]
__device__ float g_attn[Q * NH * HD];    // attention output, [Q][NH*HD]

// ---------------- SGEMM: C[M,N] = A[M,K] * B[N,K]^T ----------------
// 128x128 tile, BK=8, 256 threads, 8x8 microtile.
// mode 0: C[m*N+n]   mode 1: C[(n>>7)*Q*HD + m*HD + (n&127)]  (kv transpose)
__global__ __launch_bounds__(256) void sgemm_nt(
    const float* __restrict__ A, const float* __restrict__ B,
    float* __restrict__ C, int M, int N, int K, int mode)
{
    __shared__ float As[8][128];
    __shared__ float Bs[8][128];
    int tid = threadIdx.x;
    int tx = tid & 15, ty = tid >> 4;
    int loadRow = tid >> 1;
    int loadCol = (tid & 1) << 2;

    const float* Aptr = A + (size_t)(blockIdx.y * 128 + loadRow) * K + loadCol;
    const float* Bptr = B + (size_t)(blockIdx.x * 128 + loadRow) * K + loadCol;

    float acc[8][8];
#pragma unroll
    for (int i = 0; i < 8; i++)
#pragma unroll
        for (int j = 0; j < 8; j++) acc[i][j] = 0.0f;

    for (int kt = 0; kt < K; kt += 8) {
        float4 a4 = *(const float4*)(Aptr + kt);
        float4 b4 = *(const float4*)(Bptr + kt);
        __syncthreads();
        As[loadCol + 0][loadRow] = a4.x;
        As[loadCol + 1][loadRow] = a4.y;
        As[loadCol + 2][loadRow] = a4.z;
        As[loadCol + 3][loadRow] = a4.w;
        Bs[loadCol + 0][loadRow] = b4.x;
        Bs[loadCol + 1][loadRow] = b4.y;
        Bs[loadCol + 2][loadRow] = b4.z;
        Bs[loadCol + 3][loadRow] = b4.w;
        __syncthreads();
#pragma unroll
        for (int k = 0; k < 8; k++) {
            float a[8], b[8];
            *(float4*)(a)     = *(const float4*)&As[k][ty * 8];
            *(float4*)(a + 4) = *(const float4*)&As[k][ty * 8 + 4];
            *(float4*)(b)     = *(const float4*)&Bs[k][tx * 8];
            *(float4*)(b + 4) = *(const float4*)&Bs[k][tx * 8 + 4];
#pragma unroll
            for (int i = 0; i < 8; i++)
#pragma unroll
                for (int j = 0; j < 8; j++) acc[i][j] += a[i] * b[j];
        }
    }

#pragma unroll
    for (int i = 0; i < 8; i++) {
        int row = blockIdx.y * 128 + ty * 8 + i;
#pragma unroll
        for (int j = 0; j < 8; j++) {
            int col = blockIdx.x * 128 + tx * 8 + j;
            if (mode == 0)
                C[(size_t)row * N + col] = acc[i][j];
            else
                C[(size_t)(col >> 7) * (Q * HD) + (size_t)row * HD + (col & 127)] = acc[i][j];
        }
    }
}

// ---------------- RMSNorm + RoPE ----------------
// grid (Q, NH+NKV), 128 threads (one per hd element)
__global__ __launch_bounds__(128) void norm_rope(
    const float* __restrict__ qtmp, const float* __restrict__ ktmp,
    const float* __restrict__ cosb, const float* __restrict__ sinb,
    const float* __restrict__ qw, const float* __restrict__ kw,
    float* __restrict__ gq, float* __restrict__ newK)
{
    int s = blockIdx.x;
    int hh = blockIdx.y;
    int t = threadIdx.x;

    const float* src;
    float* dst;
    const float* w;
    if (hh < NH) {
        src = qtmp + (size_t)s * (NH * HD) + hh * HD;
        dst = gq + ((size_t)hh * Q + s) * HD;
        w = qw;
    } else {
        int kv = hh - NH;
        src = ktmp + (size_t)s * (NKV * HD) + kv * HD;
        dst = newK + ((size_t)kv * Q + s) * HD;
        w = kw;
    }

    float x = src[t];
    float v = x * x;
#pragma unroll
    for (int o = 16; o; o >>= 1) v += __shfl_xor_sync(0xffffffffu, v, o);
    __shared__ float red[4];
    if ((t & 31) == 0) red[t >> 5] = v;
    __syncthreads();
    float sum = red[0] + red[1] + red[2] + red[3];
    float rs = rsqrtf(sum * (1.0f / HD) + KEPS);
    float xn = x * rs * w[t];

    __shared__ float sh[HD];
    sh[t] = xn;
    __syncthreads();
    float c = cosb[(size_t)s * HD + t];
    float si = sinb[(size_t)s * HD + t];
    float rot = (t < 64) ? -sh[t + 64] : sh[t - 64];
    dst[t] = xn * c + rot * si;
}

// ---------------- Flash attention ----------------
// grid (NH, Q/32), 128 threads. TQ=TK=32. K and V share one SMEM buffer.
#define TQ 32
#define TK 32
#define QPAD (HD + 4)

__global__ __launch_bounds__(128) void attn_kernel(
    const float* __restrict__ gq, const float* __restrict__ pastK,
    const float* __restrict__ pastV, const float* __restrict__ newK,
    const float* __restrict__ newV, float* __restrict__ out)
{
    int h = blockIdx.x;
    int q0 = blockIdx.y * TQ;
    int kvh = h >> 1;   // NH/NKV = 2
    int tid = threadIdx.x;

    __shared__ float Qs[TQ][QPAD];
    __shared__ float KVs[TK][QPAD];
    __shared__ float Ps[TQ][TQ + 1];
    __shared__ float s_corr[TQ];
    __shared__ float s_l[TQ];

    // load Q tile: gq[h][q0+r][:]
    const float* qbase = gq + ((size_t)h * Q + q0) * HD;
    for (int i = tid; i < TQ * (HD / 4); i += 128) {
        int r = i >> 5, c = i & 31;
        *(float4*)&Qs[r][c * 4] = ((const float4*)qbase)[i];
    }

    // score-phase mapping: 2 rows x 4 cols per thread
    int sc_tx = tid & 7;        // col group (4 cols)
    int sc_r = (tid >> 3) * 2;  // row pair
    // pv-phase mapping: 4 rows (stride 8) x 8 dims per thread
    int pv_tr = tid >> 4;       // rows pv_tr + 8*i
    int pv_tc = tid & 15;       // dims [pv_tc*8, +8)

    float acc[4][8];
#pragma unroll
    for (int i = 0; i < 4; i++)
#pragma unroll
        for (int j = 0; j < 8; j++) acc[i][j] = 0.0f;
    float m_reg[2] = {-1e30f, -1e30f};
    float l_reg[2] = {0.0f, 0.0f};

    const float scale = 0.08838834764831845f;  // 1/sqrt(128)
    int n_tiles = (q0 + TQ - 1 + PAST) / TK + 1;

    __syncthreads();

    for (int jt = 0; jt < n_tiles; jt++) {
        int j0 = jt * TK;
        // ---- load K tile ----
        const float* ksrc = (j0 < PAST)
            ? pastK + ((size_t)kvh * PAST + j0) * HD
            : newK + ((size_t)kvh * Q + (j0 - PAST)) * HD;
        for (int i = tid; i < TK * (HD / 4); i += 128) {
            int r = i >> 5, c = i & 31;
            *(float4*)&KVs[r][c * 4] = ((const float4*)ksrc)[i];
        }
        __syncthreads();

        // ---- scores ----
        float sreg[2][4];
#pragma unroll
        for (int i = 0; i < 2; i++)
#pragma unroll
            for (int j = 0; j < 4; j++) sreg[i][j] = 0.0f;
#pragma unroll
        for (int d = 0; d < HD; d += 4) {
            float4 qa = *(const float4*)&Qs[sc_r][d];
            float4 qb = *(const float4*)&Qs[sc_r + 1][d];
#pragma unroll
            for (int j = 0; j < 4; j++) {
                float4 kv = *(const float4*)&KVs[sc_tx * 4 + j][d];
                sreg[0][j] += qa.x * kv.x + qa.y * kv.y + qa.z * kv.z + qa.w * kv.w;
                sreg[1][j] += qb.x * kv.x + qb.y * kv.y + qb.z * kv.z + qb.w * kv.w;
            }
        }
        // mask + scale
#pragma unroll
        for (int i = 0; i < 2; i++) {
            int qg = q0 + sc_r + i + PAST;
#pragma unroll
            for (int j = 0; j < 4; j++) {
                int jg = j0 + sc_tx * 4 + j;
                sreg[i][j] = (jg <= qg) ? sreg[i][j] * scale : -1e30f;
            }
        }
        // row max (across 8 threads of the row group)
        float tmax[2];
#pragma unroll
        for (int i = 0; i < 2; i++) {
            tmax[i] = fmaxf(fmaxf(sreg[i][0], sreg[i][1]), fmaxf(sreg[i][2], sreg[i][3]));
        }
#pragma unroll
        for (int o = 1; o < 8; o <<= 1) {
            tmax[0] = fmaxf(tmax[0], __shfl_xor_sync(0xffffffffu, tmax[0], o));
            tmax[1] = fmaxf(tmax[1], __shfl_xor_sync(0xffffffffu, tmax[1], o));
        }
        float mnew[2], corr[2], psum[2] = {0.0f, 0.0f};
#pragma unroll
        for (int i = 0; i < 2; i++) {
            mnew[i] = fmaxf(m_reg[i], tmax[i]);
            corr[i] = __expf(m_reg[i] - mnew[i]);
            m_reg[i] = mnew[i];
        }
#pragma unroll
        for (int i = 0; i < 2; i++) {
#pragma unroll
            for (int j = 0; j < 4; j++) {
                float p = __expf(sreg[i][j] - mnew[i]);
                Ps[sc_r + i][sc_tx * 4 + j] = p;
                psum[i] += p;
            }
        }
#pragma unroll
        for (int o = 1; o < 8; o <<= 1) {
            psum[0] += __shfl_xor_sync(0xffffffffu, psum[0], o);
            psum[1] += __shfl_xor_sync(0xffffffffu, psum[1], o);
        }
#pragma unroll
        for (int i = 0; i < 2; i++) l_reg[i] = l_reg[i] * corr[i] + psum[i];
        if (sc_tx == 0) {
            s_corr[sc_r] = corr[0];
            s_corr[sc_r + 1] = corr[1];
        }
        __syncthreads();  // P/corr ready, K reads done

        // ---- load V tile (overwrites KVs) ----
        const float* vsrc = (j0 < PAST)
            ? pastV + ((size_t)kvh * PAST + j0) * HD
            : newV + ((size_t)kvh * Q + (j0 - PAST)) * HD;
        for (int i = tid; i < TK * (HD / 4); i += 128) {
            int r = i >> 5, c = i & 31;
            *(float4*)&KVs[r][c * 4] = ((const float4*)vsrc)[i];
        }
        __syncthreads();

        // ---- PV update ----
#pragma unroll
        for (int i = 0; i < 4; i++) {
            float cr = s_corr[pv_tr + i * 8];
#pragma unroll
            for (int d = 0; d < 8; d++) acc[i][d] *= cr;
        }
#pragma unroll 4
        for (int j = 0; j < TK; j++) {
            float4 v0 = *(const float4*)&KVs[j][pv_tc * 8];
            float4 v1 = *(const float4*)&KVs[j][pv_tc * 8 + 4];
#pragma unroll
            for (int i = 0; i < 4; i++) {
                float p = Ps[pv_tr + i * 8][j];
                acc[i][0] += p * v0.x;
                acc[i][1] += p * v0.y;
                acc[i][2] += p * v0.z;
                acc[i][3] += p * v0.w;
                acc[i][4] += p * v1.x;
                acc[i][5] += p * v1.y;
                acc[i][6] += p * v1.z;
                acc[i][7] += p * v1.w;
            }
        }
        __syncthreads();  // before next tile overwrites KVs / Ps
    }

    if (sc_tx == 0) {
        s_l[sc_r] = l_reg[0];
        s_l[sc_r + 1] = l_reg[1];
    }
    __syncthreads();

#pragma unroll
    for (int i = 0; i < 4; i++) {
        int r = pv_tr + i * 8;
        float inv = 1.0f / s_l[r];
        float* dst = out + (size_t)(q0 + r) * (NH * HD) + h * HD + pv_tc * 8;
        float4 o0 = make_float4(acc[i][0] * inv, acc[i][1] * inv, acc[i][2] * inv, acc[i][3] * inv);
        float4 o1 = make_float4(acc[i][4] * inv, acc[i][5] * inv, acc[i][6] * inv, acc[i][7] * inv);
        *(float4*)(dst) = o0;
        *(float4*)(dst + 4) = o1;
    }
}

// ---------------- launch ----------------
extern "C" void kernel_launch(void* const* d_in, const int* in_sizes, int n_in,
                              void* d_out, int out_size)
{
    const float* hs    = (const float*)d_in[0];
    const float* cosb  = (const float*)d_in[1];
    const float* sinb  = (const float*)d_in[2];
    // d_in[3] = attention_mask (pure causal; computed analytically)
    const float* pastK = (const float*)d_in[4];
    const float* pastV = (const float*)d_in[5];
    const float* Wq    = (const float*)d_in[6];
    const float* Wk    = (const float*)d_in[7];
    const float* Wv    = (const float*)d_in[8];
    const float* Wo    = (const float*)d_in[9];
    const float* qw    = (const float*)d_in[10];
    const float* kw    = (const float*)d_in[11];

    float* out  = (float*)d_out;
    float* newK = out + (size_t)Q * NH * HD;          // 4,194,304
    float* newV = newK + (size_t)NKV * Q * HD;        // +2,097,152

    float *qtmp, *ktmp, *gq, *gattn;
    cudaGetSymbolAddress((void**)&qtmp, g_qtmp);
    cudaGetSymbolAddress((void**)&ktmp, g_ktmp);
    cudaGetSymbolAddress((void**)&gq, g_q);
    cudaGetSymbolAddress((void**)&gattn, g_attn);

    // projections
    sgemm_nt<<<dim3(NH * HD / 128, Q / 128), 256>>>(hs, Wq, qtmp, Q, NH * HD, H, 0);
    sgemm_nt<<<dim3(NKV * HD / 128, Q / 128), 256>>>(hs, Wk, ktmp, Q, NKV * HD, H, 0);
    sgemm_nt<<<dim3(NKV * HD / 128, Q / 128), 256>>>(hs, Wv, newV, Q, NKV * HD, H, 1);

    // rmsnorm + rope (q -> g_q, k -> new_key region of d_out)
    norm_rope<<<dim3(Q, NH + NKV), 128>>>(qtmp, ktmp, cosb, sinb, qw, kw, gq, newK);

    // flash attention
    attn_kernel<<<dim3(NH, Q / TQ), 128>>>(gq, pastK, pastV, newK, newV, gattn);

    // output projection
    sgemm_nt<<<dim3(NH * HD / 128, Q / 128), 256>>>(gattn, Wo, out, Q, NH * HD, NH * HD, 0);
}

// round 2
// speedup vs baseline: 1.6700x; 1.6700x over previous
#include <cuda_runtime.h>

#define Q    2048
#define H    2048
#define NH   16
#define NKV  8
#define HD   128
#define PAST 2048
#define KEPS 1e-6f

// ---------------- scratch (no allocation allowed) ----------------
__device__ float g_qtmp[Q * NH * HD];    // q projection, [Q][NH*HD]
__device__ float g_ktmp[Q * NKV * HD];   // k projection, [Q][NKV*HD]
__device__ float g_q[NH * Q * HD];       // q after norm+rope, [NH][Q][HD]
__device__ float g_attn[Q * NH * HD];    // attention output, [Q][NH*HD]

// ---------------- SGEMM: C[M,N] = A[M,K] * B[N,K]^T ----------------
// 128x128 tile, BK=8, 256 threads, 8x8 microtile, double-buffered SMEM.
// mode 0: C[m*N+n]   mode 1: C[(n>>7)*Q*HD + m*HD + (n&127)]  (kv transpose)
__global__ __launch_bounds__(256) void sgemm_nt(
    const float* __restrict__ A, const float* __restrict__ B,
    float* __restrict__ C, int M, int N, int K, int mode)
{
    __shared__ float As[2][8][128];
    __shared__ float Bs[2][8][128];
    int tid = threadIdx.x;
    int tx = tid & 15, ty = tid >> 4;
    int loadRow = tid >> 1;
    int loadCol = (tid & 1) << 2;

    const float* Aptr = A + (size_t)(blockIdx.y * 128 + loadRow) * K + loadCol;
    const float* Bptr = B + (size_t)(blockIdx.x * 128 + loadRow) * K + loadCol;

    float acc[8][8];
#pragma unroll
    for (int i = 0; i < 8; i++)
#pragma unroll
        for (int j = 0; j < 8; j++) acc[i][j] = 0.0f;

    // preload tile 0 into buffer 0
    float4 a4 = *(const float4*)(Aptr);
    float4 b4 = *(const float4*)(Bptr);
    As[0][loadCol + 0][loadRow] = a4.x;
    As[0][loadCol + 1][loadRow] = a4.y;
    As[0][loadCol + 2][loadRow] = a4.z;
    As[0][loadCol + 3][loadRow] = a4.w;
    Bs[0][loadCol + 0][loadRow] = b4.x;
    Bs[0][loadCol + 1][loadRow] = b4.y;
    Bs[0][loadCol + 2][loadRow] = b4.z;
    Bs[0][loadCol + 3][loadRow] = b4.w;
    __syncthreads();

    int buf = 0;
    for (int kt = 0; kt < K; kt += 8) {
        bool more = (kt + 8) < K;
        if (more) {
            a4 = *(const float4*)(Aptr + kt + 8);
            b4 = *(const float4*)(Bptr + kt + 8);
        }
#pragma unroll
        for (int k = 0; k < 8; k++) {
            float a[8], b[8];
            *(float4*)(a)     = *(const float4*)&As[buf][k][ty * 8];
            *(float4*)(a + 4) = *(const float4*)&As[buf][k][ty * 8 + 4];
            *(float4*)(b)     = *(const float4*)&Bs[buf][k][tx * 8];
            *(float4*)(b + 4) = *(const float4*)&Bs[buf][k][tx * 8 + 4];
#pragma unroll
            for (int i = 0; i < 8; i++)
#pragma unroll
                for (int j = 0; j < 8; j++) acc[i][j] += a[i] * b[j];
        }
        if (more) {
            int nb = buf ^ 1;
            As[nb][loadCol + 0][loadRow] = a4.x;
            As[nb][loadCol + 1][loadRow] = a4.y;
            As[nb][loadCol + 2][loadRow] = a4.z;
            As[nb][loadCol + 3][loadRow] = a4.w;
            Bs[nb][loadCol + 0][loadRow] = b4.x;
            Bs[nb][loadCol + 1][loadRow] = b4.y;
            Bs[nb][loadCol + 2][loadRow] = b4.z;
            Bs[nb][loadCol + 3][loadRow] = b4.w;
            __syncthreads();
            buf = nb;
        }
    }

#pragma unroll
    for (int i = 0; i < 8; i++) {
        int row = blockIdx.y * 128 + ty * 8 + i;
#pragma unroll
        for (int j = 0; j < 8; j++) {
            int col = blockIdx.x * 128 + tx * 8 + j;
            if (mode == 0)
                C[(size_t)row * N + col] = acc[i][j];
            else
                C[(size_t)(col >> 7) * (Q * HD) + (size_t)row * HD + (col & 127)] = acc[i][j];
        }
    }
}

// ---------------- RMSNorm + RoPE ----------------
// grid (Q, NH+NKV), 128 threads (one per hd element)
__global__ __launch_bounds__(128) void norm_rope(
    const float* __restrict__ qtmp, const float* __restrict__ ktmp,
    const float* __restrict__ cosb, const float* __restrict__ sinb,
    const float* __restrict__ qw, const float* __restrict__ kw,
    float* __restrict__ gq, float* __restrict__ newK)
{
    int s = blockIdx.x;
    int hh = blockIdx.y;
    int t = threadIdx.x;

    const float* src;
    float* dst;
    const float* w;
    if (hh < NH) {
        src = qtmp + (size_t)s * (NH * HD) + hh * HD;
        dst = gq + ((size_t)hh * Q + s) * HD;
        w = qw;
    } else {
        int kv = hh - NH;
        src = ktmp + (size_t)s * (NKV * HD) + kv * HD;
        dst = newK + ((size_t)kv * Q + s) * HD;
        w = kw;
    }

    float x = src[t];
    float v = x * x;
#pragma unroll
    for (int o = 16; o; o >>= 1) v += __shfl_xor_sync(0xffffffffu, v, o);
    __shared__ float red[4];
    if ((t & 31) == 0) red[t >> 5] = v;
    __syncthreads();
    float sum = red[0] + red[1] + red[2] + red[3];
    float rs = rsqrtf(sum * (1.0f / HD) + KEPS);
    float xn = x * rs * w[t];

    __shared__ float sh[HD];
    sh[t] = xn;
    __syncthreads();
    float c = cosb[(size_t)s * HD + t];
    float si = sinb[(size_t)s * HD + t];
    float rot = (t < 64) ? -sh[t + 64] : sh[t - 64];
    dst[t] = xn * c + rot * si;
}

// ---------------- Flash attention ----------------
// grid (NH, Q/64), 256 threads. TQ=TK=64. Dynamic smem, K/V share buffer.
#define TQ 64
#define TK 64
#define DPAD (HD + 4)

__global__ __launch_bounds__(256) void attn_kernel(
    const float* __restrict__ gq, const float* __restrict__ pastK,
    const float* __restrict__ pastV, const float* __restrict__ newK,
    const float* __restrict__ newV, float* __restrict__ out)
{
    extern __shared__ float sm[];
    float (*Qs)[DPAD]   = (float(*)[DPAD])sm;
    float (*KVs)[DPAD]  = (float(*)[DPAD])(sm + TQ * DPAD);
    float (*Ps)[TK + 1] = (float(*)[TK + 1])(sm + 2 * TQ * DPAD);

    int h = blockIdx.x;
    int q0 = blockIdx.y * TQ;
    int kvh = h >> 1;   // NH/NKV = 2
    int tid = threadIdx.x;
    int tx = tid & 15;   // col group / dim group
    int ty = tid >> 4;   // row group (0..15)

    // load Q tile: gq[h][q0+r][:]  (64 rows x 128 floats = 2048 float4)
    const float* qbase = gq + ((size_t)h * Q + q0) * HD;
    for (int i = tid; i < TQ * (HD / 4); i += 256) {
        int r = i >> 5, c = (i & 31) << 2;
        *(float4*)&Qs[r][c] = ((const float4*)qbase)[i];
    }

    float acc[4][8];
#pragma unroll
    for (int i = 0; i < 4; i++)
#pragma unroll
        for (int d = 0; d < 8; d++) acc[i][d] = 0.0f;
    float m_reg[4] = {-1e30f, -1e30f, -1e30f, -1e30f};
    float l_reg[4] = {0.0f, 0.0f, 0.0f, 0.0f};

    const float scale = 0.08838834764831845f;  // 1/sqrt(128)
    int n_tiles = (PAST + q0) / TK + 1;

    __syncthreads();

    for (int jt = 0; jt < n_tiles; jt++) {
        int j0 = jt * TK;
        // ---- load K tile ----
        const float* ksrc = (j0 < PAST)
            ? pastK + ((size_t)kvh * PAST + j0) * HD
            : newK + ((size_t)kvh * Q + (j0 - PAST)) * HD;
        for (int i = tid; i < TK * (HD / 4); i += 256) {
            int r = i >> 5, c = (i & 31) << 2;
            *(float4*)&KVs[r][c] = ((const float4*)ksrc)[i];
        }
        __syncthreads();

        // ---- scores: rows ty+16i, cols tx+16j (strided 4x4) ----
        float sreg[4][4];
#pragma unroll
        for (int i = 0; i < 4; i++)
#pragma unroll
            for (int j = 0; j < 4; j++) sreg[i][j] = 0.0f;
#pragma unroll 4
        for (int d = 0; d < HD; d += 4) {
            float4 kb[4];
#pragma unroll
            for (int j = 0; j < 4; j++) kb[j] = *(const float4*)&KVs[tx + 16 * j][d];
#pragma unroll
            for (int i = 0; i < 4; i++) {
                float4 qa = *(const float4*)&Qs[ty + 16 * i][d];
#pragma unroll
                for (int j = 0; j < 4; j++) {
                    sreg[i][j] += qa.x * kb[j].x + qa.y * kb[j].y
                                + qa.z * kb[j].z + qa.w * kb[j].w;
                }
            }
        }
        // mask + scale
#pragma unroll
        for (int i = 0; i < 4; i++) {
            int qg = q0 + ty + 16 * i + PAST;
#pragma unroll
            for (int j = 0; j < 4; j++) {
                int cg = j0 + tx + 16 * j;
                sreg[i][j] = (cg <= qg) ? sreg[i][j] * scale : -1e30f;
            }
        }
        // online softmax (reduce across the 16 tx lanes of the row group)
        float tmax[4];
#pragma unroll
        for (int i = 0; i < 4; i++)
            tmax[i] = fmaxf(fmaxf(sreg[i][0], sreg[i][1]), fmaxf(sreg[i][2], sreg[i][3]));
#pragma unroll
        for (int o = 1; o < 16; o <<= 1) {
#pragma unroll
            for (int i = 0; i < 4; i++)
                tmax[i] = fmaxf(tmax[i], __shfl_xor_sync(0xffffffffu, tmax[i], o));
        }
        float corr[4], psum[4];
#pragma unroll
        for (int i = 0; i < 4; i++) {
            float mnew = fmaxf(m_reg[i], tmax[i]);
            corr[i] = __expf(m_reg[i] - mnew);
            m_reg[i] = mnew;
            psum[i] = 0.0f;
#pragma unroll
            for (int j = 0; j < 4; j++) {
                float p = __expf(sreg[i][j] - mnew);
                Ps[ty + 16 * i][tx + 16 * j] = p;
                psum[i] += p;
            }
        }
#pragma unroll
        for (int o = 1; o < 16; o <<= 1) {
#pragma unroll
            for (int i = 0; i < 4; i++)
                psum[i] += __shfl_xor_sync(0xffffffffu, psum[i], o);
        }
#pragma unroll
        for (int i = 0; i < 4; i++) l_reg[i] = l_reg[i] * corr[i] + psum[i];

        __syncthreads();  // P ready; everyone done reading K

        // ---- load V tile (overwrites KVs) ----
        const float* vsrc = (j0 < PAST)
            ? pastV + ((size_t)kvh * PAST + j0) * HD
            : newV + ((size_t)kvh * Q + (j0 - PAST)) * HD;
        for (int i = tid; i < TK * (HD / 4); i += 256) {
            int r = i >> 5, c = (i & 31) << 2;
            *(float4*)&KVs[r][c] = ((const float4*)vsrc)[i];
        }
        __syncthreads();

        // ---- PV update: rows ty+16i, dims tx*8..+7 ----
#pragma unroll
        for (int i = 0; i < 4; i++) {
            float cr = corr[i];
#pragma unroll
            for (int d = 0; d < 8; d++) acc[i][d] *= cr;
        }
#pragma unroll 4
        for (int j = 0; j < TK; j++) {
            float4 v0 = *(const float4*)&KVs[j][tx * 8];
            float4 v1 = *(const float4*)&KVs[j][tx * 8 + 4];
#pragma unroll
            for (int i = 0; i < 4; i++) {
                float p = Ps[ty + 16 * i][j];
                acc[i][0] += p * v0.x;
                acc[i][1] += p * v0.y;
                acc[i][2] += p * v0.z;
                acc[i][3] += p * v0.w;
                acc[i][4] += p * v1.x;
                acc[i][5] += p * v1.y;
                acc[i][6] += p * v1.z;
                acc[i][7] += p * v1.w;
            }
        }
        __syncthreads();  // before next tile overwrites KVs / Ps
    }

#pragma unroll
    for (int i = 0; i < 4; i++) {
        int r = ty + 16 * i;
        float inv = 1.0f / l_reg[i];
        float* dst = out + (size_t)(q0 + r) * (NH * HD) + h * HD + tx * 8;
        float4 o0 = make_float4(acc[i][0] * inv, acc[i][1] * inv, acc[i][2] * inv, acc[i][3] * inv);
        float4 o1 = make_float4(acc[i][4] * inv, acc[i][5] * inv, acc[i][6] * inv, acc[i][7] * inv);
        *(float4*)(dst) = o0;
        *(float4*)(dst + 4) = o1;
    }
}

#define ATTN_SMEM_BYTES ((2 * TQ * DPAD + TQ * (TK + 1)) * 4)

// ---------------- launch ----------------
extern "C" void kernel_launch(void* const* d_in, const int* in_sizes, int n_in,
                              void* d_out, int out_size)
{
    const float* hs    = (const float*)d_in[0];
    const float* cosb  = (const float*)d_in[1];
    const float* sinb  = (const float*)d_in[2];
    // d_in[3] = attention_mask (pure causal; computed analytically)
    const float* pastK = (const float*)d_in[4];
    const float* pastV = (const float*)d_in[5];
    const float* Wq    = (const float*)d_in[6];
    const float* Wk    = (const float*)d_in[7];
    const float* Wv    = (const float*)d_in[8];
    const float* Wo    = (const float*)d_in[9];
    const float* qw    = (const float*)d_in[10];
    const float* kw    = (const float*)d_in[11];

    float* out  = (float*)d_out;
    float* newK = out + (size_t)Q * NH * HD;          // 4,194,304
    float* newV = newK + (size_t)NKV * Q * HD;        // +2,097,152

    float *qtmp, *ktmp, *gq, *gattn;
    cudaGetSymbolAddress((void**)&qtmp, g_qtmp);
    cudaGetSymbolAddress((void**)&ktmp, g_ktmp);
    cudaGetSymbolAddress((void**)&gq, g_q);
    cudaGetSymbolAddress((void**)&gattn, g_attn);

    static int smem_set = 0;
    if (!smem_set) {
        cudaFuncSetAttribute(attn_kernel,
                             cudaFuncAttributeMaxDynamicSharedMemorySize,
                             ATTN_SMEM_BYTES);
        smem_set = 1;
    }

    // projections
    sgemm_nt<<<dim3(NH * HD / 128, Q / 128), 256>>>(hs, Wq, qtmp, Q, NH * HD, H, 0);
    sgemm_nt<<<dim3(NKV * HD / 128, Q / 128), 256>>>(hs, Wk, ktmp, Q, NKV * HD, H, 0);
    sgemm_nt<<<dim3(NKV * HD / 128, Q / 128), 256>>>(hs, Wv, newV, Q, NKV * HD, H, 1);

    // rmsnorm + rope (q -> g_q, k -> new_key region of d_out)
    norm_rope<<<dim3(Q, NH + NKV), 128>>>(qtmp, ktmp, cosb, sinb, qw, kw, gq, newK);

    // flash attention
    attn_kernel<<<dim3(NH, Q / TQ), 256, ATTN_SMEM_BYTES>>>(gq, pastK, pastV, newK, newV, gattn);

    // output projection
    sgemm_nt<<<dim3(NH * HD / 128, Q / 128), 256>>>(gattn, Wo, out, Q, NH * HD, NH * HD, 0);
}

// round 4
// speedup vs baseline: 2.1513x; 1.2882x over previous
#include <cuda_runtime.h>
#include <cuda_bf16.h>
#include <cstdint>

#define Q    2048
#define H    2048
#define NH   16
#define NKV  8
#define HD   128
#define PAST 2048
#define KEPS 1e-6f

// ---------------- scratch (no allocation allowed) ----------------
__device__ float g_qtmp[Q * NH * HD];    // q projection, [Q][NH*HD]
__device__ float g_ktmp[Q * NKV * HD];   // k projection, [Q][NKV*HD]
__device__ float g_q[NH * Q * HD];       // q after norm+rope, [NH][Q][HD]
__device__ float g_attn[Q * NH * HD];    // attention output, [Q][NH*HD]

// ---------------- helpers ----------------
__device__ __forceinline__ uint32_t smem_u32(const void* p) {
    uint32_t a;
    asm("{ .reg .u64 t; cvta.to.shared.u64 t, %1; cvt.u32.u64 %0, t; }"
        : "=r"(a) : "l"(p));
    return a;
}
__device__ __forceinline__ uint32_t packbf(__nv_bfloat16 a, __nv_bfloat16 b) {
    return (uint32_t)__bfloat16_as_ushort(a) | ((uint32_t)__bfloat16_as_ushort(b) << 16);
}
__device__ __forceinline__ void ldsm4(uint32_t* r, uint32_t addr) {
    asm volatile("ldmatrix.sync.aligned.m8n8.x4.shared.b16 {%0,%1,%2,%3}, [%4];"
                 : "=r"(r[0]), "=r"(r[1]), "=r"(r[2]), "=r"(r[3]) : "r"(addr));
}
__device__ __forceinline__ void mma_bf16(float* c, const uint32_t* a, const uint32_t* b) {
    asm volatile(
        "mma.sync.aligned.m16n8k16.row.col.f32.bf16.bf16.f32 "
        "{%0,%1,%2,%3}, {%4,%5,%6,%7}, {%8,%9}, {%0,%1,%2,%3};"
        : "+f"(c[0]), "+f"(c[1]), "+f"(c[2]), "+f"(c[3])
        : "r"(a[0]), "r"(a[1]), "r"(a[2]), "r"(a[3]), "r"(b[0]), "r"(b[1]));
}

// split fp32x16 (4 float4) into bf16 hi/lo planes, store 32B per plane
__device__ __forceinline__ void split_store(char* dst_hi, char* dst_lo, const float4* v) {
    uint32_t hi[8], lo[8];
#pragma unroll
    for (int i = 0; i < 4; i++) {
        const float* f = (const float*)&v[i];
        __nv_bfloat16 h0 = __float2bfloat16_rn(f[0]);
        __nv_bfloat16 h1 = __float2bfloat16_rn(f[1]);
        __nv_bfloat16 h2 = __float2bfloat16_rn(f[2]);
        __nv_bfloat16 h3 = __float2bfloat16_rn(f[3]);
        __nv_bfloat16 l0 = __float2bfloat16_rn(f[0] - __bfloat162float(h0));
        __nv_bfloat16 l1 = __float2bfloat16_rn(f[1] - __bfloat162float(h1));
        __nv_bfloat16 l2 = __float2bfloat16_rn(f[2] - __bfloat162float(h2));
        __nv_bfloat16 l3 = __float2bfloat16_rn(f[3] - __bfloat162float(h3));
        hi[2 * i]     = packbf(h0, h1);
        hi[2 * i + 1] = packbf(h2, h3);
        lo[2 * i]     = packbf(l0, l1);
        lo[2 * i + 1] = packbf(l2, l3);
    }
    *(uint4*)dst_hi        = ((uint4*)hi)[0];
    *(uint4*)(dst_hi + 16) = ((uint4*)hi)[1];
    *(uint4*)dst_lo        = ((uint4*)lo)[0];
    *(uint4*)(dst_lo + 16) = ((uint4*)lo)[1];
}

// ---------------- bf16-split mma.sync GEMM: C[M,N] = A[M,K] * B[N,K]^T ----------------
// 128x128 tile, BK=32, 256 threads (8 warps, 2x4), double-buffered bf16 hi/lo planes.
// mode 0: C[m*N+n]   mode 1: C[(n>>7)*Q*HD + m*HD + (n&127)]  (kv transpose)
#define ROWB   80        // bytes per smem row (40 bf16: 32 data + 8 pad)
#define PLANEB 10240     // 128 rows * 80B
#define STAGEB 40960     // 4 planes: Ahi Alo Bhi Blo
#define HG_SMEM (2 * STAGEB)

__global__ __launch_bounds__(256) void hgemm(
    const float* __restrict__ A, const float* __restrict__ B,
    float* __restrict__ C, int M, int N, int K, int mode)
{
    extern __shared__ char hsm[];
    const int tid = threadIdx.x;
    const int lane = tid & 31;
    const int wid = tid >> 5;
    const int wm = wid >> 2;   // 0..1 -> m offset *64
    const int wn = wid & 3;    // 0..3 -> n offset *32

    const uint32_t base_u = smem_u32(hsm);

    // global load mapping: row = tid>>1, 16-float segment = tid&1
    const int lrow = tid >> 1;
    const int lseg = tid & 1;
    const float* Ap = A + (size_t)(blockIdx.y * 128 + lrow) * K + lseg * 16;
    const float* Bp = B + (size_t)(blockIdx.x * 128 + lrow) * K + lseg * 16;
    const uint32_t stoff = (uint32_t)(lrow * ROWB + lseg * 32);

    // ldmatrix address components
    const int rowselA = (lane & 7) + ((lane >> 3) & 1) * 8;
    const int halfA = lane >> 4;
    const int rowselB = (lane & 7) + (lane >> 4) * 8;
    const int halfB = (lane >> 3) & 1;
    const uint32_t aoff0 = (uint32_t)(((wm * 64 + rowselA) * 40 + halfA * 8) * 2);
    const uint32_t boff0 = (uint32_t)(((wn * 32 + rowselB) * 40 + halfB * 8) * 2);

    float acc[4][4][4];
#pragma unroll
    for (int i = 0; i < 4; i++)
#pragma unroll
        for (int j = 0; j < 4; j++)
#pragma unroll
            for (int r = 0; r < 4; r++) acc[i][j][r] = 0.0f;

    // preload stage 0
    float4 pa[4], pb[4];
#pragma unroll
    for (int i = 0; i < 4; i++) {
        pa[i] = *(const float4*)(Ap + i * 4);
        pb[i] = *(const float4*)(Bp + i * 4);
    }
    split_store(hsm + stoff, hsm + PLANEB + stoff, pa);
    split_store(hsm + 2 * PLANEB + stoff, hsm + 3 * PLANEB + stoff, pb);
    __syncthreads();

    const int nst = K / 32;
    for (int s = 0; s < nst; s++) {
        const int buf = s & 1;
        const uint32_t sb = base_u + buf * STAGEB;
        const bool more = (s + 1) < nst;
        if (more) {
            int kt = (s + 1) * 32;
#pragma unroll
            for (int i = 0; i < 4; i++) {
                pa[i] = *(const float4*)(Ap + kt + i * 4);
                pb[i] = *(const float4*)(Bp + kt + i * 4);
            }
        }

#pragma unroll
        for (int kc = 0; kc < 2; kc++) {
            uint32_t ah[4][4], al[4][4];
#pragma unroll
            for (int mi = 0; mi < 4; mi++) {
                uint32_t ad = sb + aoff0 + mi * 1280 + kc * 32;
                ldsm4(ah[mi], ad);
                ldsm4(al[mi], ad + PLANEB);
            }
            uint32_t bh[4][2], bl[4][2];
#pragma unroll
            for (int p = 0; p < 2; p++) {
                uint32_t bd = sb + 2 * PLANEB + boff0 + p * 1280 + kc * 32;
                uint32_t r[4];
                ldsm4(r, bd);
                bh[2 * p][0] = r[0]; bh[2 * p][1] = r[1];
                bh[2 * p + 1][0] = r[2]; bh[2 * p + 1][1] = r[3];
                ldsm4(r, bd + PLANEB);
                bl[2 * p][0] = r[0]; bl[2 * p][1] = r[1];
                bl[2 * p + 1][0] = r[2]; bl[2 * p + 1][1] = r[3];
            }
#pragma unroll
            for (int mi = 0; mi < 4; mi++) {
#pragma unroll
                for (int nj = 0; nj < 4; nj++) {
                    mma_bf16(acc[mi][nj], ah[mi], bh[nj]);
                    mma_bf16(acc[mi][nj], ah[mi], bl[nj]);
                    mma_bf16(acc[mi][nj], al[mi], bh[nj]);
                }
            }
        }

        if (more) {
            char* nb = hsm + (buf ^ 1) * STAGEB;
            split_store(nb + stoff, nb + PLANEB + stoff, pa);
            split_store(nb + 2 * PLANEB + stoff, nb + 3 * PLANEB + stoff, pb);
            __syncthreads();
        }
    }

    // epilogue
    const int rfrag = lane >> 2;
    const int cpair = (lane & 3) * 2;
#pragma unroll
    for (int mi = 0; mi < 4; mi++) {
#pragma unroll
        for (int nj = 0; nj < 4; nj++) {
            int colg = blockIdx.x * 128 + wn * 32 + nj * 8 + cpair;
#pragma unroll
            for (int half = 0; half < 2; half++) {
                int rowg = blockIdx.y * 128 + wm * 64 + mi * 16 + rfrag + half * 8;
                float2 v = make_float2(acc[mi][nj][2 * half], acc[mi][nj][2 * half + 1]);
                if (mode == 0)
                    *(float2*)(C + (size_t)rowg * N + colg) = v;
                else
                    *(float2*)(C + (size_t)(colg >> 7) * (Q * HD) + (size_t)rowg * HD + (colg & 127)) = v;
            }
        }
    }
}

// ---------------- RMSNorm + RoPE ----------------
__global__ __launch_bounds__(128) void norm_rope(
    const float* __restrict__ qtmp, const float* __restrict__ ktmp,
    const float* __restrict__ cosb, const float* __restrict__ sinb,
    const float* __restrict__ qw, const float* __restrict__ kw,
    float* __restrict__ gq, float* __restrict__ newK)
{
    int s = blockIdx.x;
    int hh = blockIdx.y;
    int t = threadIdx.x;

    const float* src;
    float* dst;
    const float* w;
    if (hh < NH) {
        src = qtmp + (size_t)s * (NH * HD) + hh * HD;
        dst = gq + ((size_t)hh * Q + s) * HD;
        w = qw;
    } else {
        int kv = hh - NH;
        src = ktmp + (size_t)s * (NKV * HD) + kv * HD;
        dst = newK + ((size_t)kv * Q + s) * HD;
        w = kw;
    }

    float x = src[t];
    float v = x * x;
#pragma unroll
    for (int o = 16; o; o >>= 1) v += __shfl_xor_sync(0xffffffffu, v, o);
    __shared__ float red[4];
    if ((t & 31) == 0) red[t >> 5] = v;
    __syncthreads();
    float sum = red[0] + red[1] + red[2] + red[3];
    float rs = rsqrtf(sum * (1.0f / HD) + KEPS);
    float xn = x * rs * w[t];

    __shared__ float sh[HD];
    sh[t] = xn;
    __syncthreads();
    float c = cosb[(size_t)s * HD + t];
    float si = sinb[(size_t)s * HD + t];
    float rot = (t < 64) ? -sh[t + 64] : sh[t - 64];
    dst[t] = xn * c + rot * si;
}

// ---------------- Flash attention (fp32, unchanged from round 2) ----------------
#define TQ 64
#define TK 64
#define DPAD (HD + 4)

__global__ __launch_bounds__(256) void attn_kernel(
    const float* __restrict__ gq, const float* __restrict__ pastK,
    const float* __restrict__ pastV, const float* __restrict__ newK,
    const float* __restrict__ newV, float* __restrict__ out)
{
    extern __shared__ float sm[];
    float (*Qs)[DPAD]   = (float(*)[DPAD])sm;
    float (*KVs)[DPAD]  = (float(*)[DPAD])(sm + TQ * DPAD);
    float (*Ps)[TK + 1] = (float(*)[TK + 1])(sm + 2 * TQ * DPAD);

    int h = blockIdx.x;
    int q0 = blockIdx.y * TQ;
    int kvh = h >> 1;
    int tid = threadIdx.x;
    int tx = tid & 15;
    int ty = tid >> 4;

    const float* qbase = gq + ((size_t)h * Q + q0) * HD;
    for (int i = tid; i < TQ * (HD / 4); i += 256) {
        int r = i >> 5, c = (i & 31) << 2;
        *(float4*)&Qs[r][c] = ((const float4*)qbase)[i];
    }

    float acc[4][8];
#pragma unroll
    for (int i = 0; i < 4; i++)
#pragma unroll
        for (int d = 0; d < 8; d++) acc[i][d] = 0.0f;
    float m_reg[4] = {-1e30f, -1e30f, -1e30f, -1e30f};
    float l_reg[4] = {0.0f, 0.0f, 0.0f, 0.0f};

    const float scale = 0.08838834764831845f;
    int n_tiles = (PAST + q0) / TK + 1;

    __syncthreads();

    for (int jt = 0; jt < n_tiles; jt++) {
        int j0 = jt * TK;
        const float* ksrc = (j0 < PAST)
            ? pastK + ((size_t)kvh * PAST + j0) * HD
            : newK + ((size_t)kvh * Q + (j0 - PAST)) * HD;
        for (int i = tid; i < TK * (HD / 4); i += 256) {
            int r = i >> 5, c = (i & 31) << 2;
            *(float4*)&KVs[r][c] = ((const float4*)ksrc)[i];
        }
        __syncthreads();

        float sreg[4][4];
#pragma unroll
        for (int i = 0; i < 4; i++)
#pragma unroll
            for (int j = 0; j < 4; j++) sreg[i][j] = 0.0f;
#pragma unroll 4
        for (int d = 0; d < HD; d += 4) {
            float4 kb[4];
#pragma unroll
            for (int j = 0; j < 4; j++) kb[j] = *(const float4*)&KVs[tx + 16 * j][d];
#pragma unroll
            for (int i = 0; i < 4; i++) {
                float4 qa = *(const float4*)&Qs[ty + 16 * i][d];
#pragma unroll
                for (int j = 0; j < 4; j++) {
                    sreg[i][j] += qa.x * kb[j].x + qa.y * kb[j].y
                                + qa.z * kb[j].z + qa.w * kb[j].w;
                }
            }
        }
#pragma unroll
        for (int i = 0; i < 4; i++) {
            int qg = q0 + ty + 16 * i + PAST;
#pragma unroll
            for (int j = 0; j < 4; j++) {
                int cg = j0 + tx + 16 * j;
                sreg[i][j] = (cg <= qg) ? sreg[i][j] * scale : -1e30f;
            }
        }
        float tmax[4];
#pragma unroll
        for (int i = 0; i < 4; i++)
            tmax[i] = fmaxf(fmaxf(sreg[i][0], sreg[i][1]), fmaxf(sreg[i][2], sreg[i][3]));
#pragma unroll
        for (int o = 1; o < 16; o <<= 1) {
#pragma unroll
            for (int i = 0; i < 4; i++)
                tmax[i] = fmaxf(tmax[i], __shfl_xor_sync(0xffffffffu, tmax[i], o));
        }
        float corr[4], psum[4];
#pragma unroll
        for (int i = 0; i < 4; i++) {
            float mnew = fmaxf(m_reg[i], tmax[i]);
            corr[i] = __expf(m_reg[i] - mnew);
            m_reg[i] = mnew;
            psum[i] = 0.0f;
#pragma unroll
            for (int j = 0; j < 4; j++) {
                float p = __expf(sreg[i][j] - mnew);
                Ps[ty + 16 * i][tx + 16 * j] = p;
                psum[i] += p;
            }
        }
#pragma unroll
        for (int o = 1; o < 16; o <<= 1) {
#pragma unroll
            for (int i = 0; i < 4; i++)
                psum[i] += __shfl_xor_sync(0xffffffffu, psum[i], o);
        }
#pragma unroll
        for (int i = 0; i < 4; i++) l_reg[i] = l_reg[i] * corr[i] + psum[i];

        __syncthreads();

        const float* vsrc = (j0 < PAST)
            ? pastV + ((size_t)kvh * PAST + j0) * HD
            : newV + ((size_t)kvh * Q + (j0 - PAST)) * HD;
        for (int i = tid; i < TK * (HD / 4); i += 256) {
            int r = i >> 5, c = (i & 31) << 2;
            *(float4*)&KVs[r][c] = ((const float4*)vsrc)[i];
        }
        __syncthreads();

#pragma unroll
        for (int i = 0; i < 4; i++) {
            float cr = corr[i];
#pragma unroll
            for (int d = 0; d < 8; d++) acc[i][d] *= cr;
        }
#pragma unroll 4
        for (int j = 0; j < TK; j++) {
            float4 v0 = *(const float4*)&KVs[j][tx * 8];
            float4 v1 = *(const float4*)&KVs[j][tx * 8 + 4];
#pragma unroll
            for (int i = 0; i < 4; i++) {
                float p = Ps[ty + 16 * i][j];
                acc[i][0] += p * v0.x;
                acc[i][1] += p * v0.y;
                acc[i][2] += p * v0.z;
                acc[i][3] += p * v0.w;
                acc[i][4] += p * v1.x;
                acc[i][5] += p * v1.y;
                acc[i][6] += p * v1.z;
                acc[i][7] += p * v1.w;
            }
        }
        __syncthreads();
    }

#pragma unroll
    for (int i = 0; i < 4; i++) {
        int r = ty + 16 * i;
        float inv = 1.0f / l_reg[i];
        float* dst = out + (size_t)(q0 + r) * (NH * HD) + h * HD + tx * 8;
        float4 o0 = make_float4(acc[i][0] * inv, acc[i][1] * inv, acc[i][2] * inv, acc[i][3] * inv);
        float4 o1 = make_float4(acc[i][4] * inv, acc[i][5] * inv, acc[i][6] * inv, acc[i][7] * inv);
        *(float4*)(dst) = o0;
        *(float4*)(dst + 4) = o1;
    }
}

#define ATTN_SMEM_BYTES ((2 * TQ * DPAD + TQ * (TK + 1)) * 4)

// ---------------- launch ----------------
extern "C" void kernel_launch(void* const* d_in, const int* in_sizes, int n_in,
                              void* d_out, int out_size)
{
    const float* hs    = (const float*)d_in[0];
    const float* cosb  = (const float*)d_in[1];
    const float* sinb  = (const float*)d_in[2];
    // d_in[3] = attention_mask (pure causal; computed analytically)
    const float* pastK = (const float*)d_in[4];
    const float* pastV = (const float*)d_in[5];
    const float* Wq    = (const float*)d_in[6];
    const float* Wk    = (const float*)d_in[7];
    const float* Wv    = (const float*)d_in[8];
    const float* Wo    = (const float*)d_in[9];
    const float* qw    = (const float*)d_in[10];
    const float* kw    = (const float*)d_in[11];

    float* out  = (float*)d_out;
    float* newK = out + (size_t)Q * NH * HD;
    float* newV = newK + (size_t)NKV * Q * HD;

    float *qtmp, *ktmp, *gq, *gattn;
    cudaGetSymbolAddress((void**)&qtmp, g_qtmp);
    cudaGetSymbolAddress((void**)&ktmp, g_ktmp);
    cudaGetSymbolAddress((void**)&gq, g_q);
    cudaGetSymbolAddress((void**)&gattn, g_attn);

    cudaFuncSetAttribute(hgemm, cudaFuncAttributeMaxDynamicSharedMemorySize, HG_SMEM);
    cudaFuncSetAttribute(attn_kernel, cudaFuncAttributeMaxDynamicSharedMemorySize,
                         ATTN_SMEM_BYTES);

    // projections (bf16-split mma.sync)
    hgemm<<<dim3(NH * HD / 128, Q / 128), 256, HG_SMEM>>>(hs, Wq, qtmp, Q, NH * HD, H, 0);
    hgemm<<<dim3(NKV * HD / 128, Q / 128), 256, HG_SMEM>>>(hs, Wk, ktmp, Q, NKV * HD, H, 0);
    hgemm<<<dim3(NKV * HD / 128, Q / 128), 256, HG_SMEM>>>(hs, Wv, newV, Q, NKV * HD, H, 1);

    // rmsnorm + rope
    norm_rope<<<dim3(Q, NH + NKV), 128>>>(qtmp, ktmp, cosb, sinb, qw, kw, gq, newK);

    // flash attention
    attn_kernel<<<dim3(NH, Q / TQ), 256, ATTN_SMEM_BYTES>>>(gq, pastK, pastV, newK, newV, gattn);

    // output projection
    hgemm<<<dim3(NH * HD / 128, Q / 128), 256, HG_SMEM>>>(gattn, Wo, out, Q, NH * HD, NH * HD, 0);
}

// round 5
// speedup vs baseline: 5.1002x; 2.3708x over previous
#include <cuda_runtime.h>
#include <cuda_bf16.h>
#include <cstdint>

#define Q    2048
#define H    2048
#define NH   16
#define NKV  8
#define HD   128
#define PAST 2048
#define KVLEN (PAST + Q)
#define KEPS 1e-6f

typedef __nv_bfloat16 bf16;

// ---------------- scratch (no allocation allowed) ----------------
__device__ float g_qtmp[Q * NH * HD];
__device__ float g_ktmp[Q * NKV * HD];
__device__ bf16 g_hs_hi[Q * H],            g_hs_lo[Q * H];
__device__ bf16 g_wq_hi[NH * HD * H],      g_wq_lo[NH * HD * H];
__device__ bf16 g_wk_hi[NKV * HD * H],     g_wk_lo[NKV * HD * H];
__device__ bf16 g_wv_hi[NKV * HD * H],     g_wv_lo[NKV * HD * H];
__device__ bf16 g_wo_hi[NH * HD * NH * HD], g_wo_lo[NH * HD * NH * HD];
__device__ bf16 g_q_hi[NH * Q * HD],       g_q_lo[NH * Q * HD];     // scaled by 1/sqrt(d)*log2e
__device__ bf16 g_k_hi[NKV * KVLEN * HD],  g_k_lo[NKV * KVLEN * HD];
__device__ bf16 g_v_hi[NKV * KVLEN * HD],  g_v_lo[NKV * KVLEN * HD];
__device__ bf16 g_ao_hi[Q * NH * HD],      g_ao_lo[Q * NH * HD];

// ---------------- helpers ----------------
__device__ __forceinline__ uint32_t smem_u32(const void* p) {
    uint32_t a;
    asm("{ .reg .u64 t; cvta.to.shared.u64 t, %1; cvt.u32.u64 %0, t; }" : "=r"(a) : "l"(p));
    return a;
}
__device__ __forceinline__ uint32_t packbf(bf16 a, bf16 b) {
    return (uint32_t)__bfloat16_as_ushort(a) | ((uint32_t)__bfloat16_as_ushort(b) << 16);
}
__device__ __forceinline__ void split2(float a, float b, uint32_t& hi, uint32_t& lo) {
    bf16 ha = __float2bfloat16_rn(a), hb = __float2bfloat16_rn(b);
    hi = packbf(ha, hb);
    lo = packbf(__float2bfloat16_rn(a - __bfloat162float(ha)),
                __float2bfloat16_rn(b - __bfloat162float(hb)));
}
__device__ __forceinline__ void ldsm4(uint32_t* r, uint32_t addr) {
    asm volatile("ldmatrix.sync.aligned.m8n8.x4.shared.b16 {%0,%1,%2,%3}, [%4];"
                 : "=r"(r[0]), "=r"(r[1]), "=r"(r[2]), "=r"(r[3]) : "r"(addr));
}
__device__ __forceinline__ void ldsm4t(uint32_t* r, uint32_t addr) {
    asm volatile("ldmatrix.sync.aligned.m8n8.x4.trans.shared.b16 {%0,%1,%2,%3}, [%4];"
                 : "=r"(r[0]), "=r"(r[1]), "=r"(r[2]), "=r"(r[3]) : "r"(addr));
}
__device__ __forceinline__ void mma_bf16(float* c, const uint32_t* a, const uint32_t* b) {
    asm volatile(
        "mma.sync.aligned.m16n8k16.row.col.f32.bf16.bf16.f32 "
        "{%0,%1,%2,%3}, {%4,%5,%6,%7}, {%8,%9}, {%0,%1,%2,%3};"
        : "+f"(c[0]), "+f"(c[1]), "+f"(c[2]), "+f"(c[3])
        : "r"(a[0]), "r"(a[1]), "r"(a[2]), "r"(a[3]), "r"(b[0]), "r"(b[1]));
}
__device__ __forceinline__ void cp16(uint32_t dst, const void* src) {
    asm volatile("cp.async.cg.shared.global [%0], [%1], 16;"
                 :: "r"(dst), "l"(__cvta_generic_to_global(src)));
}
__device__ __forceinline__ void cpcommit() { asm volatile("cp.async.commit_group;"); }
template <int N>
__device__ __forceinline__ void cpwait() {
    asm volatile("cp.async.wait_group %0;" :: "n"(N));
}
__device__ __forceinline__ float ex2(float x) {
    float y;
    asm("ex2.approx.f32 %0, %1;" : "=f"(y) : "f"(x));
    return y;
}

// ---------------- split kernels ----------------
__global__ __launch_bounds__(256) void ksplit(const float* __restrict__ x,
                                              bf16* __restrict__ hi, bf16* __restrict__ lo)
{
    int i = blockIdx.x * 256 + threadIdx.x;
    float4 v = ((const float4*)x)[i];
    uint32_t h0, l0, h1, l1;
    split2(v.x, v.y, h0, l0);
    split2(v.z, v.w, h1, l1);
    ((uint32_t*)hi)[2 * i] = h0;  ((uint32_t*)hi)[2 * i + 1] = h1;
    ((uint32_t*)lo)[2 * i] = l0;  ((uint32_t*)lo)[2 * i + 1] = l1;
}
// pastKV -> cache at [kv][0..PAST)
__global__ __launch_bounds__(256) void ksplit_cache(const float* __restrict__ x,
                                                    bf16* __restrict__ hi, bf16* __restrict__ lo)
{
    int i = blockIdx.x * 256 + threadIdx.x;
    int e = i * 4;
    int kv = e / (PAST * HD);
    int rem = e - kv * (PAST * HD);
    size_t de = (size_t)kv * (KVLEN * HD) + rem;
    float4 v = ((const float4*)x)[i];
    uint32_t h0, l0, h1, l1;
    split2(v.x, v.y, h0, l0);
    split2(v.z, v.w, h1, l1);
    *(uint32_t*)(hi + de) = h0;  *(uint32_t*)(hi + de + 2) = h1;
    *(uint32_t*)(lo + de) = l0;  *(uint32_t*)(lo + de + 2) = l1;
}

// ---------------- bf16 presplit GEMM: C = A[M,K] * B[N,K]^T ----------------
#define ROWB   80
#define PLANEB 10240
#define STAGEB 40960
#define HG_SMEM (2 * STAGEB)

__global__ __launch_bounds__(256) void hgemm(
    const bf16* __restrict__ Ahi, const bf16* __restrict__ Alo,
    const bf16* __restrict__ Bhi, const bf16* __restrict__ Blo,
    float* __restrict__ C, int M, int N, int K, int mode,
    bf16* __restrict__ vphi, bf16* __restrict__ vplo)
{
    extern __shared__ char hsm[];
    const int tid = threadIdx.x;
    const int lane = tid & 31;
    const int wid = tid >> 5;
    const int wm = wid >> 2;
    const int wn = wid & 3;
    const uint32_t base_u = smem_u32(hsm);

    const bf16* pl[4] = {
        Ahi + (size_t)(blockIdx.y * 128) * K, Alo + (size_t)(blockIdx.y * 128) * K,
        Bhi + (size_t)(blockIdx.x * 128) * K, Blo + (size_t)(blockIdx.x * 128) * K };

    const int rowselA = lane & 15;
    const int halfA = lane >> 4;
    const int rowselB = (lane & 7) + (lane >> 4) * 8;
    const int halfB = (lane >> 3) & 1;
    const uint32_t aoff0 = (uint32_t)((wm * 64 + rowselA) * ROWB + halfA * 16);
    const uint32_t boff0 = (uint32_t)((wn * 32 + rowselB) * ROWB + halfB * 16);

    float acc[4][4][4];
#pragma unroll
    for (int i = 0; i < 4; i++)
#pragma unroll
        for (int j = 0; j < 4; j++)
#pragma unroll
            for (int r = 0; r < 4; r++) acc[i][j][r] = 0.0f;

    const int nst = K / 32;
    // issue stage 0
    {
        uint32_t dstb = base_u;
        for (int i = tid; i < 2048; i += 256) {
            int p = i >> 9, row = (i >> 2) & 127, seg = i & 3;
            cp16(dstb + p * PLANEB + row * ROWB + seg * 16,
                 pl[p] + (size_t)row * K + seg * 8);
        }
        cpcommit();
    }

    for (int s = 0; s < nst; s++) {
        cpwait<0>();
        __syncthreads();
        if (s + 1 < nst) {
            int kt = (s + 1) * 32;
            uint32_t dstb = base_u + ((s + 1) & 1) * STAGEB;
            for (int i = tid; i < 2048; i += 256) {
                int p = i >> 9, row = (i >> 2) & 127, seg = i & 3;
                cp16(dstb + p * PLANEB + row * ROWB + seg * 16,
                     pl[p] + (size_t)row * K + kt + seg * 8);
            }
            cpcommit();
        }
        const uint32_t sb = base_u + (s & 1) * STAGEB;
#pragma unroll
        for (int kc = 0; kc < 2; kc++) {
            uint32_t ah[4][4], al[4][4];
#pragma unroll
            for (int mi = 0; mi < 4; mi++) {
                uint32_t ad = sb + aoff0 + mi * (16 * ROWB) + kc * 32;
                ldsm4(ah[mi], ad);
                ldsm4(al[mi], ad + PLANEB);
            }
            uint32_t bh[4][2], bl[4][2];
#pragma unroll
            for (int p = 0; p < 2; p++) {
                uint32_t bd = sb + 2 * PLANEB + boff0 + p * (16 * ROWB) + kc * 32;
                uint32_t r[4];
                ldsm4(r, bd);
                bh[2 * p][0] = r[0]; bh[2 * p][1] = r[1];
                bh[2 * p + 1][0] = r[2]; bh[2 * p + 1][1] = r[3];
                ldsm4(r, bd + PLANEB);
                bl[2 * p][0] = r[0]; bl[2 * p][1] = r[1];
                bl[2 * p + 1][0] = r[2]; bl[2 * p + 1][1] = r[3];
            }
#pragma unroll
            for (int mi = 0; mi < 4; mi++) {
#pragma unroll
                for (int nj = 0; nj < 4; nj++) {
                    mma_bf16(acc[mi][nj], ah[mi], bh[nj]);
                    mma_bf16(acc[mi][nj], ah[mi], bl[nj]);
                    mma_bf16(acc[mi][nj], al[mi], bh[nj]);
                }
            }
        }
    }

    // epilogue
    const int rfrag = lane >> 2;
    const int cpair = (lane & 3) * 2;
#pragma unroll
    for (int mi = 0; mi < 4; mi++) {
#pragma unroll
        for (int nj = 0; nj < 4; nj++) {
            int colg = blockIdx.x * 128 + wn * 32 + nj * 8 + cpair;
#pragma unroll
            for (int half = 0; half < 2; half++) {
                int rowg = blockIdx.y * 128 + wm * 64 + mi * 16 + rfrag + half * 8;
                float2 v = make_float2(acc[mi][nj][2 * half], acc[mi][nj][2 * half + 1]);
                if (mode == 0) {
                    *(float2*)(C + (size_t)rowg * N + colg) = v;
                } else {
                    int kv = colg >> 7, d = colg & 127;
                    *(float2*)(C + (size_t)kv * (Q * HD) + (size_t)rowg * HD + d) = v;
                    uint32_t hh, ll;
                    split2(v.x, v.y, hh, ll);
                    size_t de = (size_t)kv * (KVLEN * HD) + (size_t)(PAST + rowg) * HD + d;
                    *(uint32_t*)(vphi + de) = hh;
                    *(uint32_t*)(vplo + de) = ll;
                }
            }
        }
    }
}

// ---------------- RMSNorm + RoPE (+ split outputs) ----------------
__global__ __launch_bounds__(128) void norm_rope(
    const float* __restrict__ qtmp, const float* __restrict__ ktmp,
    const float* __restrict__ cosb, const float* __restrict__ sinb,
    const float* __restrict__ qw, const float* __restrict__ kw,
    bf16* __restrict__ qhi, bf16* __restrict__ qlo,
    float* __restrict__ newK,
    bf16* __restrict__ khi, bf16* __restrict__ klo)
{
    const float QSC = 0.08838834764831845f * 1.44269504088896341f;  // scale * log2e
    int s = blockIdx.x;
    int hh = blockIdx.y;
    int t = threadIdx.x;

    const float* src;
    const float* w;
    if (hh < NH) {
        src = qtmp + (size_t)s * (NH * HD) + hh * HD;
        w = qw;
    } else {
        src = ktmp + (size_t)s * (NKV * HD) + (hh - NH) * HD;
        w = kw;
    }

    float x = src[t];
    float v = x * x;
#pragma unroll
    for (int o = 16; o; o >>= 1) v += __shfl_xor_sync(0xffffffffu, v, o);
    __shared__ float red[4];
    if ((t & 31) == 0) red[t >> 5] = v;
    __syncthreads();
    float sum = red[0] + red[1] + red[2] + red[3];
    float rs = rsqrtf(sum * (1.0f / HD) + KEPS);
    float xn = x * rs * w[t];

    __shared__ float sh[HD];
    sh[t] = xn;
    __syncthreads();
    float c = cosb[(size_t)s * HD + t];
    float si = sinb[(size_t)s * HD + t];
    float rot = (t < 64) ? -sh[t + 64] : sh[t - 64];
    float val = xn * c + rot * si;

    if (hh < NH) {
        float sv = val * QSC;
        bf16 hv = __float2bfloat16_rn(sv);
        size_t idx = ((size_t)hh * Q + s) * HD + t;
        qhi[idx] = hv;
        qlo[idx] = __float2bfloat16_rn(sv - __bfloat162float(hv));
    } else {
        int kv = hh - NH;
        newK[((size_t)kv * Q + s) * HD + t] = val;
        bf16 hv = __float2bfloat16_rn(val);
        size_t idx = ((size_t)kv * KVLEN + PAST + s) * HD + t;
        khi[idx] = hv;
        klo[idx] = __float2bfloat16_rn(val - __bfloat162float(hv));
    }
}

// ---------------- Flash attention with mma.sync ----------------
#define AT_TQ 128
#define AT_TK 64
#define KVROW 272                    // 128 bf16 = 256B + 16B pad
#define KVPLANE (64 * KVROW)         // 17408
#define TILEBUF (4 * KVPLANE)        // Khi Klo Vhi Vlo = 69632
#define AT_SMEM (2 * TILEBUF)        // double buffered = 139264
#define QPLANE (128 * KVROW)         // Q staging plane = 34816

__global__ __launch_bounds__(256, 1) void attn_mma(
    const bf16* __restrict__ qhi, const bf16* __restrict__ qlo,
    const bf16* __restrict__ khi, const bf16* __restrict__ klo,
    const bf16* __restrict__ vhi, const bf16* __restrict__ vlo,
    bf16* __restrict__ aohi, bf16* __restrict__ aolo)
{
    extern __shared__ char asmem[];
    const int h = blockIdx.x;
    const int q0 = blockIdx.y * AT_TQ;
    const int kvh = h >> 1;
    const int tid = threadIdx.x;
    const int lane = tid & 31;
    const int wid = tid >> 5;
    const uint32_t sb = smem_u32(asmem);

    // ---- stage Q and extract fragments ----
    {
        const bf16* qsrc[2] = { qhi + ((size_t)h * Q + q0) * HD,
                                qlo + ((size_t)h * Q + q0) * HD };
        for (int i = tid; i < 4096; i += 256) {
            int p = i >> 11, row = (i >> 4) & 127, seg = i & 15;
            cp16(sb + p * QPLANE + row * KVROW + seg * 16,
                 qsrc[p] + (size_t)row * HD + seg * 8);
        }
        cpcommit();
        cpwait<0>();
        __syncthreads();
    }
    uint32_t aQh[8][4], aQl[8][4];
    {
        uint32_t a0 = sb + (wid * 16 + (lane & 15)) * KVROW + (lane >> 4) * 16;
#pragma unroll
        for (int kc = 0; kc < 8; kc++) {
            ldsm4(aQh[kc], a0 + kc * 32);
            ldsm4(aQl[kc], a0 + kc * 32 + QPLANE);
        }
    }
    __syncthreads();  // done with Q staging region

    float oacc[16][4];
#pragma unroll
    for (int f = 0; f < 16; f++)
#pragma unroll
        for (int r = 0; r < 4; r++) oacc[f][r] = 0.0f;
    float m0 = -1e30f, m1 = -1e30f, l0 = 0.0f, l1 = 0.0f;

    const int nt = (PAST + q0 + AT_TQ) / AT_TK;
    const bf16* ksrc[2] = { khi + (size_t)kvh * KVLEN * HD, klo + (size_t)kvh * KVLEN * HD };
    const bf16* vsrc[2] = { vhi + (size_t)kvh * KVLEN * HD, vlo + (size_t)kvh * KVLEN * HD };

    // preload tile 0 into buf 0
    {
        for (int i = tid; i < 4096; i += 256) {
            int p = i >> 10, row = (i >> 4) & 63, seg = i & 15;
            const bf16* s0 = (p < 2) ? ksrc[p] : vsrc[p - 2];
            cp16(sb + p * KVPLANE + row * KVROW + seg * 16,
                 s0 + (size_t)row * HD + seg * 8);
        }
        cpcommit();
    }

    const int rowselB = (lane & 7) + (lane >> 4) * 8;
    const int halfB = (lane >> 3) & 1;
    const int rowV = lane & 15;
    const int halfV = (lane >> 4) * 16;

    for (int t = 0; t < nt; t++) {
        __syncthreads();   // prior compute done; (t+1)&1 buffer free
        if (t + 1 < nt) {
            int j1 = (t + 1) * AT_TK;
            uint32_t db = sb + ((t + 1) & 1) * TILEBUF;
            for (int i = tid; i < 4096; i += 256) {
                int p = i >> 10, row = (i >> 4) & 63, seg = i & 15;
                const bf16* s0 = (p < 2) ? ksrc[p] : vsrc[p - 2];
                cp16(db + p * KVPLANE + row * KVROW + seg * 16,
                     s0 + (size_t)(j1 + row) * HD + seg * 8);
            }
            cpcommit();
            cpwait<1>();
        } else {
            cpwait<0>();
        }
        __syncthreads();

        const uint32_t kb = sb + (t & 1) * TILEBUF;
        const int j0 = t * AT_TK;

        // ---- S = Q K^T ----
        float sacc[8][4];
#pragma unroll
        for (int j = 0; j < 8; j++)
#pragma unroll
            for (int r = 0; r < 4; r++) sacc[j][r] = 0.0f;
#pragma unroll
        for (int nj = 0; nj < 4; nj++) {
            uint32_t kbase = kb + (nj * 16 + rowselB) * KVROW + halfB * 16;
#pragma unroll
            for (int kc = 0; kc < 8; kc++) {
                uint32_t kh[4], kl[4];
                ldsm4(kh, kbase + kc * 32);
                ldsm4(kl, kbase + kc * 32 + KVPLANE);
                mma_bf16(sacc[2 * nj],     aQh[kc], kh);
                mma_bf16(sacc[2 * nj],     aQh[kc], kl);
                mma_bf16(sacc[2 * nj],     aQl[kc], kh);
                mma_bf16(sacc[2 * nj + 1], aQh[kc], kh + 2);
                mma_bf16(sacc[2 * nj + 1], aQh[kc], kl + 2);
                mma_bf16(sacc[2 * nj + 1], aQl[kc], kh + 2);
            }
        }

        // ---- mask (boundary tiles only) ----
        if (j0 + AT_TK - 1 > PAST + q0 + wid * 16) {
            int r0g = PAST + q0 + wid * 16 + (lane >> 2);
#pragma unroll
            for (int j = 0; j < 8; j++) {
                int cg = j0 + j * 8 + (lane & 3) * 2;
                if (cg > r0g)     sacc[j][0] = -1e30f;
                if (cg + 1 > r0g) sacc[j][1] = -1e30f;
                if (cg > r0g + 8)     sacc[j][2] = -1e30f;
                if (cg + 1 > r0g + 8) sacc[j][3] = -1e30f;
            }
        }

        // ---- online softmax (log2 domain) ----
        float t0 = -1e30f, t1 = -1e30f;
#pragma unroll
        for (int j = 0; j < 8; j++) {
            t0 = fmaxf(t0, fmaxf(sacc[j][0], sacc[j][1]));
            t1 = fmaxf(t1, fmaxf(sacc[j][2], sacc[j][3]));
        }
        t0 = fmaxf(t0, __shfl_xor_sync(0xffffffffu, t0, 1));
        t0 = fmaxf(t0, __shfl_xor_sync(0xffffffffu, t0, 2));
        t1 = fmaxf(t1, __shfl_xor_sync(0xffffffffu, t1, 1));
        t1 = fmaxf(t1, __shfl_xor_sync(0xffffffffu, t1, 2));
        float mn0 = fmaxf(m0, t0), mn1 = fmaxf(m1, t1);
        float c0 = ex2(m0 - mn0), c1 = ex2(m1 - mn1);
        m0 = mn0; m1 = mn1;
        float ps0 = 0.0f, ps1 = 0.0f;
#pragma unroll
        for (int j = 0; j < 8; j++) {
            sacc[j][0] = ex2(sacc[j][0] - mn0); ps0 += sacc[j][0];
            sacc[j][1] = ex2(sacc[j][1] - mn0); ps0 += sacc[j][1];
            sacc[j][2] = ex2(sacc[j][2] - mn1); ps1 += sacc[j][2];
            sacc[j][3] = ex2(sacc[j][3] - mn1); ps1 += sacc[j][3];
        }
        ps0 += __shfl_xor_sync(0xffffffffu, ps0, 1);
        ps0 += __shfl_xor_sync(0xffffffffu, ps0, 2);
        ps1 += __shfl_xor_sync(0xffffffffu, ps1, 1);
        ps1 += __shfl_xor_sync(0xffffffffu, ps1, 2);
        l0 = l0 * c0 + ps0;
        l1 = l1 * c1 + ps1;
#pragma unroll
        for (int f = 0; f < 16; f++) {
            oacc[f][0] *= c0; oacc[f][1] *= c0;
            oacc[f][2] *= c1; oacc[f][3] *= c1;
        }

        // ---- pack P fragments (split hi/lo) ----
        uint32_t pH[4][4], pL[4][4];
#pragma unroll
        for (int kc = 0; kc < 4; kc++) {
            split2(sacc[2 * kc][0],     sacc[2 * kc][1],     pH[kc][0], pL[kc][0]);
            split2(sacc[2 * kc][2],     sacc[2 * kc][3],     pH[kc][1], pL[kc][1]);
            split2(sacc[2 * kc + 1][0], sacc[2 * kc + 1][1], pH[kc][2], pL[kc][2]);
            split2(sacc[2 * kc + 1][2], sacc[2 * kc + 1][3], pH[kc][3], pL[kc][3]);
        }

        // ---- O += P V ----
        const uint32_t vb = kb + 2 * KVPLANE;
#pragma unroll
        for (int dj = 0; dj < 8; dj++) {
#pragma unroll
            for (int kc = 0; kc < 4; kc++) {
                uint32_t vh[4], vl[4];
                uint32_t va = vb + (kc * 16 + rowV) * KVROW + dj * 32 + halfV;
                ldsm4t(vh, va);
                ldsm4t(vl, va + KVPLANE);
                mma_bf16(oacc[2 * dj],     pH[kc], vh);
                mma_bf16(oacc[2 * dj],     pH[kc], vl);
                mma_bf16(oacc[2 * dj],     pL[kc], vh);
                mma_bf16(oacc[2 * dj + 1], pH[kc], vh + 2);
                mma_bf16(oacc[2 * dj + 1], pH[kc], vl + 2);
                mma_bf16(oacc[2 * dj + 1], pL[kc], vh + 2);
            }
        }
    }

    // ---- epilogue: normalize + split-store ----
    float inv0 = 1.0f / l0, inv1 = 1.0f / l1;
    int r0 = q0 + wid * 16 + (lane >> 2);
#pragma unroll
    for (int f = 0; f < 16; f++) {
        int d = f * 8 + (lane & 3) * 2;
        size_t e0 = (size_t)r0 * (NH * HD) + h * HD + d;
        size_t e1 = e0 + (size_t)8 * (NH * HD);
        uint32_t hh, ll;
        split2(oacc[f][0] * inv0, oacc[f][1] * inv0, hh, ll);
        *(uint32_t*)(aohi + e0) = hh;
        *(uint32_t*)(aolo + e0) = ll;
        split2(oacc[f][2] * inv1, oacc[f][3] * inv1, hh, ll);
        *(uint32_t*)(aohi + e1) = hh;
        *(uint32_t*)(aolo + e1) = ll;
    }
}

// ---------------- launch ----------------
extern "C" void kernel_launch(void* const* d_in, const int* in_sizes, int n_in,
                              void* d_out, int out_size)
{
    const float* hs    = (const float*)d_in[0];
    const float* cosb  = (const float*)d_in[1];
    const float* sinb  = (const float*)d_in[2];
    // d_in[3] = attention_mask (pure causal; computed analytically)
    const float* pastK = (const float*)d_in[4];
    const float* pastV = (const float*)d_in[5];
    const float* Wq    = (const float*)d_in[6];
    const float* Wk    = (const float*)d_in[7];
    const float* Wv    = (const float*)d_in[8];
    const float* Wo    = (const float*)d_in[9];
    const float* qw    = (const float*)d_in[10];
    const float* kw    = (const float*)d_in[11];

    float* out  = (float*)d_out;
    float* newK = out + (size_t)Q * NH * HD;
    float* newV = newK + (size_t)NKV * Q * HD;

    float *qtmp, *ktmp;
    bf16 *hshi, *hslo, *wqhi, *wqlo, *wkhi, *wklo, *wvhi, *wvlo, *wohi, *wolo;
    bf16 *qphi, *qplo, *kphi, *kplo, *vphi, *vplo, *aohi, *aolo;
    cudaGetSymbolAddress((void**)&qtmp, g_qtmp);
    cudaGetSymbolAddress((void**)&ktmp, g_ktmp);
    cudaGetSymbolAddress((void**)&hshi, g_hs_hi);
    cudaGetSymbolAddress((void**)&hslo, g_hs_lo);
    cudaGetSymbolAddress((void**)&wqhi, g_wq_hi);
    cudaGetSymbolAddress((void**)&wqlo, g_wq_lo);
    cudaGetSymbolAddress((void**)&wkhi, g_wk_hi);
    cudaGetSymbolAddress((void**)&wklo, g_wk_lo);
    cudaGetSymbolAddress((void**)&wvhi, g_wv_hi);
    cudaGetSymbolAddress((void**)&wvlo, g_wv_lo);
    cudaGetSymbolAddress((void**)&wohi, g_wo_hi);
    cudaGetSymbolAddress((void**)&wolo, g_wo_lo);
    cudaGetSymbolAddress((void**)&qphi, g_q_hi);
    cudaGetSymbolAddress((void**)&qplo, g_q_lo);
    cudaGetSymbolAddress((void**)&kphi, g_k_hi);
    cudaGetSymbolAddress((void**)&kplo, g_k_lo);
    cudaGetSymbolAddress((void**)&vphi, g_v_hi);
    cudaGetSymbolAddress((void**)&vplo, g_v_lo);
    cudaGetSymbolAddress((void**)&aohi, g_ao_hi);
    cudaGetSymbolAddress((void**)&aolo, g_ao_lo);

    cudaFuncSetAttribute(hgemm, cudaFuncAttributeMaxDynamicSharedMemorySize, HG_SMEM);
    cudaFuncSetAttribute(attn_mma, cudaFuncAttributeMaxDynamicSharedMemorySize, AT_SMEM);

    // splits
    ksplit<<<(Q * H) / 1024, 256>>>(hs, hshi, hslo);
    ksplit<<<(NH * HD * H) / 1024, 256>>>(Wq, wqhi, wqlo);
    ksplit<<<(NKV * HD * H) / 1024, 256>>>(Wk, wkhi, wklo);
    ksplit<<<(NKV * HD * H) / 1024, 256>>>(Wv, wvhi, wvlo);
    ksplit<<<(NH * HD * NH * HD) / 1024, 256>>>(Wo, wohi, wolo);
    ksplit_cache<<<(NKV * PAST * HD) / 1024, 256>>>(pastK, kphi, kplo);
    ksplit_cache<<<(NKV * PAST * HD) / 1024, 256>>>(pastV, vphi, vplo);

    // projections
    hgemm<<<dim3(NH * HD / 128, Q / 128), 256, HG_SMEM>>>(
        hshi, hslo, wqhi, wqlo, qtmp, Q, NH * HD, H, 0, nullptr, nullptr);
    hgemm<<<dim3(NKV * HD / 128, Q / 128), 256, HG_SMEM>>>(
        hshi, hslo, wkhi, wklo, ktmp, Q, NKV * HD, H, 0, nullptr, nullptr);
    hgemm<<<dim3(NKV * HD / 128, Q / 128), 256, HG_SMEM>>>(
        hshi, hslo, wvhi, wvlo, newV, Q, NKV * HD, H, 1, vphi, vplo);

    // rmsnorm + rope (+ splits)
    norm_rope<<<dim3(Q, NH + NKV), 128>>>(qtmp, ktmp, cosb, sinb, qw, kw,
                                          qphi, qplo, newK, kphi, kplo);

    // attention
    attn_mma<<<dim3(NH, Q / AT_TQ), 256, AT_SMEM>>>(
        qphi, qplo, kphi, kplo, vphi, vplo, aohi, aolo);

    // output projection
    hgemm<<<dim3(NH * HD / 128, Q / 128), 256, HG_SMEM>>>(
        aohi, aolo, wohi, wolo, out, Q, NH * HD, NH * HD, 0, nullptr, nullptr);
}

// round 6
// speedup vs baseline: 5.5360x; 1.0854x over previous
#include <cuda_runtime.h>
#include <cuda_bf16.h>
#include <cstdint>

#define Q    2048
#define H    2048
#define NH   16
#define NKV  8
#define HD   128
#define PAST 2048
#define KVLEN (PAST + Q)
#define KEPS 1e-6f

typedef __nv_bfloat16 bf16;

// ---------------- scratch (no allocation allowed) ----------------
__device__ float g_qtmp[Q * NH * HD];
__device__ float g_ktmp[Q * NKV * HD];
__device__ bf16 g_hs_hi[Q * H],            g_hs_lo[Q * H];
__device__ bf16 g_wq_hi[NH * HD * H],      g_wq_lo[NH * HD * H];
__device__ bf16 g_wk_hi[NKV * HD * H],     g_wk_lo[NKV * HD * H];
__device__ bf16 g_wv_hi[NKV * HD * H],     g_wv_lo[NKV * HD * H];
__device__ bf16 g_wo_hi[NH * HD * NH * HD], g_wo_lo[NH * HD * NH * HD];
__device__ bf16 g_q_hi[NH * Q * HD],       g_q_lo[NH * Q * HD];     // scaled by 1/sqrt(d)*log2e
__device__ bf16 g_k_hi[NKV * KVLEN * HD],  g_k_lo[NKV * KVLEN * HD];
__device__ bf16 g_v_hi[NKV * KVLEN * HD],  g_v_lo[NKV * KVLEN * HD];
__device__ bf16 g_ao_hi[Q * NH * HD],      g_ao_lo[Q * NH * HD];

// ---------------- helpers ----------------
__device__ __forceinline__ uint32_t smem_u32(const void* p) {
    uint32_t a;
    asm("{ .reg .u64 t; cvta.to.shared.u64 t, %1; cvt.u32.u64 %0, t; }" : "=r"(a) : "l"(p));
    return a;
}
__device__ __forceinline__ uint32_t packbf(bf16 a, bf16 b) {
    return (uint32_t)__bfloat16_as_ushort(a) | ((uint32_t)__bfloat16_as_ushort(b) << 16);
}
__device__ __forceinline__ void split2(float a, float b, uint32_t& hi, uint32_t& lo) {
    bf16 ha = __float2bfloat16_rn(a), hb = __float2bfloat16_rn(b);
    hi = packbf(ha, hb);
    lo = packbf(__float2bfloat16_rn(a - __bfloat162float(ha)),
                __float2bfloat16_rn(b - __bfloat162float(hb)));
}
__device__ __forceinline__ void ldsm4(uint32_t* r, uint32_t addr) {
    asm volatile("ldmatrix.sync.aligned.m8n8.x4.shared.b16 {%0,%1,%2,%3}, [%4];"
                 : "=r"(r[0]), "=r"(r[1]), "=r"(r[2]), "=r"(r[3]) : "r"(addr));
}
__device__ __forceinline__ void ldsm4t(uint32_t* r, uint32_t addr) {
    asm volatile("ldmatrix.sync.aligned.m8n8.x4.trans.shared.b16 {%0,%1,%2,%3}, [%4];"
                 : "=r"(r[0]), "=r"(r[1]), "=r"(r[2]), "=r"(r[3]) : "r"(addr));
}
__device__ __forceinline__ void mma_bf16(float* c, const uint32_t* a, const uint32_t* b) {
    asm volatile(
        "mma.sync.aligned.m16n8k16.row.col.f32.bf16.bf16.f32 "
        "{%0,%1,%2,%3}, {%4,%5,%6,%7}, {%8,%9}, {%0,%1,%2,%3};"
        : "+f"(c[0]), "+f"(c[1]), "+f"(c[2]), "+f"(c[3])
        : "r"(a[0]), "r"(a[1]), "r"(a[2]), "r"(a[3]), "r"(b[0]), "r"(b[1]));
}
__device__ __forceinline__ void cp16(uint32_t dst, const void* src) {
    asm volatile("cp.async.cg.shared.global [%0], [%1], 16;"
                 :: "r"(dst), "l"(__cvta_generic_to_global(src)));
}
__device__ __forceinline__ void cpcommit() { asm volatile("cp.async.commit_group;"); }
template <int N>
__device__ __forceinline__ void cpwait() {
    asm volatile("cp.async.wait_group %0;" :: "n"(N));
}
__device__ __forceinline__ float ex2(float x) {
    float y;
    asm("ex2.approx.f32 %0, %1;" : "=f"(y) : "f"(x));
    return y;
}

// ---------------- split kernels ----------------
__global__ __launch_bounds__(256) void ksplit(const float* __restrict__ x,
                                              bf16* __restrict__ hi, bf16* __restrict__ lo)
{
    int i = blockIdx.x * 256 + threadIdx.x;
    float4 v = ((const float4*)x)[i];
    uint32_t h0, l0, h1, l1;
    split2(v.x, v.y, h0, l0);
    split2(v.z, v.w, h1, l1);
    ((uint32_t*)hi)[2 * i] = h0;  ((uint32_t*)hi)[2 * i + 1] = h1;
    ((uint32_t*)lo)[2 * i] = l0;  ((uint32_t*)lo)[2 * i + 1] = l1;
}
__global__ __launch_bounds__(256) void ksplit_cache(const float* __restrict__ x,
                                                    bf16* __restrict__ hi, bf16* __restrict__ lo)
{
    int i = blockIdx.x * 256 + threadIdx.x;
    int e = i * 4;
    int kv = e / (PAST * HD);
    int rem = e - kv * (PAST * HD);
    size_t de = (size_t)kv * (KVLEN * HD) + rem;
    float4 v = ((const float4*)x)[i];
    uint32_t h0, l0, h1, l1;
    split2(v.x, v.y, h0, l0);
    split2(v.z, v.w, h1, l1);
    *(uint32_t*)(hi + de) = h0;  *(uint32_t*)(hi + de + 2) = h1;
    *(uint32_t*)(lo + de) = l0;  *(uint32_t*)(lo + de + 2) = l1;
}

// ---------------- GEMM core macro pieces ----------------
#define ROWB   80
#define PLANEB 10240
#define STAGEB 40960
#define HG_SMEM (2 * STAGEB)

// ---------------- fused QKV projection GEMM ----------------
// grid (32, 16): x<16 -> Q cols, x<24 -> K cols, else V cols (transpose+split epi)
__global__ __launch_bounds__(256) void hgemm_qkv(
    const bf16* __restrict__ hshi, const bf16* __restrict__ hslo,
    const bf16* __restrict__ wqhi, const bf16* __restrict__ wqlo,
    const bf16* __restrict__ wkhi, const bf16* __restrict__ wklo,
    const bf16* __restrict__ wvhi, const bf16* __restrict__ wvlo,
    float* __restrict__ qtmp, float* __restrict__ ktmp, float* __restrict__ newV,
    bf16* __restrict__ vphi, bf16* __restrict__ vplo)
{
    extern __shared__ char hsm[];
    const int bx = blockIdx.x;
    const int tid = threadIdx.x;
    const int lane = tid & 31;
    const int wid = tid >> 5;
    const int wm = wid >> 2;
    const int wn = wid & 3;
    const uint32_t base_u = smem_u32(hsm);
    const int K = H;

    const bf16 *Bhi, *Blo;
    int colb;
    if (bx < 16)      { Bhi = wqhi; Blo = wqlo; colb = bx * 128; }
    else if (bx < 24) { Bhi = wkhi; Blo = wklo; colb = (bx - 16) * 128; }
    else              { Bhi = wvhi; Blo = wvlo; colb = (bx - 24) * 128; }

    const bf16* pl[4] = {
        hshi + (size_t)(blockIdx.y * 128) * K, hslo + (size_t)(blockIdx.y * 128) * K,
        Bhi + (size_t)colb * K,                Blo + (size_t)colb * K };

    const int rowselA = lane & 15;
    const int halfA = lane >> 4;
    const int rowselB = (lane & 7) + (lane >> 4) * 8;
    const int halfB = (lane >> 3) & 1;
    const uint32_t aoff0 = (uint32_t)((wm * 64 + rowselA) * ROWB + halfA * 16);
    const uint32_t boff0 = (uint32_t)((wn * 32 + rowselB) * ROWB + halfB * 16);

    float acc[4][4][4];
#pragma unroll
    for (int i = 0; i < 4; i++)
#pragma unroll
        for (int j = 0; j < 4; j++)
#pragma unroll
            for (int r = 0; r < 4; r++) acc[i][j][r] = 0.0f;

    const int nst = K / 32;
    {
        uint32_t dstb = base_u;
        for (int i = tid; i < 2048; i += 256) {
            int p = i >> 9, row = (i >> 2) & 127, seg = i & 3;
            cp16(dstb + p * PLANEB + row * ROWB + seg * 16,
                 pl[p] + (size_t)row * K + seg * 8);
        }
        cpcommit();
    }

    for (int s = 0; s < nst; s++) {
        cpwait<0>();
        __syncthreads();
        if (s + 1 < nst) {
            int kt = (s + 1) * 32;
            uint32_t dstb = base_u + ((s + 1) & 1) * STAGEB;
            for (int i = tid; i < 2048; i += 256) {
                int p = i >> 9, row = (i >> 2) & 127, seg = i & 3;
                cp16(dstb + p * PLANEB + row * ROWB + seg * 16,
                     pl[p] + (size_t)row * K + kt + seg * 8);
            }
            cpcommit();
        }
        const uint32_t sb = base_u + (s & 1) * STAGEB;
#pragma unroll
        for (int kc = 0; kc < 2; kc++) {
            uint32_t ah[4][4], al[4][4];
#pragma unroll
            for (int mi = 0; mi < 4; mi++) {
                uint32_t ad = sb + aoff0 + mi * (16 * ROWB) + kc * 32;
                ldsm4(ah[mi], ad);
                ldsm4(al[mi], ad + PLANEB);
            }
            uint32_t bh[4][2], bl[4][2];
#pragma unroll
            for (int p = 0; p < 2; p++) {
                uint32_t bd = sb + 2 * PLANEB + boff0 + p * (16 * ROWB) + kc * 32;
                uint32_t r[4];
                ldsm4(r, bd);
                bh[2 * p][0] = r[0]; bh[2 * p][1] = r[1];
                bh[2 * p + 1][0] = r[2]; bh[2 * p + 1][1] = r[3];
                ldsm4(r, bd + PLANEB);
                bl[2 * p][0] = r[0]; bl[2 * p][1] = r[1];
                bl[2 * p + 1][0] = r[2]; bl[2 * p + 1][1] = r[3];
            }
#pragma unroll
            for (int mi = 0; mi < 4; mi++) {
#pragma unroll
                for (int nj = 0; nj < 4; nj++) {
                    mma_bf16(acc[mi][nj], ah[mi], bh[nj]);
                    mma_bf16(acc[mi][nj], ah[mi], bl[nj]);
                    mma_bf16(acc[mi][nj], al[mi], bh[nj]);
                }
            }
        }
    }

    const int rfrag = lane >> 2;
    const int cpair = (lane & 3) * 2;
#pragma unroll
    for (int mi = 0; mi < 4; mi++) {
#pragma unroll
        for (int nj = 0; nj < 4; nj++) {
            int coll = colb + wn * 32 + nj * 8 + cpair;
#pragma unroll
            for (int half = 0; half < 2; half++) {
                int rowg = blockIdx.y * 128 + wm * 64 + mi * 16 + rfrag + half * 8;
                float2 v = make_float2(acc[mi][nj][2 * half], acc[mi][nj][2 * half + 1]);
                if (bx < 16) {
                    *(float2*)(qtmp + (size_t)rowg * (NH * HD) + coll) = v;
                } else if (bx < 24) {
                    *(float2*)(ktmp + (size_t)rowg * (NKV * HD) + coll) = v;
                } else {
                    int kv = coll >> 7, d = coll & 127;
                    *(float2*)(newV + (size_t)kv * (Q * HD) + (size_t)rowg * HD + d) = v;
                    uint32_t hh, ll;
                    split2(v.x, v.y, hh, ll);
                    size_t de = (size_t)kv * (KVLEN * HD) + (size_t)(PAST + rowg) * HD + d;
                    *(uint32_t*)(vphi + de) = hh;
                    *(uint32_t*)(vplo + de) = ll;
                }
            }
        }
    }
}

// ---------------- output projection GEMM: out = AO[M,K2] * Wo[N,K2]^T ----------------
__global__ __launch_bounds__(256) void hgemm_o(
    const bf16* __restrict__ Ahi, const bf16* __restrict__ Alo,
    const bf16* __restrict__ Bhi, const bf16* __restrict__ Blo,
    float* __restrict__ C)
{
    extern __shared__ char hsm[];
    const int tid = threadIdx.x;
    const int lane = tid & 31;
    const int wid = tid >> 5;
    const int wm = wid >> 2;
    const int wn = wid & 3;
    const uint32_t base_u = smem_u32(hsm);
    const int K = NH * HD, N = NH * HD;

    const bf16* pl[4] = {
        Ahi + (size_t)(blockIdx.y * 128) * K, Alo + (size_t)(blockIdx.y * 128) * K,
        Bhi + (size_t)(blockIdx.x * 128) * K, Blo + (size_t)(blockIdx.x * 128) * K };

    const int rowselA = lane & 15;
    const int halfA = lane >> 4;
    const int rowselB = (lane & 7) + (lane >> 4) * 8;
    const int halfB = (lane >> 3) & 1;
    const uint32_t aoff0 = (uint32_t)((wm * 64 + rowselA) * ROWB + halfA * 16);
    const uint32_t boff0 = (uint32_t)((wn * 32 + rowselB) * ROWB + halfB * 16);

    float acc[4][4][4];
#pragma unroll
    for (int i = 0; i < 4; i++)
#pragma unroll
        for (int j = 0; j < 4; j++)
#pragma unroll
            for (int r = 0; r < 4; r++) acc[i][j][r] = 0.0f;

    const int nst = K / 32;
    {
        uint32_t dstb = base_u;
        for (int i = tid; i < 2048; i += 256) {
            int p = i >> 9, row = (i >> 2) & 127, seg = i & 3;
            cp16(dstb + p * PLANEB + row * ROWB + seg * 16,
                 pl[p] + (size_t)row * K + seg * 8);
        }
        cpcommit();
    }

    for (int s = 0; s < nst; s++) {
        cpwait<0>();
        __syncthreads();
        if (s + 1 < nst) {
            int kt = (s + 1) * 32;
            uint32_t dstb = base_u + ((s + 1) & 1) * STAGEB;
            for (int i = tid; i < 2048; i += 256) {
                int p = i >> 9, row = (i >> 2) & 127, seg = i & 3;
                cp16(dstb + p * PLANEB + row * ROWB + seg * 16,
                     pl[p] + (size_t)row * K + kt + seg * 8);
            }
            cpcommit();
        }
        const uint32_t sb = base_u + (s & 1) * STAGEB;
#pragma unroll
        for (int kc = 0; kc < 2; kc++) {
            uint32_t ah[4][4], al[4][4];
#pragma unroll
            for (int mi = 0; mi < 4; mi++) {
                uint32_t ad = sb + aoff0 + mi * (16 * ROWB) + kc * 32;
                ldsm4(ah[mi], ad);
                ldsm4(al[mi], ad + PLANEB);
            }
            uint32_t bh[4][2], bl[4][2];
#pragma unroll
            for (int p = 0; p < 2; p++) {
                uint32_t bd = sb + 2 * PLANEB + boff0 + p * (16 * ROWB) + kc * 32;
                uint32_t r[4];
                ldsm4(r, bd);
                bh[2 * p][0] = r[0]; bh[2 * p][1] = r[1];
                bh[2 * p + 1][0] = r[2]; bh[2 * p + 1][1] = r[3];
                ldsm4(r, bd + PLANEB);
                bl[2 * p][0] = r[0]; bl[2 * p][1] = r[1];
                bl[2 * p + 1][0] = r[2]; bl[2 * p + 1][1] = r[3];
            }
#pragma unroll
            for (int mi = 0; mi < 4; mi++) {
#pragma unroll
                for (int nj = 0; nj < 4; nj++) {
                    mma_bf16(acc[mi][nj], ah[mi], bh[nj]);
                    mma_bf16(acc[mi][nj], ah[mi], bl[nj]);
                    mma_bf16(acc[mi][nj], al[mi], bh[nj]);
                }
            }
        }
    }

    const int rfrag = lane >> 2;
    const int cpair = (lane & 3) * 2;
#pragma unroll
    for (int mi = 0; mi < 4; mi++) {
#pragma unroll
        for (int nj = 0; nj < 4; nj++) {
            int colg = blockIdx.x * 128 + wn * 32 + nj * 8 + cpair;
#pragma unroll
            for (int half = 0; half < 2; half++) {
                int rowg = blockIdx.y * 128 + wm * 64 + mi * 16 + rfrag + half * 8;
                *(float2*)(C + (size_t)rowg * N + colg) =
                    make_float2(acc[mi][nj][2 * half], acc[mi][nj][2 * half + 1]);
            }
        }
    }
}

// ---------------- RMSNorm + RoPE (+ split outputs) ----------------
__global__ __launch_bounds__(128) void norm_rope(
    const float* __restrict__ qtmp, const float* __restrict__ ktmp,
    const float* __restrict__ cosb, const float* __restrict__ sinb,
    const float* __restrict__ qw, const float* __restrict__ kw,
    bf16* __restrict__ qhi, bf16* __restrict__ qlo,
    float* __restrict__ newK,
    bf16* __restrict__ khi, bf16* __restrict__ klo)
{
    const float QSC = 0.08838834764831845f * 1.44269504088896341f;
    int s = blockIdx.x;
    int hh = blockIdx.y;
    int t = threadIdx.x;

    const float* src;
    const float* w;
    if (hh < NH) {
        src = qtmp + (size_t)s * (NH * HD) + hh * HD;
        w = qw;
    } else {
        src = ktmp + (size_t)s * (NKV * HD) + (hh - NH) * HD;
        w = kw;
    }

    float x = src[t];
    float v = x * x;
#pragma unroll
    for (int o = 16; o; o >>= 1) v += __shfl_xor_sync(0xffffffffu, v, o);
    __shared__ float red[4];
    if ((t & 31) == 0) red[t >> 5] = v;
    __syncthreads();
    float sum = red[0] + red[1] + red[2] + red[3];
    float rs = rsqrtf(sum * (1.0f / HD) + KEPS);
    float xn = x * rs * w[t];

    __shared__ float sh[HD];
    sh[t] = xn;
    __syncthreads();
    float c = cosb[(size_t)s * HD + t];
    float si = sinb[(size_t)s * HD + t];
    float rot = (t < 64) ? -sh[t + 64] : sh[t - 64];
    float val = xn * c + rot * si;

    if (hh < NH) {
        float sv = val * QSC;
        bf16 hv = __float2bfloat16_rn(sv);
        size_t idx = ((size_t)hh * Q + s) * HD + t;
        qhi[idx] = hv;
        qlo[idx] = __float2bfloat16_rn(sv - __bfloat162float(hv));
    } else {
        int kv = hh - NH;
        newK[((size_t)kv * Q + s) * HD + t] = val;
        bf16 hv = __float2bfloat16_rn(val);
        size_t idx = ((size_t)kv * KVLEN + PAST + s) * HD + t;
        khi[idx] = hv;
        klo[idx] = __float2bfloat16_rn(val - __bfloat162float(hv));
    }
}

// ---------------- Flash attention with mma.sync ----------------
#define AT_TQ 128
#define AT_TK 64
#define KVROW 272
#define KVPLANE (64 * KVROW)
#define TILEBUF (4 * KVPLANE)
#define AT_SMEM (2 * TILEBUF)
#define QPLANE (128 * KVROW)

__global__ __launch_bounds__(256, 1) void attn_mma(
    const bf16* __restrict__ qhi, const bf16* __restrict__ qlo,
    const bf16* __restrict__ khi, const bf16* __restrict__ klo,
    const bf16* __restrict__ vhi, const bf16* __restrict__ vlo,
    bf16* __restrict__ aohi, bf16* __restrict__ aolo)
{
    extern __shared__ char asmem[];
    const int h = blockIdx.x;
    const int q0 = ((int)gridDim.y - 1 - (int)blockIdx.y) * AT_TQ;  // largest-first
    const int kvh = h >> 1;
    const int tid = threadIdx.x;
    const int lane = tid & 31;
    const int wid = tid >> 5;
    const uint32_t sb = smem_u32(asmem);

    {
        const bf16* qsrc[2] = { qhi + ((size_t)h * Q + q0) * HD,
                                qlo + ((size_t)h * Q + q0) * HD };
        for (int i = tid; i < 4096; i += 256) {
            int p = i >> 11, row = (i >> 4) & 127, seg = i & 15;
            cp16(sb + p * QPLANE + row * KVROW + seg * 16,
                 qsrc[p] + (size_t)row * HD + seg * 8);
        }
        cpcommit();
        cpwait<0>();
        __syncthreads();
    }
    uint32_t aQh[8][4], aQl[8][4];
    {
        uint32_t a0 = sb + (wid * 16 + (lane & 15)) * KVROW + (lane >> 4) * 16;
#pragma unroll
        for (int kc = 0; kc < 8; kc++) {
            ldsm4(aQh[kc], a0 + kc * 32);
            ldsm4(aQl[kc], a0 + kc * 32 + QPLANE);
        }
    }
    __syncthreads();

    float oacc[16][4];
#pragma unroll
    for (int f = 0; f < 16; f++)
#pragma unroll
        for (int r = 0; r < 4; r++) oacc[f][r] = 0.0f;
    float m0 = -1e30f, m1 = -1e30f, l0 = 0.0f, l1 = 0.0f;

    const int nt = (PAST + q0 + AT_TQ) / AT_TK;
    const bf16* ksrc[2] = { khi + (size_t)kvh * KVLEN * HD, klo + (size_t)kvh * KVLEN * HD };
    const bf16* vsrc[2] = { vhi + (size_t)kvh * KVLEN * HD, vlo + (size_t)kvh * KVLEN * HD };

    {
        for (int i = tid; i < 4096; i += 256) {
            int p = i >> 10, row = (i >> 4) & 63, seg = i & 15;
            const bf16* s0 = (p < 2) ? ksrc[p] : vsrc[p - 2];
            cp16(sb + p * KVPLANE + row * KVROW + seg * 16,
                 s0 + (size_t)row * HD + seg * 8);
        }
        cpcommit();
    }

    const int rowselB = (lane & 7) + (lane >> 4) * 8;
    const int halfB = (lane >> 3) & 1;
    const int rowV = lane & 15;
    const int halfV = (lane >> 4) * 16;

    for (int t = 0; t < nt; t++) {
        __syncthreads();
        if (t + 1 < nt) {
            int j1 = (t + 1) * AT_TK;
            uint32_t db = sb + ((t + 1) & 1) * TILEBUF;
            for (int i = tid; i < 4096; i += 256) {
                int p = i >> 10, row = (i >> 4) & 63, seg = i & 15;
                const bf16* s0 = (p < 2) ? ksrc[p] : vsrc[p - 2];
                cp16(db + p * KVPLANE + row * KVROW + seg * 16,
                     s0 + (size_t)(j1 + row) * HD + seg * 8);
            }
            cpcommit();
            cpwait<1>();
        } else {
            cpwait<0>();
        }
        __syncthreads();

        const uint32_t kb = sb + (t & 1) * TILEBUF;
        const int j0 = t * AT_TK;

        float sacc[8][4];
#pragma unroll
        for (int j = 0; j < 8; j++)
#pragma unroll
            for (int r = 0; r < 4; r++) sacc[j][r] = 0.0f;
#pragma unroll
        for (int nj = 0; nj < 4; nj++) {
            uint32_t kbase = kb + (nj * 16 + rowselB) * KVROW + halfB * 16;
#pragma unroll
            for (int kc = 0; kc < 8; kc++) {
                uint32_t kh[4], kl[4];
                ldsm4(kh, kbase + kc * 32);
                ldsm4(kl, kbase + kc * 32 + KVPLANE);
                mma_bf16(sacc[2 * nj],     aQh[kc], kh);
                mma_bf16(sacc[2 * nj],     aQh[kc], kl);
                mma_bf16(sacc[2 * nj],     aQl[kc], kh);
                mma_bf16(sacc[2 * nj + 1], aQh[kc], kh + 2);
                mma_bf16(sacc[2 * nj + 1], aQh[kc], kl + 2);
                mma_bf16(sacc[2 * nj + 1], aQl[kc], kh + 2);
            }
        }

        if (j0 + AT_TK - 1 > PAST + q0 + wid * 16) {
            int r0g = PAST + q0 + wid * 16 + (lane >> 2);
#pragma unroll
            for (int j = 0; j < 8; j++) {
                int cg = j0 + j * 8 + (lane & 3) * 2;
                if (cg > r0g)     sacc[j][0] = -1e30f;
                if (cg + 1 > r0g) sacc[j][1] = -1e30f;
                if (cg > r0g + 8)     sacc[j][2] = -1e30f;
                if (cg + 1 > r0g + 8) sacc[j][3] = -1e30f;
            }
        }

        float t0 = -1e30f, t1 = -1e30f;
#pragma unroll
        for (int j = 0; j < 8; j++) {
            t0 = fmaxf(t0, fmaxf(sacc[j][0], sacc[j][1]));
            t1 = fmaxf(t1, fmaxf(sacc[j][2], sacc[j][3]));
        }
        t0 = fmaxf(t0, __shfl_xor_sync(0xffffffffu, t0, 1));
        t0 = fmaxf(t0, __shfl_xor_sync(0xffffffffu, t0, 2));
        t1 = fmaxf(t1, __shfl_xor_sync(0xffffffffu, t1, 1));
        t1 = fmaxf(t1, __shfl_xor_sync(0xffffffffu, t1, 2));
        float mn0 = fmaxf(m0, t0), mn1 = fmaxf(m1, t1);
        float c0 = ex2(m0 - mn0), c1 = ex2(m1 - mn1);
        m0 = mn0; m1 = mn1;
        float ps0 = 0.0f, ps1 = 0.0f;
#pragma unroll
        for (int j = 0; j < 8; j++) {
            sacc[j][0] = ex2(sacc[j][0] - mn0); ps0 += sacc[j][0];
            sacc[j][1] = ex2(sacc[j][1] - mn0); ps0 += sacc[j][1];
            sacc[j][2] = ex2(sacc[j][2] - mn1); ps1 += sacc[j][2];
            sacc[j][3] = ex2(sacc[j][3] - mn1); ps1 += sacc[j][3];
        }
        ps0 += __shfl_xor_sync(0xffffffffu, ps0, 1);
        ps0 += __shfl_xor_sync(0xffffffffu, ps0, 2);
        ps1 += __shfl_xor_sync(0xffffffffu, ps1, 1);
        ps1 += __shfl_xor_sync(0xffffffffu, ps1, 2);
        l0 = l0 * c0 + ps0;
        l1 = l1 * c1 + ps1;
#pragma unroll
        for (int f = 0; f < 16; f++) {
            oacc[f][0] *= c0; oacc[f][1] *= c0;
            oacc[f][2] *= c1; oacc[f][3] *= c1;
        }

        uint32_t pH[4][4], pL[4][4];
#pragma unroll
        for (int kc = 0; kc < 4; kc++) {
            split2(sacc[2 * kc][0],     sacc[2 * kc][1],     pH[kc][0], pL[kc][0]);
            split2(sacc[2 * kc][2],     sacc[2 * kc][3],     pH[kc][1], pL[kc][1]);
            split2(sacc[2 * kc + 1][0], sacc[2 * kc + 1][1], pH[kc][2], pL[kc][2]);
            split2(sacc[2 * kc + 1][2], sacc[2 * kc + 1][3], pH[kc][3], pL[kc][3]);
        }

        const uint32_t vb = kb + 2 * KVPLANE;
#pragma unroll
        for (int dj = 0; dj < 8; dj++) {
#pragma unroll
            for (int kc = 0; kc < 4; kc++) {
                uint32_t vh[4], vl[4];
                uint32_t va = vb + (kc * 16 + rowV) * KVROW + dj * 32 + halfV;
                ldsm4t(vh, va);
                ldsm4t(vl, va + KVPLANE);
                mma_bf16(oacc[2 * dj],     pH[kc], vh);
                mma_bf16(oacc[2 * dj],     pH[kc], vl);
                mma_bf16(oacc[2 * dj],     pL[kc], vh);
                mma_bf16(oacc[2 * dj + 1], pH[kc], vh + 2);
                mma_bf16(oacc[2 * dj + 1], pH[kc], vl + 2);
                mma_bf16(oacc[2 * dj + 1], pL[kc], vh + 2);
            }
        }
    }

    float inv0 = 1.0f / l0, inv1 = 1.0f / l1;
    int r0 = q0 + wid * 16 + (lane >> 2);
#pragma unroll
    for (int f = 0; f < 16; f++) {
        int d = f * 8 + (lane & 3) * 2;
        size_t e0 = (size_t)r0 * (NH * HD) + h * HD + d;
        size_t e1 = e0 + (size_t)8 * (NH * HD);
        uint32_t hh, ll;
        split2(oacc[f][0] * inv0, oacc[f][1] * inv0, hh, ll);
        *(uint32_t*)(aohi + e0) = hh;
        *(uint32_t*)(aolo + e0) = ll;
        split2(oacc[f][2] * inv1, oacc[f][3] * inv1, hh, ll);
        *(uint32_t*)(aohi + e1) = hh;
        *(uint32_t*)(aolo + e1) = ll;
    }
}

// ---------------- launch ----------------
extern "C" void kernel_launch(void* const* d_in, const int* in_sizes, int n_in,
                              void* d_out, int out_size)
{
    const float* hs    = (const float*)d_in[0];
    const float* cosb  = (const float*)d_in[1];
    const float* sinb  = (const float*)d_in[2];
    const float* pastK = (const float*)d_in[4];
    const float* pastV = (const float*)d_in[5];
    const float* Wq    = (const float*)d_in[6];
    const float* Wk    = (const float*)d_in[7];
    const float* Wv    = (const float*)d_in[8];
    const float* Wo    = (const float*)d_in[9];
    const float* qw    = (const float*)d_in[10];
    const float* kw    = (const float*)d_in[11];

    float* out  = (float*)d_out;
    float* newK = out + (size_t)Q * NH * HD;
    float* newV = newK + (size_t)NKV * Q * HD;

    float *qtmp, *ktmp;
    bf16 *hshi, *hslo, *wqhi, *wqlo, *wkhi, *wklo, *wvhi, *wvlo, *wohi, *wolo;
    bf16 *qphi, *qplo, *kphi, *kplo, *vphi, *vplo, *aohi, *aolo;
    cudaGetSymbolAddress((void**)&qtmp, g_qtmp);
    cudaGetSymbolAddress((void**)&ktmp, g_ktmp);
    cudaGetSymbolAddress((void**)&hshi, g_hs_hi);
    cudaGetSymbolAddress((void**)&hslo, g_hs_lo);
    cudaGetSymbolAddress((void**)&wqhi, g_wq_hi);
    cudaGetSymbolAddress((void**)&wqlo, g_wq_lo);
    cudaGetSymbolAddress((void**)&wkhi, g_wk_hi);
    cudaGetSymbolAddress((void**)&wklo, g_wk_lo);
    cudaGetSymbolAddress((void**)&wvhi, g_wv_hi);
    cudaGetSymbolAddress((void**)&wvlo, g_wv_lo);
    cudaGetSymbolAddress((void**)&wohi, g_wo_hi);
    cudaGetSymbolAddress((void**)&wolo, g_wo_lo);
    cudaGetSymbolAddress((void**)&qphi, g_q_hi);
    cudaGetSymbolAddress((void**)&qplo, g_q_lo);
    cudaGetSymbolAddress((void**)&kphi, g_k_hi);
    cudaGetSymbolAddress((void**)&kplo, g_k_lo);
    cudaGetSymbolAddress((void**)&vphi, g_v_hi);
    cudaGetSymbolAddress((void**)&vplo, g_v_lo);
    cudaGetSymbolAddress((void**)&aohi, g_ao_hi);
    cudaGetSymbolAddress((void**)&aolo, g_ao_lo);

    cudaFuncSetAttribute(hgemm_qkv, cudaFuncAttributeMaxDynamicSharedMemorySize, HG_SMEM);
    cudaFuncSetAttribute(hgemm_o, cudaFuncAttributeMaxDynamicSharedMemorySize, HG_SMEM);
    cudaFuncSetAttribute(attn_mma, cudaFuncAttributeMaxDynamicSharedMemorySize, AT_SMEM);

    // splits
    ksplit<<<(Q * H) / 1024, 256>>>(hs, hshi, hslo);
    ksplit<<<(NH * HD * H) / 1024, 256>>>(Wq, wqhi, wqlo);
    ksplit<<<(NKV * HD * H) / 1024, 256>>>(Wk, wkhi, wklo);
    ksplit<<<(NKV * HD * H) / 1024, 256>>>(Wv, wvhi, wvlo);
    ksplit<<<(NH * HD * NH * HD) / 1024, 256>>>(Wo, wohi, wolo);
    ksplit_cache<<<(NKV * PAST * HD) / 1024, 256>>>(pastK, kphi, kplo);
    ksplit_cache<<<(NKV * PAST * HD) / 1024, 256>>>(pastV, vphi, vplo);

    // fused QKV projection
    hgemm_qkv<<<dim3(32, Q / 128), 256, HG_SMEM>>>(
        hshi, hslo, wqhi, wqlo, wkhi, wklo, wvhi, wvlo,
        qtmp, ktmp, newV, vphi, vplo);

    // rmsnorm + rope (+ splits)
    norm_rope<<<dim3(Q, NH + NKV), 128>>>(qtmp, ktmp, cosb, sinb, qw, kw,
                                          qphi, qplo, newK, kphi, kplo);

    // attention
    attn_mma<<<dim3(NH, Q / AT_TQ), 256, AT_SMEM>>>(
        qphi, qplo, kphi, kplo, vphi, vplo, aohi, aolo);

    // output projection
    hgemm_o<<<dim3(NH * HD / 128, Q / 128), 256, HG_SMEM>>>(
        aohi, aolo, wohi, wolo, out);
}

// round 7
// speedup vs baseline: 5.6442x; 1.0195x over previous
#include <cuda_runtime.h>
#include <cuda_bf16.h>
#include <cstdint>

#define Q    2048
#define H    2048
#define NH   16
#define NKV  8
#define HD   128
#define PAST 2048
#define KVLEN (PAST + Q)
#define KEPS 1e-6f

typedef __nv_bfloat16 bf16;

// ---------------- scratch (no allocation allowed) ----------------
__device__ float g_qtmp[Q * NH * HD];
__device__ float g_ktmp[Q * NKV * HD];
__device__ bf16 g_hs_hi[Q * H],            g_hs_lo[Q * H];
__device__ bf16 g_wq_hi[NH * HD * H],      g_wq_lo[NH * HD * H];
__device__ bf16 g_wk_hi[NKV * HD * H],     g_wk_lo[NKV * HD * H];
__device__ bf16 g_wv_hi[NKV * HD * H],     g_wv_lo[NKV * HD * H];
__device__ bf16 g_wo_hi[NH * HD * NH * HD], g_wo_lo[NH * HD * NH * HD];
__device__ bf16 g_q_hi[NH * Q * HD],       g_q_lo[NH * Q * HD];
__device__ bf16 g_k_hi[NKV * KVLEN * HD],  g_k_lo[NKV * KVLEN * HD];
__device__ bf16 g_v_hi[NKV * KVLEN * HD],  g_v_lo[NKV * KVLEN * HD];
__device__ bf16 g_ao_hi[Q * NH * HD],      g_ao_lo[Q * NH * HD];

// ---------------- helpers ----------------
__device__ __forceinline__ uint32_t smem_u32(const void* p) {
    uint32_t a;
    asm("{ .reg .u64 t; cvta.to.shared.u64 t, %1; cvt.u32.u64 %0, t; }" : "=r"(a) : "l"(p));
    return a;
}
__device__ __forceinline__ uint32_t packbf(bf16 a, bf16 b) {
    return (uint32_t)__bfloat16_as_ushort(a) | ((uint32_t)__bfloat16_as_ushort(b) << 16);
}
__device__ __forceinline__ void split2(float a, float b, uint32_t& hi, uint32_t& lo) {
    bf16 ha = __float2bfloat16_rn(a), hb = __float2bfloat16_rn(b);
    hi = packbf(ha, hb);
    lo = packbf(__float2bfloat16_rn(a - __bfloat162float(ha)),
                __float2bfloat16_rn(b - __bfloat162float(hb)));
}
__device__ __forceinline__ void ldsm4(uint32_t* r, uint32_t addr) {
    asm volatile("ldmatrix.sync.aligned.m8n8.x4.shared.b16 {%0,%1,%2,%3}, [%4];"
                 : "=r"(r[0]), "=r"(r[1]), "=r"(r[2]), "=r"(r[3]) : "r"(addr));
}
__device__ __forceinline__ void ldsm4t(uint32_t* r, uint32_t addr) {
    asm volatile("ldmatrix.sync.aligned.m8n8.x4.trans.shared.b16 {%0,%1,%2,%3}, [%4];"
                 : "=r"(r[0]), "=r"(r[1]), "=r"(r[2]), "=r"(r[3]) : "r"(addr));
}
__device__ __forceinline__ void mma_bf16(float* c, const uint32_t* a, const uint32_t* b) {
    asm volatile(
        "mma.sync.aligned.m16n8k16.row.col.f32.bf16.bf16.f32 "
        "{%0,%1,%2,%3}, {%4,%5,%6,%7}, {%8,%9}, {%0,%1,%2,%3};"
        : "+f"(c[0]), "+f"(c[1]), "+f"(c[2]), "+f"(c[3])
        : "r"(a[0]), "r"(a[1]), "r"(a[2]), "r"(a[3]), "r"(b[0]), "r"(b[1]));
}
__device__ __forceinline__ void cp16(uint32_t dst, const void* src) {
    asm volatile("cp.async.cg.shared.global [%0], [%1], 16;"
                 :: "r"(dst), "l"(__cvta_generic_to_global(src)));
}
__device__ __forceinline__ void cpcommit() { asm volatile("cp.async.commit_group;"); }
template <int N>
__device__ __forceinline__ void cpwait() {
    asm volatile("cp.async.wait_group %0;" :: "n"(N));
}
__device__ __forceinline__ float ex2(float x) {
    float y;
    asm("ex2.approx.f32 %0, %1;" : "=f"(y) : "f"(x));
    return y;
}

// ---------------- merged split kernels ----------------
// block ranges in units of 1024 floats (256 thr x float4):
// hs [0,4096) wq [4096,8192) wk [8192,10240) wv [10240,12288) wo [12288,16384)
__global__ __launch_bounds__(256) void ksplit_all(
    const float* __restrict__ hs, bf16* __restrict__ hshi, bf16* __restrict__ hslo,
    const float* __restrict__ wq, bf16* __restrict__ wqhi, bf16* __restrict__ wqlo,
    const float* __restrict__ wk, bf16* __restrict__ wkhi, bf16* __restrict__ wklo,
    const float* __restrict__ wv, bf16* __restrict__ wvhi, bf16* __restrict__ wvlo,
    const float* __restrict__ wo, bf16* __restrict__ wohi, bf16* __restrict__ wolo)
{
    int b = blockIdx.x;
    const float* src;
    bf16 *hi, *lo;
    int base;
    if (b < 4096)       { src = hs; hi = hshi; lo = hslo; base = 0; }
    else if (b < 8192)  { src = wq; hi = wqhi; lo = wqlo; base = 4096; }
    else if (b < 10240) { src = wk; hi = wkhi; lo = wklo; base = 8192; }
    else if (b < 12288) { src = wv; hi = wvhi; lo = wvlo; base = 10240; }
    else                { src = wo; hi = wohi; lo = wolo; base = 12288; }
    int i = (b - base) * 256 + threadIdx.x;
    float4 v = ((const float4*)src)[i];
    uint32_t h0, l0, h1, l1;
    split2(v.x, v.y, h0, l0);
    split2(v.z, v.w, h1, l1);
    ((uint32_t*)hi)[2 * i] = h0;  ((uint32_t*)hi)[2 * i + 1] = h1;
    ((uint32_t*)lo)[2 * i] = l0;  ((uint32_t*)lo)[2 * i + 1] = l1;
}
// both caches: grid 2*2048, x>=2048 -> V
__global__ __launch_bounds__(256) void ksplit_cache2(
    const float* __restrict__ pk, bf16* __restrict__ khi, bf16* __restrict__ klo,
    const float* __restrict__ pv, bf16* __restrict__ vhi, bf16* __restrict__ vlo)
{
    int b = blockIdx.x;
    const float* x;
    bf16 *hi, *lo;
    if (b < 2048) { x = pk; hi = khi; lo = klo; }
    else          { x = pv; hi = vhi; lo = vlo; b -= 2048; }
    int i = b * 256 + threadIdx.x;
    int e = i * 4;
    int kv = e / (PAST * HD);
    int rem = e - kv * (PAST * HD);
    size_t de = (size_t)kv * (KVLEN * HD) + rem;
    float4 v = ((const float4*)x)[i];
    uint32_t h0, l0, h1, l1;
    split2(v.x, v.y, h0, l0);
    split2(v.z, v.w, h1, l1);
    *(uint32_t*)(hi + de) = h0;  *(uint32_t*)(hi + de + 2) = h1;
    *(uint32_t*)(lo + de) = l0;  *(uint32_t*)(lo + de + 2) = l1;
}

// ---------------- GEMM constants ----------------
#define ROWB   80
#define PLANEB 10240
#define STAGEB 40960
#define HG_SMEM (2 * STAGEB)

// ---------------- fused QKV projection GEMM ----------------
__global__ __launch_bounds__(256) void hgemm_qkv(
    const bf16* __restrict__ hshi, const bf16* __restrict__ hslo,
    const bf16* __restrict__ wqhi, const bf16* __restrict__ wqlo,
    const bf16* __restrict__ wkhi, const bf16* __restrict__ wklo,
    const bf16* __restrict__ wvhi, const bf16* __restrict__ wvlo,
    float* __restrict__ qtmp, float* __restrict__ ktmp, float* __restrict__ newV,
    bf16* __restrict__ vphi, bf16* __restrict__ vplo)
{
    extern __shared__ char hsm[];
    const int bx = blockIdx.x;
    const int tid = threadIdx.x;
    const int lane = tid & 31;
    const int wid = tid >> 5;
    const int wm = wid >> 2;
    const int wn = wid & 3;
    const uint32_t base_u = smem_u32(hsm);
    const int K = H;

    const bf16 *Bhi, *Blo;
    int colb;
    if (bx < 16)      { Bhi = wqhi; Blo = wqlo; colb = bx * 128; }
    else if (bx < 24) { Bhi = wkhi; Blo = wklo; colb = (bx - 16) * 128; }
    else              { Bhi = wvhi; Blo = wvlo; colb = (bx - 24) * 128; }

    const bf16* pl[4] = {
        hshi + (size_t)(blockIdx.y * 128) * K, hslo + (size_t)(blockIdx.y * 128) * K,
        Bhi + (size_t)colb * K,                Blo + (size_t)colb * K };

    const int rowselA = lane & 15;
    const int halfA = lane >> 4;
    const int rowselB = (lane & 7) + (lane >> 4) * 8;
    const int halfB = (lane >> 3) & 1;
    const uint32_t aoff0 = (uint32_t)((wm * 64 + rowselA) * ROWB + halfA * 16);
    const uint32_t boff0 = (uint32_t)((wn * 32 + rowselB) * ROWB + halfB * 16);

    float acc[4][4][4];
#pragma unroll
    for (int i = 0; i < 4; i++)
#pragma unroll
        for (int j = 0; j < 4; j++)
#pragma unroll
            for (int r = 0; r < 4; r++) acc[i][j][r] = 0.0f;

    const int nst = K / 32;
    {
        uint32_t dstb = base_u;
        for (int i = tid; i < 2048; i += 256) {
            int p = i >> 9, row = (i >> 2) & 127, seg = i & 3;
            cp16(dstb + p * PLANEB + row * ROWB + seg * 16,
                 pl[p] + (size_t)row * K + seg * 8);
        }
        cpcommit();
    }

    for (int s = 0; s < nst; s++) {
        cpwait<0>();
        __syncthreads();
        if (s + 1 < nst) {
            int kt = (s + 1) * 32;
            uint32_t dstb = base_u + ((s + 1) & 1) * STAGEB;
            for (int i = tid; i < 2048; i += 256) {
                int p = i >> 9, row = (i >> 2) & 127, seg = i & 3;
                cp16(dstb + p * PLANEB + row * ROWB + seg * 16,
                     pl[p] + (size_t)row * K + kt + seg * 8);
            }
            cpcommit();
        }
        const uint32_t sb = base_u + (s & 1) * STAGEB;
#pragma unroll
        for (int kc = 0; kc < 2; kc++) {
            uint32_t ah[4][4], al[4][4];
#pragma unroll
            for (int mi = 0; mi < 4; mi++) {
                uint32_t ad = sb + aoff0 + mi * (16 * ROWB) + kc * 32;
                ldsm4(ah[mi], ad);
                ldsm4(al[mi], ad + PLANEB);
            }
            uint32_t bh[4][2], bl[4][2];
#pragma unroll
            for (int p = 0; p < 2; p++) {
                uint32_t bd = sb + 2 * PLANEB + boff0 + p * (16 * ROWB) + kc * 32;
                uint32_t r[4];
                ldsm4(r, bd);
                bh[2 * p][0] = r[0]; bh[2 * p][1] = r[1];
                bh[2 * p + 1][0] = r[2]; bh[2 * p + 1][1] = r[3];
                ldsm4(r, bd + PLANEB);
                bl[2 * p][0] = r[0]; bl[2 * p][1] = r[1];
                bl[2 * p + 1][0] = r[2]; bl[2 * p + 1][1] = r[3];
            }
#pragma unroll
            for (int mi = 0; mi < 4; mi++) {
#pragma unroll
                for (int nj = 0; nj < 4; nj++) {
                    mma_bf16(acc[mi][nj], ah[mi], bh[nj]);
                    mma_bf16(acc[mi][nj], ah[mi], bl[nj]);
                    mma_bf16(acc[mi][nj], al[mi], bh[nj]);
                }
            }
        }
    }

    const int rfrag = lane >> 2;
    const int cpair = (lane & 3) * 2;
#pragma unroll
    for (int mi = 0; mi < 4; mi++) {
#pragma unroll
        for (int nj = 0; nj < 4; nj++) {
            int coll = colb + wn * 32 + nj * 8 + cpair;
#pragma unroll
            for (int half = 0; half < 2; half++) {
                int rowg = blockIdx.y * 128 + wm * 64 + mi * 16 + rfrag + half * 8;
                float2 v = make_float2(acc[mi][nj][2 * half], acc[mi][nj][2 * half + 1]);
                if (bx < 16) {
                    *(float2*)(qtmp + (size_t)rowg * (NH * HD) + coll) = v;
                } else if (bx < 24) {
                    *(float2*)(ktmp + (size_t)rowg * (NKV * HD) + coll) = v;
                } else {
                    int kv = coll >> 7, d = coll & 127;
                    *(float2*)(newV + (size_t)kv * (Q * HD) + (size_t)rowg * HD + d) = v;
                    uint32_t hh, ll;
                    split2(v.x, v.y, hh, ll);
                    size_t de = (size_t)kv * (KVLEN * HD) + (size_t)(PAST + rowg) * HD + d;
                    *(uint32_t*)(vphi + de) = hh;
                    *(uint32_t*)(vplo + de) = ll;
                }
            }
        }
    }
}

// ---------------- output projection GEMM ----------------
__global__ __launch_bounds__(256) void hgemm_o(
    const bf16* __restrict__ Ahi, const bf16* __restrict__ Alo,
    const bf16* __restrict__ Bhi, const bf16* __restrict__ Blo,
    float* __restrict__ C)
{
    extern __shared__ char hsm[];
    const int tid = threadIdx.x;
    const int lane = tid & 31;
    const int wid = tid >> 5;
    const int wm = wid >> 2;
    const int wn = wid & 3;
    const uint32_t base_u = smem_u32(hsm);
    const int K = NH * HD, N = NH * HD;

    const bf16* pl[4] = {
        Ahi + (size_t)(blockIdx.y * 128) * K, Alo + (size_t)(blockIdx.y * 128) * K,
        Bhi + (size_t)(blockIdx.x * 128) * K, Blo + (size_t)(blockIdx.x * 128) * K };

    const int rowselA = lane & 15;
    const int halfA = lane >> 4;
    const int rowselB = (lane & 7) + (lane >> 4) * 8;
    const int halfB = (lane >> 3) & 1;
    const uint32_t aoff0 = (uint32_t)((wm * 64 + rowselA) * ROWB + halfA * 16);
    const uint32_t boff0 = (uint32_t)((wn * 32 + rowselB) * ROWB + halfB * 16);

    float acc[4][4][4];
#pragma unroll
    for (int i = 0; i < 4; i++)
#pragma unroll
        for (int j = 0; j < 4; j++)
#pragma unroll
            for (int r = 0; r < 4; r++) acc[i][j][r] = 0.0f;

    const int nst = K / 32;
    {
        uint32_t dstb = base_u;
        for (int i = tid; i < 2048; i += 256) {
            int p = i >> 9, row = (i >> 2) & 127, seg = i & 3;
            cp16(dstb + p * PLANEB + row * ROWB + seg * 16,
                 pl[p] + (size_t)row * K + seg * 8);
        }
        cpcommit();
    }

    for (int s = 0; s < nst; s++) {
        cpwait<0>();
        __syncthreads();
        if (s + 1 < nst) {
            int kt = (s + 1) * 32;
            uint32_t dstb = base_u + ((s + 1) & 1) * STAGEB;
            for (int i = tid; i < 2048; i += 256) {
                int p = i >> 9, row = (i >> 2) & 127, seg = i & 3;
                cp16(dstb + p * PLANEB + row * ROWB + seg * 16,
                     pl[p] + (size_t)row * K + kt + seg * 8);
            }
            cpcommit();
        }
        const uint32_t sb = base_u + (s & 1) * STAGEB;
#pragma unroll
        for (int kc = 0; kc < 2; kc++) {
            uint32_t ah[4][4], al[4][4];
#pragma unroll
            for (int mi = 0; mi < 4; mi++) {
                uint32_t ad = sb + aoff0 + mi * (16 * ROWB) + kc * 32;
                ldsm4(ah[mi], ad);
                ldsm4(al[mi], ad + PLANEB);
            }
            uint32_t bh[4][2], bl[4][2];
#pragma unroll
            for (int p = 0; p < 2; p++) {
                uint32_t bd = sb + 2 * PLANEB + boff0 + p * (16 * ROWB) + kc * 32;
                uint32_t r[4];
                ldsm4(r, bd);
                bh[2 * p][0] = r[0]; bh[2 * p][1] = r[1];
                bh[2 * p + 1][0] = r[2]; bh[2 * p + 1][1] = r[3];
                ldsm4(r, bd + PLANEB);
                bl[2 * p][0] = r[0]; bl[2 * p][1] = r[1];
                bl[2 * p + 1][0] = r[2]; bl[2 * p + 1][1] = r[3];
            }
#pragma unroll
            for (int mi = 0; mi < 4; mi++) {
#pragma unroll
                for (int nj = 0; nj < 4; nj++) {
                    mma_bf16(acc[mi][nj], ah[mi], bh[nj]);
                    mma_bf16(acc[mi][nj], ah[mi], bl[nj]);
                    mma_bf16(acc[mi][nj], al[mi], bh[nj]);
                }
            }
        }
    }

    const int rfrag = lane >> 2;
    const int cpair = (lane & 3) * 2;
#pragma unroll
    for (int mi = 0; mi < 4; mi++) {
#pragma unroll
        for (int nj = 0; nj < 4; nj++) {
            int colg = blockIdx.x * 128 + wn * 32 + nj * 8 + cpair;
#pragma unroll
            for (int half = 0; half < 2; half++) {
                int rowg = blockIdx.y * 128 + wm * 64 + mi * 16 + rfrag + half * 8;
                *(float2*)(C + (size_t)rowg * N + colg) =
                    make_float2(acc[mi][nj][2 * half], acc[mi][nj][2 * half + 1]);
            }
        }
    }
}

// ---------------- RMSNorm + RoPE (+ split outputs) ----------------
__global__ __launch_bounds__(128) void norm_rope(
    const float* __restrict__ qtmp, const float* __restrict__ ktmp,
    const float* __restrict__ cosb, const float* __restrict__ sinb,
    const float* __restrict__ qw, const float* __restrict__ kw,
    bf16* __restrict__ qhi, bf16* __restrict__ qlo,
    float* __restrict__ newK,
    bf16* __restrict__ khi, bf16* __restrict__ klo)
{
    const float QSC = 0.08838834764831845f * 1.44269504088896341f;
    int s = blockIdx.x;
    int hh = blockIdx.y;
    int t = threadIdx.x;

    const float* src;
    const float* w;
    if (hh < NH) {
        src = qtmp + (size_t)s * (NH * HD) + hh * HD;
        w = qw;
    } else {
        src = ktmp + (size_t)s * (NKV * HD) + (hh - NH) * HD;
        w = kw;
    }

    float x = src[t];
    float v = x * x;
#pragma unroll
    for (int o = 16; o; o >>= 1) v += __shfl_xor_sync(0xffffffffu, v, o);
    __shared__ float red[4];
    if ((t & 31) == 0) red[t >> 5] = v;
    __syncthreads();
    float sum = red[0] + red[1] + red[2] + red[3];
    float rs = rsqrtf(sum * (1.0f / HD) + KEPS);
    float xn = x * rs * w[t];

    __shared__ float sh[HD];
    sh[t] = xn;
    __syncthreads();
    float c = cosb[(size_t)s * HD + t];
    float si = sinb[(size_t)s * HD + t];
    float rot = (t < 64) ? -sh[t + 64] : sh[t - 64];
    float val = xn * c + rot * si;

    if (hh < NH) {
        float sv = val * QSC;
        bf16 hv = __float2bfloat16_rn(sv);
        size_t idx = ((size_t)hh * Q + s) * HD + t;
        qhi[idx] = hv;
        qlo[idx] = __float2bfloat16_rn(sv - __bfloat162float(hv));
    } else {
        int kv = hh - NH;
        newK[((size_t)kv * Q + s) * HD + t] = val;
        bf16 hv = __float2bfloat16_rn(val);
        size_t idx = ((size_t)kv * KVLEN + PAST + s) * HD + t;
        khi[idx] = hv;
        klo[idx] = __float2bfloat16_rn(val - __bfloat162float(hv));
    }
}

// ---------------- Flash attention with mma.sync ----------------
#define AT_TQ 128
#define AT_TK 64
#define KVROW 272
#define KVPLANE (64 * KVROW)
#define TILEBUF (4 * KVPLANE)
#define AT_SMEM (2 * TILEBUF)
#define QPLANE (128 * KVROW)

__global__ __launch_bounds__(256, 1) void attn_mma(
    const bf16* __restrict__ qhi, const bf16* __restrict__ qlo,
    const bf16* __restrict__ khi, const bf16* __restrict__ klo,
    const bf16* __restrict__ vhi, const bf16* __restrict__ vlo,
    bf16* __restrict__ aohi, bf16* __restrict__ aolo)
{
    extern __shared__ char asmem[];
    const int h = blockIdx.x;
    const int q0 = ((int)gridDim.y - 1 - (int)blockIdx.y) * AT_TQ;  // largest-first
    const int kvh = h >> 1;
    const int tid = threadIdx.x;
    const int lane = tid & 31;
    const int wid = tid >> 5;
    const uint32_t sb = smem_u32(asmem);

    {
        const bf16* qsrc[2] = { qhi + ((size_t)h * Q + q0) * HD,
                                qlo + ((size_t)h * Q + q0) * HD };
        for (int i = tid; i < 4096; i += 256) {
            int p = i >> 11, row = (i >> 4) & 127, seg = i & 15;
            cp16(sb + p * QPLANE + row * KVROW + seg * 16,
                 qsrc[p] + (size_t)row * HD + seg * 8);
        }
        cpcommit();
        cpwait<0>();
        __syncthreads();
    }
    uint32_t aQh[8][4], aQl[8][4];
    {
        uint32_t a0 = sb + (wid * 16 + (lane & 15)) * KVROW + (lane >> 4) * 16;
#pragma unroll
        for (int kc = 0; kc < 8; kc++) {
            ldsm4(aQh[kc], a0 + kc * 32);
            ldsm4(aQl[kc], a0 + kc * 32 + QPLANE);
        }
    }
    __syncthreads();

    float oacc[16][4];
#pragma unroll
    for (int f = 0; f < 16; f++)
#pragma unroll
        for (int r = 0; r < 4; r++) oacc[f][r] = 0.0f;
    float m0 = -1e30f, m1 = -1e30f, l0 = 0.0f, l1 = 0.0f;

    const int nt = (PAST + q0 + AT_TQ) / AT_TK;
    const bf16* ksrc[2] = { khi + (size_t)kvh * KVLEN * HD, klo + (size_t)kvh * KVLEN * HD };
    const bf16* vsrc[2] = { vhi + (size_t)kvh * KVLEN * HD, vlo + (size_t)kvh * KVLEN * HD };

    {
        for (int i = tid; i < 4096; i += 256) {
            int p = i >> 10, row = (i >> 4) & 63, seg = i & 15;
            const bf16* s0 = (p < 2) ? ksrc[p] : vsrc[p - 2];
            cp16(sb + p * KVPLANE + row * KVROW + seg * 16,
                 s0 + (size_t)row * HD + seg * 8);
        }
        cpcommit();
    }

    const int rowselB = (lane & 7) + (lane >> 4) * 8;
    const int halfB = (lane >> 3) & 1;
    const int rowV = lane & 15;
    const int halfV = (lane >> 4) * 16;

    for (int t = 0; t < nt; t++) {
        __syncthreads();
        if (t + 1 < nt) {
            int j1 = (t + 1) * AT_TK;
            uint32_t db = sb + ((t + 1) & 1) * TILEBUF;
            for (int i = tid; i < 4096; i += 256) {
                int p = i >> 10, row = (i >> 4) & 63, seg = i & 15;
                const bf16* s0 = (p < 2) ? ksrc[p] : vsrc[p - 2];
                cp16(db + p * KVPLANE + row * KVROW + seg * 16,
                     s0 + (size_t)(j1 + row) * HD + seg * 8);
            }
            cpcommit();
            cpwait<1>();
        } else {
            cpwait<0>();
        }
        __syncthreads();

        const uint32_t kb = sb + (t & 1) * TILEBUF;
        const int j0 = t * AT_TK;

        // ---- S = Q K^T : kc outer / nj inner -> 8 accumulator chains ----
        float sacc[8][4];
#pragma unroll
        for (int j = 0; j < 8; j++)
#pragma unroll
            for (int r = 0; r < 4; r++) sacc[j][r] = 0.0f;
#pragma unroll
        for (int kc = 0; kc < 8; kc++) {
#pragma unroll
            for (int nj = 0; nj < 4; nj++) {
                uint32_t kh[4], kl[4];
                uint32_t kbase = kb + (nj * 16 + rowselB) * KVROW + halfB * 16 + kc * 32;
                ldsm4(kh, kbase);
                ldsm4(kl, kbase + KVPLANE);
                mma_bf16(sacc[2 * nj],     aQh[kc], kh);
                mma_bf16(sacc[2 * nj],     aQh[kc], kl);
                mma_bf16(sacc[2 * nj],     aQl[kc], kh);
                mma_bf16(sacc[2 * nj + 1], aQh[kc], kh + 2);
                mma_bf16(sacc[2 * nj + 1], aQh[kc], kl + 2);
                mma_bf16(sacc[2 * nj + 1], aQl[kc], kh + 2);
            }
        }

        if (j0 + AT_TK - 1 > PAST + q0 + wid * 16) {
            int r0g = PAST + q0 + wid * 16 + (lane >> 2);
#pragma unroll
            for (int j = 0; j < 8; j++) {
                int cg = j0 + j * 8 + (lane & 3) * 2;
                if (cg > r0g)     sacc[j][0] = -1e30f;
                if (cg + 1 > r0g) sacc[j][1] = -1e30f;
                if (cg > r0g + 8)     sacc[j][2] = -1e30f;
                if (cg + 1 > r0g + 8) sacc[j][3] = -1e30f;
            }
        }

        float t0 = -1e30f, t1 = -1e30f;
#pragma unroll
        for (int j = 0; j < 8; j++) {
            t0 = fmaxf(t0, fmaxf(sacc[j][0], sacc[j][1]));
            t1 = fmaxf(t1, fmaxf(sacc[j][2], sacc[j][3]));
        }
        t0 = fmaxf(t0, __shfl_xor_sync(0xffffffffu, t0, 1));
        t0 = fmaxf(t0, __shfl_xor_sync(0xffffffffu, t0, 2));
        t1 = fmaxf(t1, __shfl_xor_sync(0xffffffffu, t1, 1));
        t1 = fmaxf(t1, __shfl_xor_sync(0xffffffffu, t1, 2));
        float mn0 = fmaxf(m0, t0), mn1 = fmaxf(m1, t1);
        float c0 = ex2(m0 - mn0), c1 = ex2(m1 - mn1);
        m0 = mn0; m1 = mn1;
        float ps0 = 0.0f, ps1 = 0.0f;
#pragma unroll
        for (int j = 0; j < 8; j++) {
            sacc[j][0] = ex2(sacc[j][0] - mn0); ps0 += sacc[j][0];
            sacc[j][1] = ex2(sacc[j][1] - mn0); ps0 += sacc[j][1];
            sacc[j][2] = ex2(sacc[j][2] - mn1); ps1 += sacc[j][2];
            sacc[j][3] = ex2(sacc[j][3] - mn1); ps1 += sacc[j][3];
        }
        ps0 += __shfl_xor_sync(0xffffffffu, ps0, 1);
        ps0 += __shfl_xor_sync(0xffffffffu, ps0, 2);
        ps1 += __shfl_xor_sync(0xffffffffu, ps1, 1);
        ps1 += __shfl_xor_sync(0xffffffffu, ps1, 2);
        l0 = l0 * c0 + ps0;
        l1 = l1 * c1 + ps1;
#pragma unroll
        for (int f = 0; f < 16; f++) {
            oacc[f][0] *= c0; oacc[f][1] *= c0;
            oacc[f][2] *= c1; oacc[f][3] *= c1;
        }

        uint32_t pH[4][4], pL[4][4];
#pragma unroll
        for (int kc = 0; kc < 4; kc++) {
            split2(sacc[2 * kc][0],     sacc[2 * kc][1],     pH[kc][0], pL[kc][0]);
            split2(sacc[2 * kc][2],     sacc[2 * kc][3],     pH[kc][1], pL[kc][1]);
            split2(sacc[2 * kc + 1][0], sacc[2 * kc + 1][1], pH[kc][2], pL[kc][2]);
            split2(sacc[2 * kc + 1][2], sacc[2 * kc + 1][3], pH[kc][3], pL[kc][3]);
        }

        // ---- O += P V : kc outer / dj inner -> 16 accumulator chains ----
        const uint32_t vb = kb + 2 * KVPLANE;
#pragma unroll
        for (int kc = 0; kc < 4; kc++) {
#pragma unroll
            for (int dj = 0; dj < 8; dj++) {
                uint32_t vh[4], vl[4];
                uint32_t va = vb + (kc * 16 + rowV) * KVROW + dj * 32 + halfV;
                ldsm4t(vh, va);
                ldsm4t(vl, va + KVPLANE);
                mma_bf16(oacc[2 * dj],     pH[kc], vh);
                mma_bf16(oacc[2 * dj],     pH[kc], vl);
                mma_bf16(oacc[2 * dj],     pL[kc], vh);
                mma_bf16(oacc[2 * dj + 1], pH[kc], vh + 2);
                mma_bf16(oacc[2 * dj + 1], pH[kc], vl + 2);
                mma_bf16(oacc[2 * dj + 1], pL[kc], vh + 2);
            }
        }
    }

    float inv0 = 1.0f / l0, inv1 = 1.0f / l1;
    int r0 = q0 + wid * 16 + (lane >> 2);
#pragma unroll
    for (int f = 0; f < 16; f++) {
        int d = f * 8 + (lane & 3) * 2;
        size_t e0 = (size_t)r0 * (NH * HD) + h * HD + d;
        size_t e1 = e0 + (size_t)8 * (NH * HD);
        uint32_t hh, ll;
        split2(oacc[f][0] * inv0, oacc[f][1] * inv0, hh, ll);
        *(uint32_t*)(aohi + e0) = hh;
        *(uint32_t*)(aolo + e0) = ll;
        split2(oacc[f][2] * inv1, oacc[f][3] * inv1, hh, ll);
        *(uint32_t*)(aohi + e1) = hh;
        *(uint32_t*)(aolo + e1) = ll;
    }
}

// ---------------- launch ----------------
extern "C" void kernel_launch(void* const* d_in, const int* in_sizes, int n_in,
                              void* d_out, int out_size)
{
    const float* hs    = (const float*)d_in[0];
    const float* cosb  = (const float*)d_in[1];
    const float* sinb  = (const float*)d_in[2];
    const float* pastK = (const float*)d_in[4];
    const float* pastV = (const float*)d_in[5];
    const float* Wq    = (const float*)d_in[6];
    const float* Wk    = (const float*)d_in[7];
    const float* Wv    = (const float*)d_in[8];
    const float* Wo    = (const float*)d_in[9];
    const float* qw    = (const float*)d_in[10];
    const float* kw    = (const float*)d_in[11];

    float* out  = (float*)d_out;
    float* newK = out + (size_t)Q * NH * HD;
    float* newV = newK + (size_t)NKV * Q * HD;

    float *qtmp, *ktmp;
    bf16 *hshi, *hslo, *wqhi, *wqlo, *wkhi, *wklo, *wvhi, *wvlo, *wohi, *wolo;
    bf16 *qphi, *qplo, *kphi, *kplo, *vphi, *vplo, *aohi, *aolo;
    cudaGetSymbolAddress((void**)&qtmp, g_qtmp);
    cudaGetSymbolAddress((void**)&ktmp, g_ktmp);
    cudaGetSymbolAddress((void**)&hshi, g_hs_hi);
    cudaGetSymbolAddress((void**)&hslo, g_hs_lo);
    cudaGetSymbolAddress((void**)&wqhi, g_wq_hi);
    cudaGetSymbolAddress((void**)&wqlo, g_wq_lo);
    cudaGetSymbolAddress((void**)&wkhi, g_wk_hi);
    cudaGetSymbolAddress((void**)&wklo, g_wk_lo);
    cudaGetSymbolAddress((void**)&wvhi, g_wv_hi);
    cudaGetSymbolAddress((void**)&wvlo, g_wv_lo);
    cudaGetSymbolAddress((void**)&wohi, g_wo_hi);
    cudaGetSymbolAddress((void**)&wolo, g_wo_lo);
    cudaGetSymbolAddress((void**)&qphi, g_q_hi);
    cudaGetSymbolAddress((void**)&qplo, g_q_lo);
    cudaGetSymbolAddress((void**)&kphi, g_k_hi);
    cudaGetSymbolAddress((void**)&kplo, g_k_lo);
    cudaGetSymbolAddress((void**)&vphi, g_v_hi);
    cudaGetSymbolAddress((void**)&vplo, g_v_lo);
    cudaGetSymbolAddress((void**)&aohi, g_ao_hi);
    cudaGetSymbolAddress((void**)&aolo, g_ao_lo);

    cudaFuncSetAttribute(hgemm_qkv, cudaFuncAttributeMaxDynamicSharedMemorySize, HG_SMEM);
    cudaFuncSetAttribute(hgemm_o, cudaFuncAttributeMaxDynamicSharedMemorySize, HG_SMEM);
    cudaFuncSetAttribute(attn_mma, cudaFuncAttributeMaxDynamicSharedMemorySize, AT_SMEM);

    // merged splits (2 launches)
    ksplit_all<<<16384, 256>>>(hs, hshi, hslo, Wq, wqhi, wqlo, Wk, wkhi, wklo,
                               Wv, wvhi, wvlo, Wo, wohi, wolo);
    ksplit_cache2<<<4096, 256>>>(pastK, kphi, kplo, pastV, vphi, vplo);

    // fused QKV projection
    hgemm_qkv<<<dim3(32, Q / 128), 256, HG_SMEM>>>(
        hshi, hslo, wqhi, wqlo, wkhi, wklo, wvhi, wvlo,
        qtmp, ktmp, newV, vphi, vplo);

    // rmsnorm + rope (+ splits)
    norm_rope<<<dim3(Q, NH + NKV), 128>>>(qtmp, ktmp, cosb, sinb, qw, kw,
                                          qphi, qplo, newK, kphi, kplo);

    // attention
    attn_mma<<<dim3(NH, Q / AT_TQ), 256, AT_SMEM>>>(
        qphi, qplo, kphi, kplo, vphi, vplo, aohi, aolo);

    // output projection
    hgemm_o<<<dim3(NH * HD / 128, Q / 128), 256, HG_SMEM>>>(
        aohi, aolo, wohi, wolo, out);
}

// round 8
// speedup vs baseline: 8.6274x; 1.5285x over previous
#include <cuda_runtime.h>
#include <cuda_fp16.h>
#include <cstdint>

#define Q    2048
#define H    2048
#define NH   16
#define NKV  8
#define HD   128
#define PAST 2048
#define KVLEN (PAST + Q)
#define KEPS 1e-6f

typedef __half h16;

// ---------------- scratch (no allocation allowed) ----------------
__device__ float g_qtmp[Q * NH * HD];
__device__ float g_ktmp[Q * NKV * HD];
__device__ h16 g_hs_h[Q * H];                                  // activations: single plane
__device__ h16 g_wq_h[NH * HD * H],      g_wq_l[NH * HD * H];  // weights: split
__device__ h16 g_wk_h[NKV * HD * H],     g_wk_l[NKV * HD * H];
__device__ h16 g_wv_h[NKV * HD * H],     g_wv_l[NKV * HD * H];
__device__ h16 g_wo_h[NH * HD * NH * HD], g_wo_l[NH * HD * NH * HD];
__device__ h16 g_q_h[NH * Q * HD],       g_q_l[NH * Q * HD];   // q split (scaled)
__device__ h16 g_k_h[NKV * KVLEN * HD];                        // K cache: single plane
__device__ h16 g_v_h[NKV * KVLEN * HD];                        // V cache: single plane
__device__ h16 g_ao_h[Q * NH * HD];                            // attn out: single plane

// ---------------- helpers ----------------
__device__ __forceinline__ uint32_t smem_u32(const void* p) {
    uint32_t a;
    asm("{ .reg .u64 t; cvta.to.shared.u64 t, %1; cvt.u32.u64 %0, t; }" : "=r"(a) : "l"(p));
    return a;
}
__device__ __forceinline__ uint32_t packh(h16 a, h16 b) {
    return (uint32_t)__half_as_ushort(a) | ((uint32_t)__half_as_ushort(b) << 16);
}
__device__ __forceinline__ uint32_t cvt2h(float a, float b) {
    return packh(__float2half_rn(a), __float2half_rn(b));
}
__device__ __forceinline__ void split2h(float a, float b, uint32_t& hi, uint32_t& lo) {
    h16 ha = __float2half_rn(a), hb = __float2half_rn(b);
    hi = packh(ha, hb);
    lo = packh(__float2half_rn(a - __half2float(ha)),
               __float2half_rn(b - __half2float(hb)));
}
__device__ __forceinline__ void ldsm4(uint32_t* r, uint32_t addr) {
    asm volatile("ldmatrix.sync.aligned.m8n8.x4.shared.b16 {%0,%1,%2,%3}, [%4];"
                 : "=r"(r[0]), "=r"(r[1]), "=r"(r[2]), "=r"(r[3]) : "r"(addr));
}
__device__ __forceinline__ void ldsm4t(uint32_t* r, uint32_t addr) {
    asm volatile("ldmatrix.sync.aligned.m8n8.x4.trans.shared.b16 {%0,%1,%2,%3}, [%4];"
                 : "=r"(r[0]), "=r"(r[1]), "=r"(r[2]), "=r"(r[3]) : "r"(addr));
}
__device__ __forceinline__ void mma_f16(float* c, const uint32_t* a, const uint32_t* b) {
    asm volatile(
        "mma.sync.aligned.m16n8k16.row.col.f32.f16.f16.f32 "
        "{%0,%1,%2,%3}, {%4,%5,%6,%7}, {%8,%9}, {%0,%1,%2,%3};"
        : "+f"(c[0]), "+f"(c[1]), "+f"(c[2]), "+f"(c[3])
        : "r"(a[0]), "r"(a[1]), "r"(a[2]), "r"(a[3]), "r"(b[0]), "r"(b[1]));
}
__device__ __forceinline__ void cp16(uint32_t dst, const void* src) {
    asm volatile("cp.async.cg.shared.global [%0], [%1], 16;"
                 :: "r"(dst), "l"(__cvta_generic_to_global(src)));
}
__device__ __forceinline__ void cpcommit() { asm volatile("cp.async.commit_group;"); }
template <int N>
__device__ __forceinline__ void cpwait() {
    asm volatile("cp.async.wait_group %0;" :: "n"(N));
}
__device__ __forceinline__ float ex2(float x) {
    float y;
    asm("ex2.approx.f32 %0, %1;" : "=f"(y) : "f"(x));
    return y;
}

// ---------------- merged split kernels ----------------
// block ranges (1024 floats each): hs [0,4096) single-plane,
// wq [4096,8192) wk [8192,10240) wv [10240,12288) wo [12288,16384) split
__global__ __launch_bounds__(256) void ksplit_all(
    const float* __restrict__ hs, h16* __restrict__ hsh,
    const float* __restrict__ wq, h16* __restrict__ wqh, h16* __restrict__ wql,
    const float* __restrict__ wk, h16* __restrict__ wkh, h16* __restrict__ wkl,
    const float* __restrict__ wv, h16* __restrict__ wvh, h16* __restrict__ wvl,
    const float* __restrict__ wo, h16* __restrict__ woh, h16* __restrict__ wol)
{
    int b = blockIdx.x;
    if (b < 4096) {
        int i = b * 256 + threadIdx.x;
        float4 v = ((const float4*)hs)[i];
        ((uint32_t*)hsh)[2 * i]     = cvt2h(v.x, v.y);
        ((uint32_t*)hsh)[2 * i + 1] = cvt2h(v.z, v.w);
        return;
    }
    const float* src;
    h16 *hi, *lo;
    int base;
    if (b < 8192)       { src = wq; hi = wqh; lo = wql; base = 4096; }
    else if (b < 10240) { src = wk; hi = wkh; lo = wkl; base = 8192; }
    else if (b < 12288) { src = wv; hi = wvh; lo = wvl; base = 10240; }
    else                { src = wo; hi = woh; lo = wol; base = 12288; }
    int i = (b - base) * 256 + threadIdx.x;
    float4 v = ((const float4*)src)[i];
    uint32_t h0, l0, h1, l1;
    split2h(v.x, v.y, h0, l0);
    split2h(v.z, v.w, h1, l1);
    ((uint32_t*)hi)[2 * i] = h0;  ((uint32_t*)hi)[2 * i + 1] = h1;
    ((uint32_t*)lo)[2 * i] = l0;  ((uint32_t*)lo)[2 * i + 1] = l1;
}
// both caches -> single fp16 plane each; grid 2*2048
__global__ __launch_bounds__(256) void ksplit_cache2(
    const float* __restrict__ pk, h16* __restrict__ kh,
    const float* __restrict__ pv, h16* __restrict__ vh)
{
    int b = blockIdx.x;
    const float* x;
    h16* dst;
    if (b < 2048) { x = pk; dst = kh; }
    else          { x = pv; dst = vh; b -= 2048; }
    int i = b * 256 + threadIdx.x;
    int e = i * 4;
    int kv = e / (PAST * HD);
    int rem = e - kv * (PAST * HD);
    size_t de = (size_t)kv * (KVLEN * HD) + rem;
    float4 v = ((const float4*)x)[i];
    *(uint32_t*)(dst + de)     = cvt2h(v.x, v.y);
    *(uint32_t*)(dst + de + 2) = cvt2h(v.z, v.w);
}

// ---------------- GEMM constants ----------------
#define ROWB   80
#define PLANEB 10240
#define STAGEB 30720         // 3 planes: A, Bhi, Blo
#define HG_SMEM (2 * STAGEB)

// ---------------- fused QKV projection GEMM ----------------
// grid (32, 16): x<16 -> Q cols, x<24 -> K cols, else V cols
__global__ __launch_bounds__(256) void hgemm_qkv(
    const h16* __restrict__ hsh,
    const h16* __restrict__ wqh, const h16* __restrict__ wql,
    const h16* __restrict__ wkh, const h16* __restrict__ wkl,
    const h16* __restrict__ wvh, const h16* __restrict__ wvl,
    float* __restrict__ qtmp, float* __restrict__ ktmp, float* __restrict__ newV,
    h16* __restrict__ vph)
{
    extern __shared__ char hsm[];
    const int bx = blockIdx.x;
    const int tid = threadIdx.x;
    const int lane = tid & 31;
    const int wid = tid >> 5;
    const int wm = wid >> 2;
    const int wn = wid & 3;
    const uint32_t base_u = smem_u32(hsm);
    const int K = H;

    const h16 *Bhi, *Blo;
    int colb;
    if (bx < 16)      { Bhi = wqh; Blo = wql; colb = bx * 128; }
    else if (bx < 24) { Bhi = wkh; Blo = wkl; colb = (bx - 16) * 128; }
    else              { Bhi = wvh; Blo = wvl; colb = (bx - 24) * 128; }

    const h16* pl[3] = {
        hsh + (size_t)(blockIdx.y * 128) * K,
        Bhi + (size_t)colb * K,
        Blo + (size_t)colb * K };

    const int rowselA = lane & 15;
    const int halfA = lane >> 4;
    const int rowselB = (lane & 7) + (lane >> 4) * 8;
    const int halfB = (lane >> 3) & 1;
    const uint32_t aoff0 = (uint32_t)((wm * 64 + rowselA) * ROWB + halfA * 16);
    const uint32_t boff0 = (uint32_t)((wn * 32 + rowselB) * ROWB + halfB * 16);

    float acc[4][4][4];
#pragma unroll
    for (int i = 0; i < 4; i++)
#pragma unroll
        for (int j = 0; j < 4; j++)
#pragma unroll
            for (int r = 0; r < 4; r++) acc[i][j][r] = 0.0f;

    const int nst = K / 32;
    {
        uint32_t dstb = base_u;
        for (int i = tid; i < 1536; i += 256) {
            int p = i >> 9, row = (i >> 2) & 127, seg = i & 3;
            cp16(dstb + p * PLANEB + row * ROWB + seg * 16,
                 pl[p] + (size_t)row * K + seg * 8);
        }
        cpcommit();
    }

    for (int s = 0; s < nst; s++) {
        cpwait<0>();
        __syncthreads();
        if (s + 1 < nst) {
            int kt = (s + 1) * 32;
            uint32_t dstb = base_u + ((s + 1) & 1) * STAGEB;
            for (int i = tid; i < 1536; i += 256) {
                int p = i >> 9, row = (i >> 2) & 127, seg = i & 3;
                cp16(dstb + p * PLANEB + row * ROWB + seg * 16,
                     pl[p] + (size_t)row * K + kt + seg * 8);
            }
            cpcommit();
        }
        const uint32_t sb = base_u + (s & 1) * STAGEB;
#pragma unroll
        for (int kc = 0; kc < 2; kc++) {
            uint32_t ah[4][4];
#pragma unroll
            for (int mi = 0; mi < 4; mi++)
                ldsm4(ah[mi], sb + aoff0 + mi * (16 * ROWB) + kc * 32);
            uint32_t bh[4][2], bl[4][2];
#pragma unroll
            for (int p = 0; p < 2; p++) {
                uint32_t bd = sb + PLANEB + boff0 + p * (16 * ROWB) + kc * 32;
                uint32_t r[4];
                ldsm4(r, bd);
                bh[2 * p][0] = r[0]; bh[2 * p][1] = r[1];
                bh[2 * p + 1][0] = r[2]; bh[2 * p + 1][1] = r[3];
                ldsm4(r, bd + PLANEB);
                bl[2 * p][0] = r[0]; bl[2 * p][1] = r[1];
                bl[2 * p + 1][0] = r[2]; bl[2 * p + 1][1] = r[3];
            }
#pragma unroll
            for (int mi = 0; mi < 4; mi++) {
#pragma unroll
                for (int nj = 0; nj < 4; nj++) {
                    mma_f16(acc[mi][nj], ah[mi], bh[nj]);
                    mma_f16(acc[mi][nj], ah[mi], bl[nj]);
                }
            }
        }
    }

    const int rfrag = lane >> 2;
    const int cpair = (lane & 3) * 2;
#pragma unroll
    for (int mi = 0; mi < 4; mi++) {
#pragma unroll
        for (int nj = 0; nj < 4; nj++) {
            int coll = colb + wn * 32 + nj * 8 + cpair;
#pragma unroll
            for (int half = 0; half < 2; half++) {
                int rowg = blockIdx.y * 128 + wm * 64 + mi * 16 + rfrag + half * 8;
                float2 v = make_float2(acc[mi][nj][2 * half], acc[mi][nj][2 * half + 1]);
                if (bx < 16) {
                    *(float2*)(qtmp + (size_t)rowg * (NH * HD) + coll) = v;
                } else if (bx < 24) {
                    *(float2*)(ktmp + (size_t)rowg * (NKV * HD) + coll) = v;
                } else {
                    int kv = coll >> 7, d = coll & 127;
                    *(float2*)(newV + (size_t)kv * (Q * HD) + (size_t)rowg * HD + d) = v;
                    size_t de = (size_t)kv * (KVLEN * HD) + (size_t)(PAST + rowg) * HD + d;
                    *(uint32_t*)(vph + de) = cvt2h(v.x, v.y);
                }
            }
        }
    }
}

// ---------------- output projection GEMM ----------------
__global__ __launch_bounds__(256) void hgemm_o(
    const h16* __restrict__ Ah,
    const h16* __restrict__ Bhi, const h16* __restrict__ Blo,
    float* __restrict__ C)
{
    extern __shared__ char hsm[];
    const int tid = threadIdx.x;
    const int lane = tid & 31;
    const int wid = tid >> 5;
    const int wm = wid >> 2;
    const int wn = wid & 3;
    const uint32_t base_u = smem_u32(hsm);
    const int K = NH * HD, N = NH * HD;

    const h16* pl[3] = {
        Ah + (size_t)(blockIdx.y * 128) * K,
        Bhi + (size_t)(blockIdx.x * 128) * K,
        Blo + (size_t)(blockIdx.x * 128) * K };

    const int rowselA = lane & 15;
    const int halfA = lane >> 4;
    const int rowselB = (lane & 7) + (lane >> 4) * 8;
    const int halfB = (lane >> 3) & 1;
    const uint32_t aoff0 = (uint32_t)((wm * 64 + rowselA) * ROWB + halfA * 16);
    const uint32_t boff0 = (uint32_t)((wn * 32 + rowselB) * ROWB + halfB * 16);

    float acc[4][4][4];
#pragma unroll
    for (int i = 0; i < 4; i++)
#pragma unroll
        for (int j = 0; j < 4; j++)
#pragma unroll
            for (int r = 0; r < 4; r++) acc[i][j][r] = 0.0f;

    const int nst = K / 32;
    {
        uint32_t dstb = base_u;
        for (int i = tid; i < 1536; i += 256) {
            int p = i >> 9, row = (i >> 2) & 127, seg = i & 3;
            cp16(dstb + p * PLANEB + row * ROWB + seg * 16,
                 pl[p] + (size_t)row * K + seg * 8);
        }
        cpcommit();
    }

    for (int s = 0; s < nst; s++) {
        cpwait<0>();
        __syncthreads();
        if (s + 1 < nst) {
            int kt = (s + 1) * 32;
            uint32_t dstb = base_u + ((s + 1) & 1) * STAGEB;
            for (int i = tid; i < 1536; i += 256) {
                int p = i >> 9, row = (i >> 2) & 127, seg = i & 3;
                cp16(dstb + p * PLANEB + row * ROWB + seg * 16,
                     pl[p] + (size_t)row * K + kt + seg * 8);
            }
            cpcommit();
        }
        const uint32_t sb = base_u + (s & 1) * STAGEB;
#pragma unroll
        for (int kc = 0; kc < 2; kc++) {
            uint32_t ah[4][4];
#pragma unroll
            for (int mi = 0; mi < 4; mi++)
                ldsm4(ah[mi], sb + aoff0 + mi * (16 * ROWB) + kc * 32);
            uint32_t bh[4][2], bl[4][2];
#pragma unroll
            for (int p = 0; p < 2; p++) {
                uint32_t bd = sb + PLANEB + boff0 + p * (16 * ROWB) + kc * 32;
                uint32_t r[4];
                ldsm4(r, bd);
                bh[2 * p][0] = r[0]; bh[2 * p][1] = r[1];
                bh[2 * p + 1][0] = r[2]; bh[2 * p + 1][1] = r[3];
                ldsm4(r, bd + PLANEB);
                bl[2 * p][0] = r[0]; bl[2 * p][1] = r[1];
                bl[2 * p + 1][0] = r[2]; bl[2 * p + 1][1] = r[3];
            }
#pragma unroll
            for (int mi = 0; mi < 4; mi++) {
#pragma unroll
                for (int nj = 0; nj < 4; nj++) {
                    mma_f16(acc[mi][nj], ah[mi], bh[nj]);
                    mma_f16(acc[mi][nj], ah[mi], bl[nj]);
                }
            }
        }
    }

    const int rfrag = lane >> 2;
    const int cpair = (lane & 3) * 2;
#pragma unroll
    for (int mi = 0; mi < 4; mi++) {
#pragma unroll
        for (int nj = 0; nj < 4; nj++) {
            int colg = blockIdx.x * 128 + wn * 32 + nj * 8 + cpair;
#pragma unroll
            for (int half = 0; half < 2; half++) {
                int rowg = blockIdx.y * 128 + wm * 64 + mi * 16 + rfrag + half * 8;
                *(float2*)(C + (size_t)rowg * N + colg) =
                    make_float2(acc[mi][nj][2 * half], acc[mi][nj][2 * half + 1]);
            }
        }
    }
}

// ---------------- RMSNorm + RoPE (+ fp16 outputs) ----------------
__global__ __launch_bounds__(128) void norm_rope(
    const float* __restrict__ qtmp, const float* __restrict__ ktmp,
    const float* __restrict__ cosb, const float* __restrict__ sinb,
    const float* __restrict__ qw, const float* __restrict__ kw,
    h16* __restrict__ qh, h16* __restrict__ ql,
    float* __restrict__ newK, h16* __restrict__ kh)
{
    const float QSC = 0.08838834764831845f * 1.44269504088896341f;
    int s = blockIdx.x;
    int hh = blockIdx.y;
    int t = threadIdx.x;

    const float* src;
    const float* w;
    if (hh < NH) {
        src = qtmp + (size_t)s * (NH * HD) + hh * HD;
        w = qw;
    } else {
        src = ktmp + (size_t)s * (NKV * HD) + (hh - NH) * HD;
        w = kw;
    }

    float x = src[t];
    float v = x * x;
#pragma unroll
    for (int o = 16; o; o >>= 1) v += __shfl_xor_sync(0xffffffffu, v, o);
    __shared__ float red[4];
    if ((t & 31) == 0) red[t >> 5] = v;
    __syncthreads();
    float sum = red[0] + red[1] + red[2] + red[3];
    float rs = rsqrtf(sum * (1.0f / HD) + KEPS);
    float xn = x * rs * w[t];

    __shared__ float sh[HD];
    sh[t] = xn;
    __syncthreads();
    float c = cosb[(size_t)s * HD + t];
    float si = sinb[(size_t)s * HD + t];
    float rot = (t < 64) ? -sh[t + 64] : sh[t - 64];
    float val = xn * c + rot * si;

    if (hh < NH) {
        float sv = val * QSC;
        h16 hv = __float2half_rn(sv);
        size_t idx = ((size_t)hh * Q + s) * HD + t;
        qh[idx] = hv;
        ql[idx] = __float2half_rn(sv - __half2float(hv));
    } else {
        int kv = hh - NH;
        newK[((size_t)kv * Q + s) * HD + t] = val;
        kh[((size_t)kv * KVLEN + PAST + s) * HD + t] = __float2half_rn(val);
    }
}

// ---------------- Flash attention with mma.sync (fp16) ----------------
#define AT_TQ 128
#define AT_TK 64
#define KVROW 272
#define KVPLANE (64 * KVROW)         // 17408
#define TILEBUF (2 * KVPLANE)        // K + V single planes = 34816
#define AT_SMEM (2 * TILEBUF)        // 69632
#define QPLANE (128 * KVROW)         // 34816

__global__ __launch_bounds__(256, 1) void attn_mma(
    const h16* __restrict__ qh, const h16* __restrict__ ql,
    const h16* __restrict__ kch, const h16* __restrict__ vch,
    h16* __restrict__ aoh)
{
    extern __shared__ char asmem[];
    const int h = blockIdx.x;
    const int q0 = ((int)gridDim.y - 1 - (int)blockIdx.y) * AT_TQ;  // largest-first
    const int kvh = h >> 1;
    const int tid = threadIdx.x;
    const int lane = tid & 31;
    const int wid = tid >> 5;
    const uint32_t sb = smem_u32(asmem);

    // stage Q (2 planes fill entire smem), extract fragments
    {
        const h16* qsrc[2] = { qh + ((size_t)h * Q + q0) * HD,
                               ql + ((size_t)h * Q + q0) * HD };
        for (int i = tid; i < 4096; i += 256) {
            int p = i >> 11, row = (i >> 4) & 127, seg = i & 15;
            cp16(sb + p * QPLANE + row * KVROW + seg * 16,
                 qsrc[p] + (size_t)row * HD + seg * 8);
        }
        cpcommit();
        cpwait<0>();
        __syncthreads();
    }
    uint32_t aQh[8][4], aQl[8][4];
    {
        uint32_t a0 = sb + (wid * 16 + (lane & 15)) * KVROW + (lane >> 4) * 16;
#pragma unroll
        for (int kc = 0; kc < 8; kc++) {
            ldsm4(aQh[kc], a0 + kc * 32);
            ldsm4(aQl[kc], a0 + kc * 32 + QPLANE);
        }
    }
    __syncthreads();

    float oacc[16][4];
#pragma unroll
    for (int f = 0; f < 16; f++)
#pragma unroll
        for (int r = 0; r < 4; r++) oacc[f][r] = 0.0f;
    float m0 = -1e30f, m1 = -1e30f, l0 = 0.0f, l1 = 0.0f;

    const int nt = (PAST + q0 + AT_TQ) / AT_TK;
    const h16* ksrc = kch + (size_t)kvh * KVLEN * HD;
    const h16* vsrc = vch + (size_t)kvh * KVLEN * HD;

    // preload tile 0 into buf 0 (K plane then V plane)
    {
        for (int i = tid; i < 2048; i += 256) {
            int p = i >> 10, row = (i >> 4) & 63, seg = i & 15;
            const h16* s0 = p ? vsrc : ksrc;
            cp16(sb + p * KVPLANE + row * KVROW + seg * 16,
                 s0 + (size_t)row * HD + seg * 8);
        }
        cpcommit();
    }

    const int rowselB = (lane & 7) + (lane >> 4) * 8;
    const int halfB = (lane >> 3) & 1;
    const int rowV = lane & 15;
    const int halfV = (lane >> 4) * 16;

    for (int t = 0; t < nt; t++) {
        __syncthreads();
        if (t + 1 < nt) {
            int j1 = (t + 1) * AT_TK;
            uint32_t db = sb + ((t + 1) & 1) * TILEBUF;
            for (int i = tid; i < 2048; i += 256) {
                int p = i >> 10, row = (i >> 4) & 63, seg = i & 15;
                const h16* s0 = p ? vsrc : ksrc;
                cp16(db + p * KVPLANE + row * KVROW + seg * 16,
                     s0 + (size_t)(j1 + row) * HD + seg * 8);
            }
            cpcommit();
            cpwait<1>();
        } else {
            cpwait<0>();
        }
        __syncthreads();

        const uint32_t kb = sb + (t & 1) * TILEBUF;
        const int j0 = t * AT_TK;

        // ---- S = Q K^T : Q split, K single ----
        float sacc[8][4];
#pragma unroll
        for (int j = 0; j < 8; j++)
#pragma unroll
            for (int r = 0; r < 4; r++) sacc[j][r] = 0.0f;
#pragma unroll
        for (int kc = 0; kc < 8; kc++) {
#pragma unroll
            for (int nj = 0; nj < 4; nj++) {
                uint32_t kh[4];
                ldsm4(kh, kb + (nj * 16 + rowselB) * KVROW + halfB * 16 + kc * 32);
                mma_f16(sacc[2 * nj],     aQh[kc], kh);
                mma_f16(sacc[2 * nj],     aQl[kc], kh);
                mma_f16(sacc[2 * nj + 1], aQh[kc], kh + 2);
                mma_f16(sacc[2 * nj + 1], aQl[kc], kh + 2);
            }
        }

        if (j0 + AT_TK - 1 > PAST + q0 + wid * 16) {
            int r0g = PAST + q0 + wid * 16 + (lane >> 2);
#pragma unroll
            for (int j = 0; j < 8; j++) {
                int cg = j0 + j * 8 + (lane & 3) * 2;
                if (cg > r0g)     sacc[j][0] = -1e30f;
                if (cg + 1 > r0g) sacc[j][1] = -1e30f;
                if (cg > r0g + 8)     sacc[j][2] = -1e30f;
                if (cg + 1 > r0g + 8) sacc[j][3] = -1e30f;
            }
        }

        float t0 = -1e30f, t1 = -1e30f;
#pragma unroll
        for (int j = 0; j < 8; j++) {
            t0 = fmaxf(t0, fmaxf(sacc[j][0], sacc[j][1]));
            t1 = fmaxf(t1, fmaxf(sacc[j][2], sacc[j][3]));
        }
        t0 = fmaxf(t0, __shfl_xor_sync(0xffffffffu, t0, 1));
        t0 = fmaxf(t0, __shfl_xor_sync(0xffffffffu, t0, 2));
        t1 = fmaxf(t1, __shfl_xor_sync(0xffffffffu, t1, 1));
        t1 = fmaxf(t1, __shfl_xor_sync(0xffffffffu, t1, 2));
        float mn0 = fmaxf(m0, t0), mn1 = fmaxf(m1, t1);
        float c0 = ex2(m0 - mn0), c1 = ex2(m1 - mn1);
        m0 = mn0; m1 = mn1;
        float ps0 = 0.0f, ps1 = 0.0f;
#pragma unroll
        for (int j = 0; j < 8; j++) {
            sacc[j][0] = ex2(sacc[j][0] - mn0); ps0 += sacc[j][0];
            sacc[j][1] = ex2(sacc[j][1] - mn0); ps0 += sacc[j][1];
            sacc[j][2] = ex2(sacc[j][2] - mn1); ps1 += sacc[j][2];
            sacc[j][3] = ex2(sacc[j][3] - mn1); ps1 += sacc[j][3];
        }
        ps0 += __shfl_xor_sync(0xffffffffu, ps0, 1);
        ps0 += __shfl_xor_sync(0xffffffffu, ps0, 2);
        ps1 += __shfl_xor_sync(0xffffffffu, ps1, 1);
        ps1 += __shfl_xor_sync(0xffffffffu, ps1, 2);
        l0 = l0 * c0 + ps0;
        l1 = l1 * c1 + ps1;
#pragma unroll
        for (int f = 0; f < 16; f++) {
            oacc[f][0] *= c0; oacc[f][1] *= c0;
            oacc[f][2] *= c1; oacc[f][3] *= c1;
        }

        // ---- pack P (split), V single ----
        uint32_t pH[4][4], pL[4][4];
#pragma unroll
        for (int kc = 0; kc < 4; kc++) {
            split2h(sacc[2 * kc][0],     sacc[2 * kc][1],     pH[kc][0], pL[kc][0]);
            split2h(sacc[2 * kc][2],     sacc[2 * kc][3],     pH[kc][1], pL[kc][1]);
            split2h(sacc[2 * kc + 1][0], sacc[2 * kc + 1][1], pH[kc][2], pL[kc][2]);
            split2h(sacc[2 * kc + 1][2], sacc[2 * kc + 1][3], pH[kc][3], pL[kc][3]);
        }

        // ---- O += P V ----
        const uint32_t vb = kb + KVPLANE;
#pragma unroll
        for (int kc = 0; kc < 4; kc++) {
#pragma unroll
            for (int dj = 0; dj < 8; dj++) {
                uint32_t vh[4];
                ldsm4t(vh, vb + (kc * 16 + rowV) * KVROW + dj * 32 + halfV);
                mma_f16(oacc[2 * dj],     pH[kc], vh);
                mma_f16(oacc[2 * dj],     pL[kc], vh);
                mma_f16(oacc[2 * dj + 1], pH[kc], vh + 2);
                mma_f16(oacc[2 * dj + 1], pL[kc], vh + 2);
            }
        }
    }

    float inv0 = 1.0f / l0, inv1 = 1.0f / l1;
    int r0 = q0 + wid * 16 + (lane >> 2);
#pragma unroll
    for (int f = 0; f < 16; f++) {
        int d = f * 8 + (lane & 3) * 2;
        size_t e0 = (size_t)r0 * (NH * HD) + h * HD + d;
        size_t e1 = e0 + (size_t)8 * (NH * HD);
        *(uint32_t*)(aoh + e0) = cvt2h(oacc[f][0] * inv0, oacc[f][1] * inv0);
        *(uint32_t*)(aoh + e1) = cvt2h(oacc[f][2] * inv1, oacc[f][3] * inv1);
    }
}

// ---------------- launch ----------------
extern "C" void kernel_launch(void* const* d_in, const int* in_sizes, int n_in,
                              void* d_out, int out_size)
{
    const float* hs    = (const float*)d_in[0];
    const float* cosb  = (const float*)d_in[1];
    const float* sinb  = (const float*)d_in[2];
    const float* pastK = (const float*)d_in[4];
    const float* pastV = (const float*)d_in[5];
    const float* Wq    = (const float*)d_in[6];
    const float* Wk    = (const float*)d_in[7];
    const float* Wv    = (const float*)d_in[8];
    const float* Wo    = (const float*)d_in[9];
    const float* qw    = (const float*)d_in[10];
    const float* kw    = (const float*)d_in[11];

    float* out  = (float*)d_out;
    float* newK = out + (size_t)Q * NH * HD;
    float* newV = newK + (size_t)NKV * Q * HD;

    float *qtmp, *ktmp;
    h16 *hsh, *wqh, *wql, *wkh, *wkl, *wvh, *wvl, *woh, *wol;
    h16 *qph, *qpl, *kph, *vph, *aoh;
    cudaGetSymbolAddress((void**)&qtmp, g_qtmp);
    cudaGetSymbolAddress((void**)&ktmp, g_ktmp);
    cudaGetSymbolAddress((void**)&hsh, g_hs_h);
    cudaGetSymbolAddress((void**)&wqh, g_wq_h);
    cudaGetSymbolAddress((void**)&wql, g_wq_l);
    cudaGetSymbolAddress((void**)&wkh, g_wk_h);
    cudaGetSymbolAddress((void**)&wkl, g_wk_l);
    cudaGetSymbolAddress((void**)&wvh, g_wv_h);
    cudaGetSymbolAddress((void**)&wvl, g_wv_l);
    cudaGetSymbolAddress((void**)&woh, g_wo_h);
    cudaGetSymbolAddress((void**)&wol, g_wo_l);
    cudaGetSymbolAddress((void**)&qph, g_q_h);
    cudaGetSymbolAddress((void**)&qpl, g_q_l);
    cudaGetSymbolAddress((void**)&kph, g_k_h);
    cudaGetSymbolAddress((void**)&vph, g_v_h);
    cudaGetSymbolAddress((void**)&aoh, g_ao_h);

    cudaFuncSetAttribute(hgemm_qkv, cudaFuncAttributeMaxDynamicSharedMemorySize, HG_SMEM);
    cudaFuncSetAttribute(hgemm_o, cudaFuncAttributeMaxDynamicSharedMemorySize, HG_SMEM);
    cudaFuncSetAttribute(attn_mma, cudaFuncAttributeMaxDynamicSharedMemorySize, AT_SMEM);

    // merged splits
    ksplit_all<<<16384, 256>>>(hs, hsh, Wq, wqh, wql, Wk, wkh, wkl,
                               Wv, wvh, wvl, Wo, woh, wol);
    ksplit_cache2<<<4096, 256>>>(pastK, kph, pastV, vph);

    // fused QKV projection
    hgemm_qkv<<<dim3(32, Q / 128), 256, HG_SMEM>>>(
        hsh, wqh, wql, wkh, wkl, wvh, wvl, qtmp, ktmp, newV, vph);

    // rmsnorm + rope
    norm_rope<<<dim3(Q, NH + NKV), 128>>>(qtmp, ktmp, cosb, sinb, qw, kw,
                                          qph, qpl, newK, kph);

    // attention
    attn_mma<<<dim3(NH, Q / AT_TQ), 256, AT_SMEM>>>(qph, qpl, kph, vph, aoh);

    // output projection
    hgemm_o<<<dim3(NH * HD / 128, Q / 128), 256, HG_SMEM>>>(aoh, woh, wol, out);
}

// round 9
// speedup vs baseline: 9.4730x; 1.0980x over previous
#include <cuda_runtime.h>
#include <cuda_fp16.h>
#include <cstdint>

#define Q    2048
#define H    2048
#define NH   16
#define NKV  8
#define HD   128
#define PAST 2048
#define KVLEN (PAST + Q)
#define KEPS 1e-6f

typedef __half h16;

// ---------------- scratch (no allocation allowed) ----------------
__device__ float g_qtmp[Q * NH * HD];
__device__ float g_ktmp[Q * NKV * HD];
__device__ h16 g_hs_h[Q * H];
__device__ h16 g_wq_h[NH * HD * H],      g_wq_l[NH * HD * H];
__device__ h16 g_wk_h[NKV * HD * H],     g_wk_l[NKV * HD * H];
__device__ h16 g_wv_h[NKV * HD * H],     g_wv_l[NKV * HD * H];
__device__ h16 g_wo_h[NH * HD * NH * HD], g_wo_l[NH * HD * NH * HD];
__device__ h16 g_q_h[NH * Q * HD],       g_q_l[NH * Q * HD];
__device__ h16 g_k_h[NKV * KVLEN * HD];
__device__ h16 g_v_h[NKV * KVLEN * HD];
__device__ h16 g_ao_h[Q * NH * HD];

// ---------------- helpers ----------------
__device__ __forceinline__ uint32_t smem_u32(const void* p) {
    uint32_t a;
    asm("{ .reg .u64 t; cvta.to.shared.u64 t, %1; cvt.u32.u64 %0, t; }" : "=r"(a) : "l"(p));
    return a;
}
__device__ __forceinline__ uint32_t packh(h16 a, h16 b) {
    return (uint32_t)__half_as_ushort(a) | ((uint32_t)__half_as_ushort(b) << 16);
}
__device__ __forceinline__ uint32_t cvt2h(float a, float b) {
    return packh(__float2half_rn(a), __float2half_rn(b));
}
__device__ __forceinline__ void split2h(float a, float b, uint32_t& hi, uint32_t& lo) {
    h16 ha = __float2half_rn(a), hb = __float2half_rn(b);
    hi = packh(ha, hb);
    lo = packh(__float2half_rn(a - __half2float(ha)),
               __float2half_rn(b - __half2float(hb)));
}
__device__ __forceinline__ void ldsm4(uint32_t* r, uint32_t addr) {
    asm volatile("ldmatrix.sync.aligned.m8n8.x4.shared.b16 {%0,%1,%2,%3}, [%4];"
                 : "=r"(r[0]), "=r"(r[1]), "=r"(r[2]), "=r"(r[3]) : "r"(addr));
}
__device__ __forceinline__ void ldsm4t(uint32_t* r, uint32_t addr) {
    asm volatile("ldmatrix.sync.aligned.m8n8.x4.trans.shared.b16 {%0,%1,%2,%3}, [%4];"
                 : "=r"(r[0]), "=r"(r[1]), "=r"(r[2]), "=r"(r[3]) : "r"(addr));
}
__device__ __forceinline__ void mma_f16(float* c, const uint32_t* a, const uint32_t* b) {
    asm volatile(
        "mma.sync.aligned.m16n8k16.row.col.f32.f16.f16.f32 "
        "{%0,%1,%2,%3}, {%4,%5,%6,%7}, {%8,%9}, {%0,%1,%2,%3};"
        : "+f"(c[0]), "+f"(c[1]), "+f"(c[2]), "+f"(c[3])
        : "r"(a[0]), "r"(a[1]), "r"(a[2]), "r"(a[3]), "r"(b[0]), "r"(b[1]));
}
__device__ __forceinline__ void cp16(uint32_t dst, const void* src) {
    asm volatile("cp.async.cg.shared.global [%0], [%1], 16;"
                 :: "r"(dst), "l"(__cvta_generic_to_global(src)));
}
__device__ __forceinline__ void cpcommit() { asm volatile("cp.async.commit_group;"); }
template <int N>
__device__ __forceinline__ void cpwait() {
    asm volatile("cp.async.wait_group %0;" :: "n"(N));
}
__device__ __forceinline__ float ex2(float x) {
    float y;
    asm("ex2.approx.f32 %0, %1;" : "=f"(y) : "f"(x));
    return y;
}

// ---------------- single merged split kernel ----------------
// block ranges (1024 floats each):
// hs [0,4096) single | wq [4096,8192) wk [8192,10240) wv [10240,12288)
// wo [12288,16384) split | pastK [16384,18432) pastV [18432,20480) cache single
__global__ __launch_bounds__(256) void ksplit_all(
    const float* __restrict__ hs, h16* __restrict__ hsh,
    const float* __restrict__ wq, h16* __restrict__ wqh, h16* __restrict__ wql,
    const float* __restrict__ wk, h16* __restrict__ wkh, h16* __restrict__ wkl,
    const float* __restrict__ wv, h16* __restrict__ wvh, h16* __restrict__ wvl,
    const float* __restrict__ wo, h16* __restrict__ woh, h16* __restrict__ wol,
    const float* __restrict__ pk, h16* __restrict__ kch,
    const float* __restrict__ pv, h16* __restrict__ vch)
{
    int b = blockIdx.x;
    if (b < 4096) {
        int i = b * 256 + threadIdx.x;
        float4 v = ((const float4*)hs)[i];
        ((uint32_t*)hsh)[2 * i]     = cvt2h(v.x, v.y);
        ((uint32_t*)hsh)[2 * i + 1] = cvt2h(v.z, v.w);
        return;
    }
    if (b >= 16384) {
        b -= 16384;
        const float* x;
        h16* dst;
        if (b < 2048) { x = pk; dst = kch; }
        else          { x = pv; dst = vch; b -= 2048; }
        int i = b * 256 + threadIdx.x;
        int e = i * 4;
        int kv = e / (PAST * HD);
        int rem = e - kv * (PAST * HD);
        size_t de = (size_t)kv * (KVLEN * HD) + rem;
        float4 v = ((const float4*)x)[i];
        *(uint32_t*)(dst + de)     = cvt2h(v.x, v.y);
        *(uint32_t*)(dst + de + 2) = cvt2h(v.z, v.w);
        return;
    }
    const float* src;
    h16 *hi, *lo;
    int base;
    if (b < 8192)       { src = wq; hi = wqh; lo = wql; base = 4096; }
    else if (b < 10240) { src = wk; hi = wkh; lo = wkl; base = 8192; }
    else if (b < 12288) { src = wv; hi = wvh; lo = wvl; base = 10240; }
    else                { src = wo; hi = woh; lo = wol; base = 12288; }
    int i = (b - base) * 256 + threadIdx.x;
    float4 v = ((const float4*)src)[i];
    uint32_t h0, l0, h1, l1;
    split2h(v.x, v.y, h0, l0);
    split2h(v.z, v.w, h1, l1);
    ((uint32_t*)hi)[2 * i] = h0;  ((uint32_t*)hi)[2 * i + 1] = h1;
    ((uint32_t*)lo)[2 * i] = l0;  ((uint32_t*)lo)[2 * i + 1] = l1;
}

// ---------------- GEMM constants ----------------
#define ROWB   80
#define PLANEB 10240
#define STAGEB 30720
#define HG_SMEM (2 * STAGEB)

// ---------------- fused QKV projection GEMM ----------------
__global__ __launch_bounds__(256) void hgemm_qkv(
    const h16* __restrict__ hsh,
    const h16* __restrict__ wqh, const h16* __restrict__ wql,
    const h16* __restrict__ wkh, const h16* __restrict__ wkl,
    const h16* __restrict__ wvh, const h16* __restrict__ wvl,
    float* __restrict__ qtmp, float* __restrict__ ktmp, float* __restrict__ newV,
    h16* __restrict__ vph)
{
    extern __shared__ char hsm[];
    const int bx = blockIdx.x;
    const int tid = threadIdx.x;
    const int lane = tid & 31;
    const int wid = tid >> 5;
    const int wm = wid >> 2;
    const int wn = wid & 3;
    const uint32_t base_u = smem_u32(hsm);
    const int K = H;

    const h16 *Bhi, *Blo;
    int colb;
    if (bx < 16)      { Bhi = wqh; Blo = wql; colb = bx * 128; }
    else if (bx < 24) { Bhi = wkh; Blo = wkl; colb = (bx - 16) * 128; }
    else              { Bhi = wvh; Blo = wvl; colb = (bx - 24) * 128; }

    const h16* pl[3] = {
        hsh + (size_t)(blockIdx.y * 128) * K,
        Bhi + (size_t)colb * K,
        Blo + (size_t)colb * K };

    const int rowselA = lane & 15;
    const int halfA = lane >> 4;
    const int rowselB = (lane & 7) + (lane >> 4) * 8;
    const int halfB = (lane >> 3) & 1;
    const uint32_t aoff0 = (uint32_t)((wm * 64 + rowselA) * ROWB + halfA * 16);
    const uint32_t boff0 = (uint32_t)((wn * 32 + rowselB) * ROWB + halfB * 16);

    float acc[4][4][4];
#pragma unroll
    for (int i = 0; i < 4; i++)
#pragma unroll
        for (int j = 0; j < 4; j++)
#pragma unroll
            for (int r = 0; r < 4; r++) acc[i][j][r] = 0.0f;

    const int nst = K / 32;
    {
        uint32_t dstb = base_u;
        for (int i = tid; i < 1536; i += 256) {
            int p = i >> 9, row = (i >> 2) & 127, seg = i & 3;
            cp16(dstb + p * PLANEB + row * ROWB + seg * 16,
                 pl[p] + (size_t)row * K + seg * 8);
        }
        cpcommit();
    }

    for (int s = 0; s < nst; s++) {
        cpwait<0>();
        __syncthreads();
        if (s + 1 < nst) {
            int kt = (s + 1) * 32;
            uint32_t dstb = base_u + ((s + 1) & 1) * STAGEB;
            for (int i = tid; i < 1536; i += 256) {
                int p = i >> 9, row = (i >> 2) & 127, seg = i & 3;
                cp16(dstb + p * PLANEB + row * ROWB + seg * 16,
                     pl[p] + (size_t)row * K + kt + seg * 8);
            }
            cpcommit();
        }
        const uint32_t sb = base_u + (s & 1) * STAGEB;
#pragma unroll
        for (int kc = 0; kc < 2; kc++) {
            uint32_t ah[4][4];
#pragma unroll
            for (int mi = 0; mi < 4; mi++)
                ldsm4(ah[mi], sb + aoff0 + mi * (16 * ROWB) + kc * 32);
            uint32_t bh[4][2], bl[4][2];
#pragma unroll
            for (int p = 0; p < 2; p++) {
                uint32_t bd = sb + PLANEB + boff0 + p * (16 * ROWB) + kc * 32;
                uint32_t r[4];
                ldsm4(r, bd);
                bh[2 * p][0] = r[0]; bh[2 * p][1] = r[1];
                bh[2 * p + 1][0] = r[2]; bh[2 * p + 1][1] = r[3];
                ldsm4(r, bd + PLANEB);
                bl[2 * p][0] = r[0]; bl[2 * p][1] = r[1];
                bl[2 * p + 1][0] = r[2]; bl[2 * p + 1][1] = r[3];
            }
#pragma unroll
            for (int mi = 0; mi < 4; mi++) {
#pragma unroll
                for (int nj = 0; nj < 4; nj++) {
                    mma_f16(acc[mi][nj], ah[mi], bh[nj]);
                    mma_f16(acc[mi][nj], ah[mi], bl[nj]);
                }
            }
        }
    }

    const int rfrag = lane >> 2;
    const int cpair = (lane & 3) * 2;
#pragma unroll
    for (int mi = 0; mi < 4; mi++) {
#pragma unroll
        for (int nj = 0; nj < 4; nj++) {
            int coll = colb + wn * 32 + nj * 8 + cpair;
#pragma unroll
            for (int half = 0; half < 2; half++) {
                int rowg = blockIdx.y * 128 + wm * 64 + mi * 16 + rfrag + half * 8;
                float2 v = make_float2(acc[mi][nj][2 * half], acc[mi][nj][2 * half + 1]);
                if (bx < 16) {
                    *(float2*)(qtmp + (size_t)rowg * (NH * HD) + coll) = v;
                } else if (bx < 24) {
                    *(float2*)(ktmp + (size_t)rowg * (NKV * HD) + coll) = v;
                } else {
                    int kv = coll >> 7, d = coll & 127;
                    *(float2*)(newV + (size_t)kv * (Q * HD) + (size_t)rowg * HD + d) = v;
                    size_t de = (size_t)kv * (KVLEN * HD) + (size_t)(PAST + rowg) * HD + d;
                    *(uint32_t*)(vph + de) = cvt2h(v.x, v.y);
                }
            }
        }
    }
}

// ---------------- output projection GEMM ----------------
__global__ __launch_bounds__(256) void hgemm_o(
    const h16* __restrict__ Ah,
    const h16* __restrict__ Bhi, const h16* __restrict__ Blo,
    float* __restrict__ C)
{
    extern __shared__ char hsm[];
    const int tid = threadIdx.x;
    const int lane = tid & 31;
    const int wid = tid >> 5;
    const int wm = wid >> 2;
    const int wn = wid & 3;
    const uint32_t base_u = smem_u32(hsm);
    const int K = NH * HD, N = NH * HD;

    const h16* pl[3] = {
        Ah + (size_t)(blockIdx.y * 128) * K,
        Bhi + (size_t)(blockIdx.x * 128) * K,
        Blo + (size_t)(blockIdx.x * 128) * K };

    const int rowselA = lane & 15;
    const int halfA = lane >> 4;
    const int rowselB = (lane & 7) + (lane >> 4) * 8;
    const int halfB = (lane >> 3) & 1;
    const uint32_t aoff0 = (uint32_t)((wm * 64 + rowselA) * ROWB + halfA * 16);
    const uint32_t boff0 = (uint32_t)((wn * 32 + rowselB) * ROWB + halfB * 16);

    float acc[4][4][4];
#pragma unroll
    for (int i = 0; i < 4; i++)
#pragma unroll
        for (int j = 0; j < 4; j++)
#pragma unroll
            for (int r = 0; r < 4; r++) acc[i][j][r] = 0.0f;

    const int nst = K / 32;
    {
        uint32_t dstb = base_u;
        for (int i = tid; i < 1536; i += 256) {
            int p = i >> 9, row = (i >> 2) & 127, seg = i & 3;
            cp16(dstb + p * PLANEB + row * ROWB + seg * 16,
                 pl[p] + (size_t)row * K + seg * 8);
        }
        cpcommit();
    }

    for (int s = 0; s < nst; s++) {
        cpwait<0>();
        __syncthreads();
        if (s + 1 < nst) {
            int kt = (s + 1) * 32;
            uint32_t dstb = base_u + ((s + 1) & 1) * STAGEB;
            for (int i = tid; i < 1536; i += 256) {
                int p = i >> 9, row = (i >> 2) & 127, seg = i & 3;
                cp16(dstb + p * PLANEB + row * ROWB + seg * 16,
                     pl[p] + (size_t)row * K + kt + seg * 8);
            }
            cpcommit();
        }
        const uint32_t sb = base_u + (s & 1) * STAGEB;
#pragma unroll
        for (int kc = 0; kc < 2; kc++) {
            uint32_t ah[4][4];
#pragma unroll
            for (int mi = 0; mi < 4; mi++)
                ldsm4(ah[mi], sb + aoff0 + mi * (16 * ROWB) + kc * 32);
            uint32_t bh[4][2], bl[4][2];
#pragma unroll
            for (int p = 0; p < 2; p++) {
                uint32_t bd = sb + PLANEB + boff0 + p * (16 * ROWB) + kc * 32;
                uint32_t r[4];
                ldsm4(r, bd);
                bh[2 * p][0] = r[0]; bh[2 * p][1] = r[1];
                bh[2 * p + 1][0] = r[2]; bh[2 * p + 1][1] = r[3];
                ldsm4(r, bd + PLANEB);
                bl[2 * p][0] = r[0]; bl[2 * p][1] = r[1];
                bl[2 * p + 1][0] = r[2]; bl[2 * p + 1][1] = r[3];
            }
#pragma unroll
            for (int mi = 0; mi < 4; mi++) {
#pragma unroll
                for (int nj = 0; nj < 4; nj++) {
                    mma_f16(acc[mi][nj], ah[mi], bh[nj]);
                    mma_f16(acc[mi][nj], ah[mi], bl[nj]);
                }
            }
        }
    }

    const int rfrag = lane >> 2;
    const int cpair = (lane & 3) * 2;
#pragma unroll
    for (int mi = 0; mi < 4; mi++) {
#pragma unroll
        for (int nj = 0; nj < 4; nj++) {
            int colg = blockIdx.x * 128 + wn * 32 + nj * 8 + cpair;
#pragma unroll
            for (int half = 0; half < 2; half++) {
                int rowg = blockIdx.y * 128 + wm * 64 + mi * 16 + rfrag + half * 8;
                *(float2*)(C + (size_t)rowg * N + colg) =
                    make_float2(acc[mi][nj][2 * half], acc[mi][nj][2 * half + 1]);
            }
        }
    }
}

// ---------------- RMSNorm + RoPE (+ fp16 outputs) ----------------
__global__ __launch_bounds__(128) void norm_rope(
    const float* __restrict__ qtmp, const float* __restrict__ ktmp,
    const float* __restrict__ cosb, const float* __restrict__ sinb,
    const float* __restrict__ qw, const float* __restrict__ kw,
    h16* __restrict__ qh, h16* __restrict__ ql,
    float* __restrict__ newK, h16* __restrict__ kh)
{
    const float QSC = 0.08838834764831845f * 1.44269504088896341f;
    int s = blockIdx.x;
    int hh = blockIdx.y;
    int t = threadIdx.x;

    const float* src;
    const float* w;
    if (hh < NH) {
        src = qtmp + (size_t)s * (NH * HD) + hh * HD;
        w = qw;
    } else {
        src = ktmp + (size_t)s * (NKV * HD) + (hh - NH) * HD;
        w = kw;
    }

    float x = src[t];
    float v = x * x;
#pragma unroll
    for (int o = 16; o; o >>= 1) v += __shfl_xor_sync(0xffffffffu, v, o);
    __shared__ float red[4];
    if ((t & 31) == 0) red[t >> 5] = v;
    __syncthreads();
    float sum = red[0] + red[1] + red[2] + red[3];
    float rs = rsqrtf(sum * (1.0f / HD) + KEPS);
    float xn = x * rs * w[t];

    __shared__ float sh[HD];
    sh[t] = xn;
    __syncthreads();
    float c = cosb[(size_t)s * HD + t];
    float si = sinb[(size_t)s * HD + t];
    float rot = (t < 64) ? -sh[t + 64] : sh[t - 64];
    float val = xn * c + rot * si;

    if (hh < NH) {
        float sv = val * QSC;
        h16 hv = __float2half_rn(sv);
        size_t idx = ((size_t)hh * Q + s) * HD + t;
        qh[idx] = hv;
        ql[idx] = __float2half_rn(sv - __half2float(hv));
    } else {
        int kv = hh - NH;
        newK[((size_t)kv * Q + s) * HD + t] = val;
        kh[((size_t)kv * KVLEN + PAST + s) * HD + t] = __float2half_rn(val);
    }
}

// ---------------- Flash attention with mma.sync (fp16, single-P PV) ----------------
#define AT_TQ 128
#define AT_TK 64
#define KVROW 272
#define KVPLANE (64 * KVROW)
#define TILEBUF (2 * KVPLANE)
#define AT_SMEM (2 * TILEBUF)
#define QPLANE (128 * KVROW)

__global__ __launch_bounds__(256, 1) void attn_mma(
    const h16* __restrict__ qh, const h16* __restrict__ ql,
    const h16* __restrict__ kch, const h16* __restrict__ vch,
    h16* __restrict__ aoh)
{
    extern __shared__ char asmem[];
    const int h = blockIdx.x;
    const int q0 = ((int)gridDim.y - 1 - (int)blockIdx.y) * AT_TQ;  // largest-first
    const int kvh = h >> 1;
    const int tid = threadIdx.x;
    const int lane = tid & 31;
    const int wid = tid >> 5;
    const uint32_t sb = smem_u32(asmem);

    {
        const h16* qsrc[2] = { qh + ((size_t)h * Q + q0) * HD,
                               ql + ((size_t)h * Q + q0) * HD };
        for (int i = tid; i < 4096; i += 256) {
            int p = i >> 11, row = (i >> 4) & 127, seg = i & 15;
            cp16(sb + p * QPLANE + row * KVROW + seg * 16,
                 qsrc[p] + (size_t)row * HD + seg * 8);
        }
        cpcommit();
        cpwait<0>();
        __syncthreads();
    }
    uint32_t aQh[8][4], aQl[8][4];
    {
        uint32_t a0 = sb + (wid * 16 + (lane & 15)) * KVROW + (lane >> 4) * 16;
#pragma unroll
        for (int kc = 0; kc < 8; kc++) {
            ldsm4(aQh[kc], a0 + kc * 32);
            ldsm4(aQl[kc], a0 + kc * 32 + QPLANE);
        }
    }
    __syncthreads();

    float oacc[16][4];
#pragma unroll
    for (int f = 0; f < 16; f++)
#pragma unroll
        for (int r = 0; r < 4; r++) oacc[f][r] = 0.0f;
    float m0 = -1e30f, m1 = -1e30f, l0 = 0.0f, l1 = 0.0f;

    const int nt = (PAST + q0 + AT_TQ) / AT_TK;
    const h16* ksrc = kch + (size_t)kvh * KVLEN * HD;
    const h16* vsrc = vch + (size_t)kvh * KVLEN * HD;

    {
        for (int i = tid; i < 2048; i += 256) {
            int p = i >> 10, row = (i >> 4) & 63, seg = i & 15;
            const h16* s0 = p ? vsrc : ksrc;
            cp16(sb + p * KVPLANE + row * KVROW + seg * 16,
                 s0 + (size_t)row * HD + seg * 8);
        }
        cpcommit();
    }

    const int rowselB = (lane & 7) + (lane >> 4) * 8;
    const int halfB = (lane >> 3) & 1;
    const int rowV = lane & 15;
    const int halfV = (lane >> 4) * 16;

    for (int t = 0; t < nt; t++) {
        __syncthreads();
        if (t + 1 < nt) {
            int j1 = (t + 1) * AT_TK;
            uint32_t db = sb + ((t + 1) & 1) * TILEBUF;
            for (int i = tid; i < 2048; i += 256) {
                int p = i >> 10, row = (i >> 4) & 63, seg = i & 15;
                const h16* s0 = p ? vsrc : ksrc;
                cp16(db + p * KVPLANE + row * KVROW + seg * 16,
                     s0 + (size_t)(j1 + row) * HD + seg * 8);
            }
            cpcommit();
            cpwait<1>();
        } else {
            cpwait<0>();
        }
        __syncthreads();

        const uint32_t kb = sb + (t & 1) * TILEBUF;
        const int j0 = t * AT_TK;

        // ---- S = Q K^T : Q split, K single ----
        float sacc[8][4];
#pragma unroll
        for (int j = 0; j < 8; j++)
#pragma unroll
            for (int r = 0; r < 4; r++) sacc[j][r] = 0.0f;
#pragma unroll
        for (int kc = 0; kc < 8; kc++) {
#pragma unroll
            for (int nj = 0; nj < 4; nj++) {
                uint32_t kh[4];
                ldsm4(kh, kb + (nj * 16 + rowselB) * KVROW + halfB * 16 + kc * 32);
                mma_f16(sacc[2 * nj],     aQh[kc], kh);
                mma_f16(sacc[2 * nj],     aQl[kc], kh);
                mma_f16(sacc[2 * nj + 1], aQh[kc], kh + 2);
                mma_f16(sacc[2 * nj + 1], aQl[kc], kh + 2);
            }
        }

        if (j0 + AT_TK - 1 > PAST + q0 + wid * 16) {
            int r0g = PAST + q0 + wid * 16 + (lane >> 2);
#pragma unroll
            for (int j = 0; j < 8; j++) {
                int cg = j0 + j * 8 + (lane & 3) * 2;
                if (cg > r0g)     sacc[j][0] = -1e30f;
                if (cg + 1 > r0g) sacc[j][1] = -1e30f;
                if (cg > r0g + 8)     sacc[j][2] = -1e30f;
                if (cg + 1 > r0g + 8) sacc[j][3] = -1e30f;
            }
        }

        float t0 = -1e30f, t1 = -1e30f;
#pragma unroll
        for (int j = 0; j < 8; j++) {
            t0 = fmaxf(t0, fmaxf(sacc[j][0], sacc[j][1]));
            t1 = fmaxf(t1, fmaxf(sacc[j][2], sacc[j][3]));
        }
        t0 = fmaxf(t0, __shfl_xor_sync(0xffffffffu, t0, 1));
        t0 = fmaxf(t0, __shfl_xor_sync(0xffffffffu, t0, 2));
        t1 = fmaxf(t1, __shfl_xor_sync(0xffffffffu, t1, 1));
        t1 = fmaxf(t1, __shfl_xor_sync(0xffffffffu, t1, 2));
        float mn0 = fmaxf(m0, t0), mn1 = fmaxf(m1, t1);
        float c0 = ex2(m0 - mn0), c1 = ex2(m1 - mn1);
        m0 = mn0; m1 = mn1;
        float ps0 = 0.0f, ps1 = 0.0f;
#pragma unroll
        for (int j = 0; j < 8; j++) {
            sacc[j][0] = ex2(sacc[j][0] - mn0); ps0 += sacc[j][0];
            sacc[j][1] = ex2(sacc[j][1] - mn0); ps0 += sacc[j][1];
            sacc[j][2] = ex2(sacc[j][2] - mn1); ps1 += sacc[j][2];
            sacc[j][3] = ex2(sacc[j][3] - mn1); ps1 += sacc[j][3];
        }
        ps0 += __shfl_xor_sync(0xffffffffu, ps0, 1);
        ps0 += __shfl_xor_sync(0xffffffffu, ps0, 2);
        ps1 += __shfl_xor_sync(0xffffffffu, ps1, 1);
        ps1 += __shfl_xor_sync(0xffffffffu, ps1, 2);
        l0 = l0 * c0 + ps0;
        l1 = l1 * c1 + ps1;
#pragma unroll
        for (int f = 0; f < 16; f++) {
            oacc[f][0] *= c0; oacc[f][1] *= c0;
            oacc[f][2] *= c1; oacc[f][3] *= c1;
        }

        // ---- pack P single-plane ----
        uint32_t pP[4][4];
#pragma unroll
        for (int kc = 0; kc < 4; kc++) {
            pP[kc][0] = cvt2h(sacc[2 * kc][0],     sacc[2 * kc][1]);
            pP[kc][1] = cvt2h(sacc[2 * kc][2],     sacc[2 * kc][3]);
            pP[kc][2] = cvt2h(sacc[2 * kc + 1][0], sacc[2 * kc + 1][1]);
            pP[kc][3] = cvt2h(sacc[2 * kc + 1][2], sacc[2 * kc + 1][3]);
        }

        // ---- O += P V : both single ----
        const uint32_t vb = kb + KVPLANE;
#pragma unroll
        for (int kc = 0; kc < 4; kc++) {
#pragma unroll
            for (int dj = 0; dj < 8; dj++) {
                uint32_t vh[4];
                ldsm4t(vh, vb + (kc * 16 + rowV) * KVROW + dj * 32 + halfV);
                mma_f16(oacc[2 * dj],     pP[kc], vh);
                mma_f16(oacc[2 * dj + 1], pP[kc], vh + 2);
            }
        }
    }

    float inv0 = 1.0f / l0, inv1 = 1.0f / l1;
    int r0 = q0 + wid * 16 + (lane >> 2);
#pragma unroll
    for (int f = 0; f < 16; f++) {
        int d = f * 8 + (lane & 3) * 2;
        size_t e0 = (size_t)r0 * (NH * HD) + h * HD + d;
        size_t e1 = e0 + (size_t)8 * (NH * HD);
        *(uint32_t*)(aoh + e0) = cvt2h(oacc[f][0] * inv0, oacc[f][1] * inv0);
        *(uint32_t*)(aoh + e1) = cvt2h(oacc[f][2] * inv1, oacc[f][3] * inv1);
    }
}

// ---------------- launch ----------------
extern "C" void kernel_launch(void* const* d_in, const int* in_sizes, int n_in,
                              void* d_out, int out_size)
{
    const float* hs    = (const float*)d_in[0];
    const float* cosb  = (const float*)d_in[1];
    const float* sinb  = (const float*)d_in[2];
    const float* pastK = (const float*)d_in[4];
    const float* pastV = (const float*)d_in[5];
    const float* Wq    = (const float*)d_in[6];
    const float* Wk    = (const float*)d_in[7];
    const float* Wv    = (const float*)d_in[8];
    const float* Wo    = (const float*)d_in[9];
    const float* qw    = (const float*)d_in[10];
    const float* kw    = (const float*)d_in[11];

    float* out  = (float*)d_out;
    float* newK = out + (size_t)Q * NH * HD;
    float* newV = newK + (size_t)NKV * Q * HD;

    float *qtmp, *ktmp;
    h16 *hsh, *wqh, *wql, *wkh, *wkl, *wvh, *wvl, *woh, *wol;
    h16 *qph, *qpl, *kph, *vph, *aoh;
    cudaGetSymbolAddress((void**)&qtmp, g_qtmp);
    cudaGetSymbolAddress((void**)&ktmp, g_ktmp);
    cudaGetSymbolAddress((void**)&hsh, g_hs_h);
    cudaGetSymbolAddress((void**)&wqh, g_wq_h);
    cudaGetSymbolAddress((void**)&wql, g_wq_l);
    cudaGetSymbolAddress((void**)&wkh, g_wk_h);
    cudaGetSymbolAddress((void**)&wkl, g_wk_l);
    cudaGetSymbolAddress((void**)&wvh, g_wv_h);
    cudaGetSymbolAddress((void**)&wvl, g_wv_l);
    cudaGetSymbolAddress((void**)&woh, g_wo_h);
    cudaGetSymbolAddress((void**)&wol, g_wo_l);
    cudaGetSymbolAddress((void**)&qph, g_q_h);
    cudaGetSymbolAddress((void**)&qpl, g_q_l);
    cudaGetSymbolAddress((void**)&kph, g_k_h);
    cudaGetSymbolAddress((void**)&vph, g_v_h);
    cudaGetSymbolAddress((void**)&aoh, g_ao_h);

    cudaFuncSetAttribute(hgemm_qkv, cudaFuncAttributeMaxDynamicSharedMemorySize, HG_SMEM);
    cudaFuncSetAttribute(hgemm_o, cudaFuncAttributeMaxDynamicSharedMemorySize, HG_SMEM);
    cudaFuncSetAttribute(attn_mma, cudaFuncAttributeMaxDynamicSharedMemorySize, AT_SMEM);

    // single merged split
    ksplit_all<<<20480, 256>>>(hs, hsh, Wq, wqh, wql, Wk, wkh, wkl,
                               Wv, wvh, wvl, Wo, woh, wol,
                               pastK, kph, pastV, vph);

    // fused QKV projection
    hgemm_qkv<<<dim3(32, Q / 128), 256, HG_SMEM>>>(
        hsh, wqh, wql, wkh, wkl, wvh, wvl, qtmp, ktmp, newV, vph);

    // rmsnorm + rope
    norm_rope<<<dim3(Q, NH + NKV), 128>>>(qtmp, ktmp, cosb, sinb, qw, kw,
                                          qph, qpl, newK, kph);

    // attention
    attn_mma<<<dim3(NH, Q / AT_TQ), 256, AT_SMEM>>>(qph, qpl, kph, vph, aoh);

    // output projection
    hgemm_o<<<dim3(NH * HD / 128, Q / 128), 256, HG_SMEM>>>(aoh, woh, wol, out);
}

// round 10
// speedup vs baseline: 11.2995x; 1.1928x over previous
#include <cuda_runtime.h>
#include <cuda_fp16.h>
#include <cstdint>

#define Q    2048
#define H    2048
#define NH   16
#define NKV  8
#define HD   128
#define PAST 2048
#define KVLEN (PAST + Q)
#define KEPS 1e-6f

typedef __half h16;

// ---------------- scratch (no allocation allowed) ----------------
__device__ float g_qtmp[Q * NH * HD];
__device__ float g_ktmp[Q * NKV * HD];
__device__ h16 g_hs_h[Q * H];
__device__ h16 g_wq_h[NH * HD * H],  g_wq_l[NH * HD * H];
__device__ h16 g_wk_h[NKV * HD * H], g_wk_l[NKV * HD * H];
__device__ h16 g_wv_h[NKV * HD * H];
__device__ h16 g_wo_h[NH * HD * NH * HD];
__device__ h16 g_q_h[NH * Q * HD];
__device__ h16 g_k_h[NKV * KVLEN * HD];
__device__ h16 g_v_h[NKV * KVLEN * HD];
__device__ h16 g_ao_h[Q * NH * HD];

// ---------------- helpers ----------------
__device__ __forceinline__ uint32_t smem_u32(const void* p) {
    uint32_t a;
    asm("{ .reg .u64 t; cvta.to.shared.u64 t, %1; cvt.u32.u64 %0, t; }" : "=r"(a) : "l"(p));
    return a;
}
__device__ __forceinline__ uint32_t packh(h16 a, h16 b) {
    return (uint32_t)__half_as_ushort(a) | ((uint32_t)__half_as_ushort(b) << 16);
}
__device__ __forceinline__ uint32_t cvt2h(float a, float b) {
    return packh(__float2half_rn(a), __float2half_rn(b));
}
__device__ __forceinline__ void split2h(float a, float b, uint32_t& hi, uint32_t& lo) {
    h16 ha = __float2half_rn(a), hb = __float2half_rn(b);
    hi = packh(ha, hb);
    lo = packh(__float2half_rn(a - __half2float(ha)),
               __float2half_rn(b - __half2float(hb)));
}
__device__ __forceinline__ void ldsm4(uint32_t* r, uint32_t addr) {
    asm volatile("ldmatrix.sync.aligned.m8n8.x4.shared.b16 {%0,%1,%2,%3}, [%4];"
                 : "=r"(r[0]), "=r"(r[1]), "=r"(r[2]), "=r"(r[3]) : "r"(addr));
}
__device__ __forceinline__ void ldsm4t(uint32_t* r, uint32_t addr) {
    asm volatile("ldmatrix.sync.aligned.m8n8.x4.trans.shared.b16 {%0,%1,%2,%3}, [%4];"
                 : "=r"(r[0]), "=r"(r[1]), "=r"(r[2]), "=r"(r[3]) : "r"(addr));
}
__device__ __forceinline__ void mma_f16(float* c, const uint32_t* a, const uint32_t* b) {
    asm volatile(
        "mma.sync.aligned.m16n8k16.row.col.f32.f16.f16.f32 "
        "{%0,%1,%2,%3}, {%4,%5,%6,%7}, {%8,%9}, {%0,%1,%2,%3};"
        : "+f"(c[0]), "+f"(c[1]), "+f"(c[2]), "+f"(c[3])
        : "r"(a[0]), "r"(a[1]), "r"(a[2]), "r"(a[3]), "r"(b[0]), "r"(b[1]));
}
__device__ __forceinline__ void cp16(uint32_t dst, const void* src) {
    asm volatile("cp.async.cg.shared.global [%0], [%1], 16;"
                 :: "r"(dst), "l"(__cvta_generic_to_global(src)));
}
__device__ __forceinline__ void cpcommit() { asm volatile("cp.async.commit_group;"); }
template <int N>
__device__ __forceinline__ void cpwait() {
    asm volatile("cp.async.wait_group %0;" :: "n"(N));
}
__device__ __forceinline__ float ex2(float x) {
    float y;
    asm("ex2.approx.f32 %0, %1;" : "=f"(y) : "f"(x));
    return y;
}

// ---------------- single merged split kernel ----------------
// block ranges (1024 floats each):
// hs [0,4096) single | wq [4096,8192) split | wk [8192,10240) split
// wv [10240,12288) single | wo [12288,16384) single | caches [16384,20480) single
__global__ __launch_bounds__(256) void ksplit_all(
    const float* __restrict__ hs, h16* __restrict__ hsh,
    const float* __restrict__ wq, h16* __restrict__ wqh, h16* __restrict__ wql,
    const float* __restrict__ wk, h16* __restrict__ wkh, h16* __restrict__ wkl,
    const float* __restrict__ wv, h16* __restrict__ wvh,
    const float* __restrict__ wo, h16* __restrict__ woh,
    const float* __restrict__ pk, h16* __restrict__ kch,
    const float* __restrict__ pv, h16* __restrict__ vch)
{
    int b = blockIdx.x;
    if (b >= 16384) {   // caches (strided dst)
        b -= 16384;
        const float* x;
        h16* dst;
        if (b < 2048) { x = pk; dst = kch; }
        else          { x = pv; dst = vch; b -= 2048; }
        int i = b * 256 + threadIdx.x;
        int e = i * 4;
        int kv = e / (PAST * HD);
        int rem = e - kv * (PAST * HD);
        size_t de = (size_t)kv * (KVLEN * HD) + rem;
        float4 v = ((const float4*)x)[i];
        *(uint32_t*)(dst + de)     = cvt2h(v.x, v.y);
        *(uint32_t*)(dst + de + 2) = cvt2h(v.z, v.w);
        return;
    }
    if (b < 4096 || b >= 10240) {   // single-plane conversions
        const float* src;
        h16* dst;
        int base;
        if (b < 4096)       { src = hs; dst = hsh; base = 0; }
        else if (b < 12288) { src = wv; dst = wvh; base = 10240; }
        else                { src = wo; dst = woh; base = 12288; }
        int i = (b - base) * 256 + threadIdx.x;
        float4 v = ((const float4*)src)[i];
        ((uint32_t*)dst)[2 * i]     = cvt2h(v.x, v.y);
        ((uint32_t*)dst)[2 * i + 1] = cvt2h(v.z, v.w);
        return;
    }
    // split conversions (wq, wk)
    const float* src;
    h16 *hi, *lo;
    int base;
    if (b < 8192) { src = wq; hi = wqh; lo = wql; base = 4096; }
    else          { src = wk; hi = wkh; lo = wkl; base = 8192; }
    int i = (b - base) * 256 + threadIdx.x;
    float4 v = ((const float4*)src)[i];
    uint32_t h0, l0, h1, l1;
    split2h(v.x, v.y, h0, l0);
    split2h(v.z, v.w, h1, l1);
    ((uint32_t*)hi)[2 * i] = h0;  ((uint32_t*)hi)[2 * i + 1] = h1;
    ((uint32_t*)lo)[2 * i] = l0;  ((uint32_t*)lo)[2 * i + 1] = l1;
}

// ---------------- GEMM constants ----------------
#define ROWB   80
#define PLANEB 10240
#define STAGEB 30720          // 3 planes (A, Bhi, Blo)
#define HG_SMEM (2 * STAGEB)
#define STAGEB2 20480         // 2 planes (A, B)
#define HO_SMEM (2 * STAGEB2)

// ---------------- fused QKV projection GEMM ----------------
// grid (32,16): bx<16 Q (split W), <24 K (split W), else V (single W; Blo aliased)
__global__ __launch_bounds__(256) void hgemm_qkv(
    const h16* __restrict__ hsh,
    const h16* __restrict__ wqh, const h16* __restrict__ wql,
    const h16* __restrict__ wkh, const h16* __restrict__ wkl,
    const h16* __restrict__ wvh,
    float* __restrict__ qtmp, float* __restrict__ ktmp, float* __restrict__ newV,
    h16* __restrict__ vph)
{
    extern __shared__ char hsm[];
    const int bx = blockIdx.x;
    const int tid = threadIdx.x;
    const int lane = tid & 31;
    const int wid = tid >> 5;
    const int wm = wid >> 2;
    const int wn = wid & 3;
    const uint32_t base_u = smem_u32(hsm);
    const int K = H;

    const h16 *Bhi, *Blo;
    int colb;
    if (bx < 16)      { Bhi = wqh; Blo = wql; colb = bx * 128; }
    else if (bx < 24) { Bhi = wkh; Blo = wkl; colb = (bx - 16) * 128; }
    else              { Bhi = wvh; Blo = wvh; colb = (bx - 24) * 128; }
    const bool dolo = bx < 24;

    const h16* pl[3] = {
        hsh + (size_t)(blockIdx.y * 128) * K,
        Bhi + (size_t)colb * K,
        Blo + (size_t)colb * K };

    const int rowselA = lane & 15;
    const int halfA = lane >> 4;
    const int rowselB = (lane & 7) + (lane >> 4) * 8;
    const int halfB = (lane >> 3) & 1;
    const uint32_t aoff0 = (uint32_t)((wm * 64 + rowselA) * ROWB + halfA * 16);
    const uint32_t boff0 = (uint32_t)((wn * 32 + rowselB) * ROWB + halfB * 16);

    float acc[4][4][4];
#pragma unroll
    for (int i = 0; i < 4; i++)
#pragma unroll
        for (int j = 0; j < 4; j++)
#pragma unroll
            for (int r = 0; r < 4; r++) acc[i][j][r] = 0.0f;

    const int nst = K / 32;
    const int nld = dolo ? 1536 : 1024;
    {
        uint32_t dstb = base_u;
        for (int i = tid; i < nld; i += 256) {
            int p = i >> 9, row = (i >> 2) & 127, seg = i & 3;
            cp16(dstb + p * PLANEB + row * ROWB + seg * 16,
                 pl[p] + (size_t)row * K + seg * 8);
        }
        cpcommit();
    }

    for (int s = 0; s < nst; s++) {
        cpwait<0>();
        __syncthreads();
        if (s + 1 < nst) {
            int kt = (s + 1) * 32;
            uint32_t dstb = base_u + ((s + 1) & 1) * STAGEB;
            for (int i = tid; i < nld; i += 256) {
                int p = i >> 9, row = (i >> 2) & 127, seg = i & 3;
                cp16(dstb + p * PLANEB + row * ROWB + seg * 16,
                     pl[p] + (size_t)row * K + kt + seg * 8);
            }
            cpcommit();
        }
        const uint32_t sb = base_u + (s & 1) * STAGEB;
#pragma unroll
        for (int kc = 0; kc < 2; kc++) {
            uint32_t ah[4][4];
#pragma unroll
            for (int mi = 0; mi < 4; mi++)
                ldsm4(ah[mi], sb + aoff0 + mi * (16 * ROWB) + kc * 32);
            uint32_t bh[4][2], bl[4][2];
#pragma unroll
            for (int p = 0; p < 2; p++) {
                uint32_t bd = sb + PLANEB + boff0 + p * (16 * ROWB) + kc * 32;
                uint32_t r[4];
                ldsm4(r, bd);
                bh[2 * p][0] = r[0]; bh[2 * p][1] = r[1];
                bh[2 * p + 1][0] = r[2]; bh[2 * p + 1][1] = r[3];
                if (dolo) {
                    ldsm4(r, bd + PLANEB);
                    bl[2 * p][0] = r[0]; bl[2 * p][1] = r[1];
                    bl[2 * p + 1][0] = r[2]; bl[2 * p + 1][1] = r[3];
                }
            }
#pragma unroll
            for (int mi = 0; mi < 4; mi++) {
#pragma unroll
                for (int nj = 0; nj < 4; nj++) {
                    mma_f16(acc[mi][nj], ah[mi], bh[nj]);
                    if (dolo) mma_f16(acc[mi][nj], ah[mi], bl[nj]);
                }
            }
        }
    }

    const int rfrag = lane >> 2;
    const int cpair = (lane & 3) * 2;
#pragma unroll
    for (int mi = 0; mi < 4; mi++) {
#pragma unroll
        for (int nj = 0; nj < 4; nj++) {
            int coll = colb + wn * 32 + nj * 8 + cpair;
#pragma unroll
            for (int half = 0; half < 2; half++) {
                int rowg = blockIdx.y * 128 + wm * 64 + mi * 16 + rfrag + half * 8;
                float2 v = make_float2(acc[mi][nj][2 * half], acc[mi][nj][2 * half + 1]);
                if (bx < 16) {
                    *(float2*)(qtmp + (size_t)rowg * (NH * HD) + coll) = v;
                } else if (bx < 24) {
                    *(float2*)(ktmp + (size_t)rowg * (NKV * HD) + coll) = v;
                } else {
                    int kv = coll >> 7, d = coll & 127;
                    *(float2*)(newV + (size_t)kv * (Q * HD) + (size_t)rowg * HD + d) = v;
                    size_t de = (size_t)kv * (KVLEN * HD) + (size_t)(PAST + rowg) * HD + d;
                    *(uint32_t*)(vph + de) = cvt2h(v.x, v.y);
                }
            }
        }
    }
}

// ---------------- output projection GEMM (single x single) ----------------
__global__ __launch_bounds__(256) void hgemm_o(
    const h16* __restrict__ Ah, const h16* __restrict__ Bh,
    float* __restrict__ C)
{
    extern __shared__ char hsm[];
    const int tid = threadIdx.x;
    const int lane = tid & 31;
    const int wid = tid >> 5;
    const int wm = wid >> 2;
    const int wn = wid & 3;
    const uint32_t base_u = smem_u32(hsm);
    const int K = NH * HD, N = NH * HD;

    const h16* pl[2] = {
        Ah + (size_t)(blockIdx.y * 128) * K,
        Bh + (size_t)(blockIdx.x * 128) * K };

    const int rowselA = lane & 15;
    const int halfA = lane >> 4;
    const int rowselB = (lane & 7) + (lane >> 4) * 8;
    const int halfB = (lane >> 3) & 1;
    const uint32_t aoff0 = (uint32_t)((wm * 64 + rowselA) * ROWB + halfA * 16);
    const uint32_t boff0 = (uint32_t)((wn * 32 + rowselB) * ROWB + halfB * 16);

    float acc[4][4][4];
#pragma unroll
    for (int i = 0; i < 4; i++)
#pragma unroll
        for (int j = 0; j < 4; j++)
#pragma unroll
            for (int r = 0; r < 4; r++) acc[i][j][r] = 0.0f;

    const int nst = K / 32;
    {
        uint32_t dstb = base_u;
        for (int i = tid; i < 1024; i += 256) {
            int p = i >> 9, row = (i >> 2) & 127, seg = i & 3;
            cp16(dstb + p * PLANEB + row * ROWB + seg * 16,
                 pl[p] + (size_t)row * K + seg * 8);
        }
        cpcommit();
    }

    for (int s = 0; s < nst; s++) {
        cpwait<0>();
        __syncthreads();
        if (s + 1 < nst) {
            int kt = (s + 1) * 32;
            uint32_t dstb = base_u + ((s + 1) & 1) * STAGEB2;
            for (int i = tid; i < 1024; i += 256) {
                int p = i >> 9, row = (i >> 2) & 127, seg = i & 3;
                cp16(dstb + p * PLANEB + row * ROWB + seg * 16,
                     pl[p] + (size_t)row * K + kt + seg * 8);
            }
            cpcommit();
        }
        const uint32_t sb = base_u + (s & 1) * STAGEB2;
#pragma unroll
        for (int kc = 0; kc < 2; kc++) {
            uint32_t ah[4][4];
#pragma unroll
            for (int mi = 0; mi < 4; mi++)
                ldsm4(ah[mi], sb + aoff0 + mi * (16 * ROWB) + kc * 32);
            uint32_t bh[4][2];
#pragma unroll
            for (int p = 0; p < 2; p++) {
                uint32_t r[4];
                ldsm4(r, sb + PLANEB + boff0 + p * (16 * ROWB) + kc * 32);
                bh[2 * p][0] = r[0]; bh[2 * p][1] = r[1];
                bh[2 * p + 1][0] = r[2]; bh[2 * p + 1][1] = r[3];
            }
#pragma unroll
            for (int mi = 0; mi < 4; mi++)
#pragma unroll
                for (int nj = 0; nj < 4; nj++)
                    mma_f16(acc[mi][nj], ah[mi], bh[nj]);
        }
    }

    const int rfrag = lane >> 2;
    const int cpair = (lane & 3) * 2;
#pragma unroll
    for (int mi = 0; mi < 4; mi++) {
#pragma unroll
        for (int nj = 0; nj < 4; nj++) {
            int colg = blockIdx.x * 128 + wn * 32 + nj * 8 + cpair;
#pragma unroll
            for (int half = 0; half < 2; half++) {
                int rowg = blockIdx.y * 128 + wm * 64 + mi * 16 + rfrag + half * 8;
                *(float2*)(C + (size_t)rowg * N + colg) =
                    make_float2(acc[mi][nj][2 * half], acc[mi][nj][2 * half + 1]);
            }
        }
    }
}

// ---------------- RMSNorm + RoPE (+ fp16 outputs) ----------------
__global__ __launch_bounds__(128) void norm_rope(
    const float* __restrict__ qtmp, const float* __restrict__ ktmp,
    const float* __restrict__ cosb, const float* __restrict__ sinb,
    const float* __restrict__ qw, const float* __restrict__ kw,
    h16* __restrict__ qh, float* __restrict__ newK, h16* __restrict__ kh)
{
    const float QSC = 0.08838834764831845f * 1.44269504088896341f;
    int s = blockIdx.x;
    int hh = blockIdx.y;
    int t = threadIdx.x;

    const float* src;
    const float* w;
    if (hh < NH) {
        src = qtmp + (size_t)s * (NH * HD) + hh * HD;
        w = qw;
    } else {
        src = ktmp + (size_t)s * (NKV * HD) + (hh - NH) * HD;
        w = kw;
    }

    float x = src[t];
    float v = x * x;
#pragma unroll
    for (int o = 16; o; o >>= 1) v += __shfl_xor_sync(0xffffffffu, v, o);
    __shared__ float red[4];
    if ((t & 31) == 0) red[t >> 5] = v;
    __syncthreads();
    float sum = red[0] + red[1] + red[2] + red[3];
    float rs = rsqrtf(sum * (1.0f / HD) + KEPS);
    float xn = x * rs * w[t];

    __shared__ float sh[HD];
    sh[t] = xn;
    __syncthreads();
    float c = cosb[(size_t)s * HD + t];
    float si = sinb[(size_t)s * HD + t];
    float rot = (t < 64) ? -sh[t + 64] : sh[t - 64];
    float val = xn * c + rot * si;

    if (hh < NH) {
        qh[((size_t)hh * Q + s) * HD + t] = __float2half_rn(val * QSC);
    } else {
        int kv = hh - NH;
        newK[((size_t)kv * Q + s) * HD + t] = val;
        kh[((size_t)kv * KVLEN + PAST + s) * HD + t] = __float2half_rn(val);
    }
}

// ---------------- Flash attention with mma.sync (all single-plane) ----------------
#define AT_TQ 128
#define AT_TK 64
#define KVROW 272
#define KVPLANE (64 * KVROW)
#define TILEBUF (2 * KVPLANE)
#define AT_SMEM (2 * TILEBUF)

__global__ __launch_bounds__(256, 1) void attn_mma(
    const h16* __restrict__ qh,
    const h16* __restrict__ kch, const h16* __restrict__ vch,
    h16* __restrict__ aoh)
{
    extern __shared__ char asmem[];
    const int h = blockIdx.x;
    const int q0 = ((int)gridDim.y - 1 - (int)blockIdx.y) * AT_TQ;  // largest-first
    const int kvh = h >> 1;
    const int tid = threadIdx.x;
    const int lane = tid & 31;
    const int wid = tid >> 5;
    const uint32_t sb = smem_u32(asmem);

    // stage Q (single plane), extract fragments
    {
        const h16* qsrc = qh + ((size_t)h * Q + q0) * HD;
        for (int i = tid; i < 2048; i += 256) {
            int row = i >> 4, seg = i & 15;
            cp16(sb + row * KVROW + seg * 16, qsrc + (size_t)row * HD + seg * 8);
        }
        cpcommit();
        cpwait<0>();
        __syncthreads();
    }
    uint32_t aQh[8][4];
    {
        uint32_t a0 = sb + (wid * 16 + (lane & 15)) * KVROW + (lane >> 4) * 16;
#pragma unroll
        for (int kc = 0; kc < 8; kc++)
            ldsm4(aQh[kc], a0 + kc * 32);
    }
    __syncthreads();

    float oacc[16][4];
#pragma unroll
    for (int f = 0; f < 16; f++)
#pragma unroll
        for (int r = 0; r < 4; r++) oacc[f][r] = 0.0f;
    float m0 = -1e30f, m1 = -1e30f, l0 = 0.0f, l1 = 0.0f;

    const int nt = (PAST + q0 + AT_TQ) / AT_TK;
    const h16* ksrc = kch + (size_t)kvh * KVLEN * HD;
    const h16* vsrc = vch + (size_t)kvh * KVLEN * HD;

    {
        for (int i = tid; i < 2048; i += 256) {
            int p = i >> 10, row = (i >> 4) & 63, seg = i & 15;
            const h16* s0 = p ? vsrc : ksrc;
            cp16(sb + p * KVPLANE + row * KVROW + seg * 16,
                 s0 + (size_t)row * HD + seg * 8);
        }
        cpcommit();
    }

    const int rowselB = (lane & 7) + (lane >> 4) * 8;
    const int halfB = (lane >> 3) & 1;
    const int rowV = lane & 15;
    const int halfV = (lane >> 4) * 16;

    for (int t = 0; t < nt; t++) {
        __syncthreads();
        if (t + 1 < nt) {
            int j1 = (t + 1) * AT_TK;
            uint32_t db = sb + ((t + 1) & 1) * TILEBUF;
            for (int i = tid; i < 2048; i += 256) {
                int p = i >> 10, row = (i >> 4) & 63, seg = i & 15;
                const h16* s0 = p ? vsrc : ksrc;
                cp16(db + p * KVPLANE + row * KVROW + seg * 16,
                     s0 + (size_t)(j1 + row) * HD + seg * 8);
            }
            cpcommit();
            cpwait<1>();
        } else {
            cpwait<0>();
        }
        __syncthreads();

        const uint32_t kb = sb + (t & 1) * TILEBUF;
        const int j0 = t * AT_TK;

        // ---- S = Q K^T : both single ----
        float sacc[8][4];
#pragma unroll
        for (int j = 0; j < 8; j++)
#pragma unroll
            for (int r = 0; r < 4; r++) sacc[j][r] = 0.0f;
#pragma unroll
        for (int kc = 0; kc < 8; kc++) {
#pragma unroll
            for (int nj = 0; nj < 4; nj++) {
                uint32_t kh[4];
                ldsm4(kh, kb + (nj * 16 + rowselB) * KVROW + halfB * 16 + kc * 32);
                mma_f16(sacc[2 * nj],     aQh[kc], kh);
                mma_f16(sacc[2 * nj + 1], aQh[kc], kh + 2);
            }
        }

        if (j0 + AT_TK - 1 > PAST + q0 + wid * 16) {
            int r0g = PAST + q0 + wid * 16 + (lane >> 2);
#pragma unroll
            for (int j = 0; j < 8; j++) {
                int cg = j0 + j * 8 + (lane & 3) * 2;
                if (cg > r0g)     sacc[j][0] = -1e30f;
                if (cg + 1 > r0g) sacc[j][1] = -1e30f;
                if (cg > r0g + 8)     sacc[j][2] = -1e30f;
                if (cg + 1 > r0g + 8) sacc[j][3] = -1e30f;
            }
        }

        float t0 = -1e30f, t1 = -1e30f;
#pragma unroll
        for (int j = 0; j < 8; j++) {
            t0 = fmaxf(t0, fmaxf(sacc[j][0], sacc[j][1]));
            t1 = fmaxf(t1, fmaxf(sacc[j][2], sacc[j][3]));
        }
        t0 = fmaxf(t0, __shfl_xor_sync(0xffffffffu, t0, 1));
        t0 = fmaxf(t0, __shfl_xor_sync(0xffffffffu, t0, 2));
        t1 = fmaxf(t1, __shfl_xor_sync(0xffffffffu, t1, 1));
        t1 = fmaxf(t1, __shfl_xor_sync(0xffffffffu, t1, 2));
        float mn0 = fmaxf(m0, t0), mn1 = fmaxf(m1, t1);
        float c0 = ex2(m0 - mn0), c1 = ex2(m1 - mn1);
        m0 = mn0; m1 = mn1;
        float ps0 = 0.0f, ps1 = 0.0f;
#pragma unroll
        for (int j = 0; j < 8; j++) {
            sacc[j][0] = ex2(sacc[j][0] - mn0); ps0 += sacc[j][0];
            sacc[j][1] = ex2(sacc[j][1] - mn0); ps0 += sacc[j][1];
            sacc[j][2] = ex2(sacc[j][2] - mn1); ps1 += sacc[j][2];
            sacc[j][3] = ex2(sacc[j][3] - mn1); ps1 += sacc[j][3];
        }
        ps0 += __shfl_xor_sync(0xffffffffu, ps0, 1);
        ps0 += __shfl_xor_sync(0xffffffffu, ps0, 2);
        ps1 += __shfl_xor_sync(0xffffffffu, ps1, 1);
        ps1 += __shfl_xor_sync(0xffffffffu, ps1, 2);
        l0 = l0 * c0 + ps0;
        l1 = l1 * c1 + ps1;
#pragma unroll
        for (int f = 0; f < 16; f++) {
            oacc[f][0] *= c0; oacc[f][1] *= c0;
            oacc[f][2] *= c1; oacc[f][3] *= c1;
        }

        // ---- pack P single-plane ----
        uint32_t pP[4][4];
#pragma unroll
        for (int kc = 0; kc < 4; kc++) {
            pP[kc][0] = cvt2h(sacc[2 * kc][0],     sacc[2 * kc][1]);
            pP[kc][1] = cvt2h(sacc[2 * kc][2],     sacc[2 * kc][3]);
            pP[kc][2] = cvt2h(sacc[2 * kc + 1][0], sacc[2 * kc + 1][1]);
            pP[kc][3] = cvt2h(sacc[2 * kc + 1][2], sacc[2 * kc + 1][3]);
        }

        // ---- O += P V ----
        const uint32_t vb = kb + KVPLANE;
#pragma unroll
        for (int kc = 0; kc < 4; kc++) {
#pragma unroll
            for (int dj = 0; dj < 8; dj++) {
                uint32_t vh[4];
                ldsm4t(vh, vb + (kc * 16 + rowV) * KVROW + dj * 32 + halfV);
                mma_f16(oacc[2 * dj],     pP[kc], vh);
                mma_f16(oacc[2 * dj + 1], pP[kc], vh + 2);
            }
        }
    }

    float inv0 = 1.0f / l0, inv1 = 1.0f / l1;
    int r0 = q0 + wid * 16 + (lane >> 2);
#pragma unroll
    for (int f = 0; f < 16; f++) {
        int d = f * 8 + (lane & 3) * 2;
        size_t e0 = (size_t)r0 * (NH * HD) + h * HD + d;
        size_t e1 = e0 + (size_t)8 * (NH * HD);
        *(uint32_t*)(aoh + e0) = cvt2h(oacc[f][0] * inv0, oacc[f][1] * inv0);
        *(uint32_t*)(aoh + e1) = cvt2h(oacc[f][2] * inv1, oacc[f][3] * inv1);
    }
}

// ---------------- launch ----------------
extern "C" void kernel_launch(void* const* d_in, const int* in_sizes, int n_in,
                              void* d_out, int out_size)
{
    const float* hs    = (const float*)d_in[0];
    const float* cosb  = (const float*)d_in[1];
    const float* sinb  = (const float*)d_in[2];
    const float* pastK = (const float*)d_in[4];
    const float* pastV = (const float*)d_in[5];
    const float* Wq    = (const float*)d_in[6];
    const float* Wk    = (const float*)d_in[7];
    const float* Wv    = (const float*)d_in[8];
    const float* Wo    = (const float*)d_in[9];
    const float* qw    = (const float*)d_in[10];
    const float* kw    = (const float*)d_in[11];

    float* out  = (float*)d_out;
    float* newK = out + (size_t)Q * NH * HD;
    float* newV = newK + (size_t)NKV * Q * HD;

    float *qtmp, *ktmp;
    h16 *hsh, *wqh, *wql, *wkh, *wkl, *wvh, *woh;
    h16 *qph, *kph, *vph, *aoh;
    cudaGetSymbolAddress((void**)&qtmp, g_qtmp);
    cudaGetSymbolAddress((void**)&ktmp, g_ktmp);
    cudaGetSymbolAddress((void**)&hsh, g_hs_h);
    cudaGetSymbolAddress((void**)&wqh, g_wq_h);
    cudaGetSymbolAddress((void**)&wql, g_wq_l);
    cudaGetSymbolAddress((void**)&wkh, g_wk_h);
    cudaGetSymbolAddress((void**)&wkl, g_wk_l);
    cudaGetSymbolAddress((void**)&wvh, g_wv_h);
    cudaGetSymbolAddress((void**)&woh, g_wo_h);
    cudaGetSymbolAddress((void**)&qph, g_q_h);
    cudaGetSymbolAddress((void**)&kph, g_k_h);
    cudaGetSymbolAddress((void**)&vph, g_v_h);
    cudaGetSymbolAddress((void**)&aoh, g_ao_h);

    cudaFuncSetAttribute(hgemm_qkv, cudaFuncAttributeMaxDynamicSharedMemorySize, HG_SMEM);
    cudaFuncSetAttribute(hgemm_o, cudaFuncAttributeMaxDynamicSharedMemorySize, HO_SMEM);
    cudaFuncSetAttribute(attn_mma, cudaFuncAttributeMaxDynamicSharedMemorySize, AT_SMEM);

    // single merged split
    ksplit_all<<<20480, 256>>>(hs, hsh, Wq, wqh, wql, Wk, wkh, wkl,
                               Wv, wvh, Wo, woh, pastK, kph, pastV, vph);

    // fused QKV projection
    hgemm_qkv<<<dim3(32, Q / 128), 256, HG_SMEM>>>(
        hsh, wqh, wql, wkh, wkl, wvh, qtmp, ktmp, newV, vph);

    // rmsnorm + rope
    norm_rope<<<dim3(Q, NH + NKV), 128>>>(qtmp, ktmp, cosb, sinb, qw, kw,
                                          qph, newK, kph);

    // attention
    attn_mma<<<dim3(NH, Q / AT_TQ), 256, AT_SMEM>>>(qph, kph, vph, aoh);

    // output projection
    hgemm_o<<<dim3(NH * HD / 128, Q / 128), 256, HO_SMEM>>>(aoh, woh, out);
}

// round 11
// speedup vs baseline: 11.5616x; 1.0232x over previous
#include <cuda_runtime.h>
#include <cuda_fp16.h>
#include <cstdint>

#define Q    2048
#define H    2048
#define NH   16
#define NKV  8
#define HD   128
#define PAST 2048
#define KVLEN (PAST + Q)
#define KEPS 1e-6f

typedef __half h16;

// ---------------- scratch (no allocation allowed) ----------------
__device__ float g_qtmp[Q * NH * HD];
__device__ float g_ktmp[Q * NKV * HD];
__device__ h16 g_hs_h[Q * H];
__device__ h16 g_wq_h[NH * HD * H],  g_wq_l[NH * HD * H];
__device__ h16 g_wk_h[NKV * HD * H], g_wk_l[NKV * HD * H];
__device__ h16 g_wv_h[NKV * HD * H];
__device__ h16 g_wo_h[NH * HD * NH * HD];
__device__ h16 g_q_h[NH * Q * HD];
__device__ h16 g_k_h[NKV * KVLEN * HD];
__device__ h16 g_v_h[NKV * KVLEN * HD];
__device__ h16 g_ao_h[Q * NH * HD];

// ---------------- helpers ----------------
__device__ __forceinline__ uint32_t smem_u32(const void* p) {
    uint32_t a;
    asm("{ .reg .u64 t; cvta.to.shared.u64 t, %1; cvt.u32.u64 %0, t; }" : "=r"(a) : "l"(p));
    return a;
}
__device__ __forceinline__ uint32_t packh(h16 a, h16 b) {
    return (uint32_t)__half_as_ushort(a) | ((uint32_t)__half_as_ushort(b) << 16);
}
__device__ __forceinline__ uint32_t cvt2h(float a, float b) {
    return packh(__float2half_rn(a), __float2half_rn(b));
}
__device__ __forceinline__ void split2h(float a, float b, uint32_t& hi, uint32_t& lo) {
    h16 ha = __float2half_rn(a), hb = __float2half_rn(b);
    hi = packh(ha, hb);
    lo = packh(__float2half_rn(a - __half2float(ha)),
               __float2half_rn(b - __half2float(hb)));
}
__device__ __forceinline__ void ldsm4(uint32_t* r, uint32_t addr) {
    asm volatile("ldmatrix.sync.aligned.m8n8.x4.shared.b16 {%0,%1,%2,%3}, [%4];"
                 : "=r"(r[0]), "=r"(r[1]), "=r"(r[2]), "=r"(r[3]) : "r"(addr));
}
__device__ __forceinline__ void ldsm4t(uint32_t* r, uint32_t addr) {
    asm volatile("ldmatrix.sync.aligned.m8n8.x4.trans.shared.b16 {%0,%1,%2,%3}, [%4];"
                 : "=r"(r[0]), "=r"(r[1]), "=r"(r[2]), "=r"(r[3]) : "r"(addr));
}
__device__ __forceinline__ void mma_f16(float* c, const uint32_t* a, const uint32_t* b) {
    asm volatile(
        "mma.sync.aligned.m16n8k16.row.col.f32.f16.f16.f32 "
        "{%0,%1,%2,%3}, {%4,%5,%6,%7}, {%8,%9}, {%0,%1,%2,%3};"
        : "+f"(c[0]), "+f"(c[1]), "+f"(c[2]), "+f"(c[3])
        : "r"(a[0]), "r"(a[1]), "r"(a[2]), "r"(a[3]), "r"(b[0]), "r"(b[1]));
}
__device__ __forceinline__ void cp16(uint32_t dst, const void* src) {
    asm volatile("cp.async.cg.shared.global [%0], [%1], 16;"
                 :: "r"(dst), "l"(__cvta_generic_to_global(src)));
}
__device__ __forceinline__ void cpcommit() { asm volatile("cp.async.commit_group;"); }
template <int N>
__device__ __forceinline__ void cpwait() {
    asm volatile("cp.async.wait_group %0;" :: "n"(N));
}
__device__ __forceinline__ float ex2(float x) {
    float y;
    asm("ex2.approx.f32 %0, %1;" : "=f"(y) : "f"(x));
    return y;
}

// ---------------- merged split kernel (4 float4 / thread) ----------------
// virtual block ranges (1024 floats each):
// hs [0,4096) single | wq [4096,8192) split | wk [8192,10240) split
// wv [10240,12288) single | wo [12288,16384) single | caches [16384,20480) single
__device__ __forceinline__ void ksplit_body(
    int b, int tid,
    const float* hs, h16* hsh,
    const float* wq, h16* wqh, h16* wql,
    const float* wk, h16* wkh, h16* wkl,
    const float* wv, h16* wvh,
    const float* wo, h16* woh,
    const float* pk, h16* kch,
    const float* pv, h16* vch)
{
    if (b >= 16384) {   // caches (strided dst)
        b -= 16384;
        const float* x;
        h16* dst;
        if (b < 2048) { x = pk; dst = kch; }
        else          { x = pv; dst = vch; b -= 2048; }
        int i = b * 256 + tid;
        int e = i * 4;
        int kv = e / (PAST * HD);
        int rem = e - kv * (PAST * HD);
        size_t de = (size_t)kv * (KVLEN * HD) + rem;
        float4 v = ((const float4*)x)[i];
        *(uint32_t*)(dst + de)     = cvt2h(v.x, v.y);
        *(uint32_t*)(dst + de + 2) = cvt2h(v.z, v.w);
        return;
    }
    if (b < 4096 || b >= 10240) {   // single-plane conversions
        const float* src;
        h16* dst;
        int base;
        if (b < 4096)       { src = hs; dst = hsh; base = 0; }
        else if (b < 12288) { src = wv; dst = wvh; base = 10240; }
        else                { src = wo; dst = woh; base = 12288; }
        int i = (b - base) * 256 + tid;
        float4 v = ((const float4*)src)[i];
        ((uint32_t*)dst)[2 * i]     = cvt2h(v.x, v.y);
        ((uint32_t*)dst)[2 * i + 1] = cvt2h(v.z, v.w);
        return;
    }
    // split conversions (wq, wk)
    const float* src;
    h16 *hi, *lo;
    int base;
    if (b < 8192) { src = wq; hi = wqh; lo = wql; base = 4096; }
    else          { src = wk; hi = wkh; lo = wkl; base = 8192; }
    int i = (b - base) * 256 + tid;
    float4 v = ((const float4*)src)[i];
    uint32_t h0, l0, h1, l1;
    split2h(v.x, v.y, h0, l0);
    split2h(v.z, v.w, h1, l1);
    ((uint32_t*)hi)[2 * i] = h0;  ((uint32_t*)hi)[2 * i + 1] = h1;
    ((uint32_t*)lo)[2 * i] = l0;  ((uint32_t*)lo)[2 * i + 1] = l1;
}

__global__ __launch_bounds__(256) void ksplit_all(
    const float* __restrict__ hs, h16* __restrict__ hsh,
    const float* __restrict__ wq, h16* __restrict__ wqh, h16* __restrict__ wql,
    const float* __restrict__ wk, h16* __restrict__ wkh, h16* __restrict__ wkl,
    const float* __restrict__ wv, h16* __restrict__ wvh,
    const float* __restrict__ wo, h16* __restrict__ woh,
    const float* __restrict__ pk, h16* __restrict__ kch,
    const float* __restrict__ pv, h16* __restrict__ vch)
{
#pragma unroll
    for (int j = 0; j < 4; j++) {
        ksplit_body(blockIdx.x * 4 + j, threadIdx.x,
                    hs, hsh, wq, wqh, wql, wk, wkh, wkl,
                    wv, wvh, wo, woh, pk, kch, pv, vch);
    }
}

// ---------------- GEMM constants ----------------
#define ROWB   80
#define PLANEB 10240
#define STAGEB 30720          // 3 planes (A, Bhi, Blo)
#define HG_SMEM (2 * STAGEB)
#define STAGEB2 20480         // 2 planes (A, B)
#define HO_SMEM (2 * STAGEB2)

// ---------------- fused QKV projection GEMM ----------------
__global__ __launch_bounds__(256) void hgemm_qkv(
    const h16* __restrict__ hsh,
    const h16* __restrict__ wqh, const h16* __restrict__ wql,
    const h16* __restrict__ wkh, const h16* __restrict__ wkl,
    const h16* __restrict__ wvh,
    float* __restrict__ qtmp, float* __restrict__ ktmp, float* __restrict__ newV,
    h16* __restrict__ vph)
{
    extern __shared__ char hsm[];
    const int bx = blockIdx.x;
    const int tid = threadIdx.x;
    const int lane = tid & 31;
    const int wid = tid >> 5;
    const int wm = wid >> 2;
    const int wn = wid & 3;
    const uint32_t base_u = smem_u32(hsm);
    const int K = H;

    const h16 *Bhi, *Blo;
    int colb;
    if (bx < 16)      { Bhi = wqh; Blo = wql; colb = bx * 128; }
    else if (bx < 24) { Bhi = wkh; Blo = wkl; colb = (bx - 16) * 128; }
    else              { Bhi = wvh; Blo = wvh; colb = (bx - 24) * 128; }
    const bool dolo = bx < 24;

    const h16* pl[3] = {
        hsh + (size_t)(blockIdx.y * 128) * K,
        Bhi + (size_t)colb * K,
        Blo + (size_t)colb * K };

    const int rowselA = lane & 15;
    const int halfA = lane >> 4;
    const int rowselB = (lane & 7) + (lane >> 4) * 8;
    const int halfB = (lane >> 3) & 1;
    const uint32_t aoff0 = (uint32_t)((wm * 64 + rowselA) * ROWB + halfA * 16);
    const uint32_t boff0 = (uint32_t)((wn * 32 + rowselB) * ROWB + halfB * 16);

    float acc[4][4][4];
#pragma unroll
    for (int i = 0; i < 4; i++)
#pragma unroll
        for (int j = 0; j < 4; j++)
#pragma unroll
            for (int r = 0; r < 4; r++) acc[i][j][r] = 0.0f;

    const int nst = K / 32;
    const int nld = dolo ? 1536 : 1024;
    {
        uint32_t dstb = base_u;
        for (int i = tid; i < nld; i += 256) {
            int p = i >> 9, row = (i >> 2) & 127, seg = i & 3;
            cp16(dstb + p * PLANEB + row * ROWB + seg * 16,
                 pl[p] + (size_t)row * K + seg * 8);
        }
        cpcommit();
    }

    for (int s = 0; s < nst; s++) {
        cpwait<0>();
        __syncthreads();
        if (s + 1 < nst) {
            int kt = (s + 1) * 32;
            uint32_t dstb = base_u + ((s + 1) & 1) * STAGEB;
            for (int i = tid; i < nld; i += 256) {
                int p = i >> 9, row = (i >> 2) & 127, seg = i & 3;
                cp16(dstb + p * PLANEB + row * ROWB + seg * 16,
                     pl[p] + (size_t)row * K + kt + seg * 8);
            }
            cpcommit();
        }
        const uint32_t sb = base_u + (s & 1) * STAGEB;
#pragma unroll
        for (int kc = 0; kc < 2; kc++) {
            uint32_t ah[4][4];
#pragma unroll
            for (int mi = 0; mi < 4; mi++)
                ldsm4(ah[mi], sb + aoff0 + mi * (16 * ROWB) + kc * 32);
            uint32_t bh[4][2], bl[4][2];
#pragma unroll
            for (int p = 0; p < 2; p++) {
                uint32_t bd = sb + PLANEB + boff0 + p * (16 * ROWB) + kc * 32;
                uint32_t r[4];
                ldsm4(r, bd);
                bh[2 * p][0] = r[0]; bh[2 * p][1] = r[1];
                bh[2 * p + 1][0] = r[2]; bh[2 * p + 1][1] = r[3];
                if (dolo) {
                    ldsm4(r, bd + PLANEB);
                    bl[2 * p][0] = r[0]; bl[2 * p][1] = r[1];
                    bl[2 * p + 1][0] = r[2]; bl[2 * p + 1][1] = r[3];
                }
            }
#pragma unroll
            for (int mi = 0; mi < 4; mi++) {
#pragma unroll
                for (int nj = 0; nj < 4; nj++) {
                    mma_f16(acc[mi][nj], ah[mi], bh[nj]);
                    if (dolo) mma_f16(acc[mi][nj], ah[mi], bl[nj]);
                }
            }
        }
    }

    const int rfrag = lane >> 2;
    const int cpair = (lane & 3) * 2;
#pragma unroll
    for (int mi = 0; mi < 4; mi++) {
#pragma unroll
        for (int nj = 0; nj < 4; nj++) {
            int coll = colb + wn * 32 + nj * 8 + cpair;
#pragma unroll
            for (int half = 0; half < 2; half++) {
                int rowg = blockIdx.y * 128 + wm * 64 + mi * 16 + rfrag + half * 8;
                float2 v = make_float2(acc[mi][nj][2 * half], acc[mi][nj][2 * half + 1]);
                if (bx < 16) {
                    *(float2*)(qtmp + (size_t)rowg * (NH * HD) + coll) = v;
                } else if (bx < 24) {
                    *(float2*)(ktmp + (size_t)rowg * (NKV * HD) + coll) = v;
                } else {
                    int kv = coll >> 7, d = coll & 127;
                    *(float2*)(newV + (size_t)kv * (Q * HD) + (size_t)rowg * HD + d) = v;
                    size_t de = (size_t)kv * (KVLEN * HD) + (size_t)(PAST + rowg) * HD + d;
                    *(uint32_t*)(vph + de) = cvt2h(v.x, v.y);
                }
            }
        }
    }
}

// ---------------- output projection GEMM (single x single) ----------------
__global__ __launch_bounds__(256) void hgemm_o(
    const h16* __restrict__ Ah, const h16* __restrict__ Bh,
    float* __restrict__ C)
{
    extern __shared__ char hsm[];
    const int tid = threadIdx.x;
    const int lane = tid & 31;
    const int wid = tid >> 5;
    const int wm = wid >> 2;
    const int wn = wid & 3;
    const uint32_t base_u = smem_u32(hsm);
    const int K = NH * HD, N = NH * HD;

    const h16* pl[2] = {
        Ah + (size_t)(blockIdx.y * 128) * K,
        Bh + (size_t)(blockIdx.x * 128) * K };

    const int rowselA = lane & 15;
    const int halfA = lane >> 4;
    const int rowselB = (lane & 7) + (lane >> 4) * 8;
    const int halfB = (lane >> 3) & 1;
    const uint32_t aoff0 = (uint32_t)((wm * 64 + rowselA) * ROWB + halfA * 16);
    const uint32_t boff0 = (uint32_t)((wn * 32 + rowselB) * ROWB + halfB * 16);

    float acc[4][4][4];
#pragma unroll
    for (int i = 0; i < 4; i++)
#pragma unroll
        for (int j = 0; j < 4; j++)
#pragma unroll
            for (int r = 0; r < 4; r++) acc[i][j][r] = 0.0f;

    const int nst = K / 32;
    {
        uint32_t dstb = base_u;
        for (int i = tid; i < 1024; i += 256) {
            int p = i >> 9, row = (i >> 2) & 127, seg = i & 3;
            cp16(dstb + p * PLANEB + row * ROWB + seg * 16,
                 pl[p] + (size_t)row * K + seg * 8);
        }
        cpcommit();
    }

    for (int s = 0; s < nst; s++) {
        cpwait<0>();
        __syncthreads();
        if (s + 1 < nst) {
            int kt = (s + 1) * 32;
            uint32_t dstb = base_u + ((s + 1) & 1) * STAGEB2;
            for (int i = tid; i < 1024; i += 256) {
                int p = i >> 9, row = (i >> 2) & 127, seg = i & 3;
                cp16(dstb + p * PLANEB + row * ROWB + seg * 16,
                     pl[p] + (size_t)row * K + kt + seg * 8);
            }
            cpcommit();
        }
        const uint32_t sb = base_u + (s & 1) * STAGEB2;
#pragma unroll
        for (int kc = 0; kc < 2; kc++) {
            uint32_t ah[4][4];
#pragma unroll
            for (int mi = 0; mi < 4; mi++)
                ldsm4(ah[mi], sb + aoff0 + mi * (16 * ROWB) + kc * 32);
            uint32_t bh[4][2];
#pragma unroll
            for (int p = 0; p < 2; p++) {
                uint32_t r[4];
                ldsm4(r, sb + PLANEB + boff0 + p * (16 * ROWB) + kc * 32);
                bh[2 * p][0] = r[0]; bh[2 * p][1] = r[1];
                bh[2 * p + 1][0] = r[2]; bh[2 * p + 1][1] = r[3];
            }
#pragma unroll
            for (int mi = 0; mi < 4; mi++)
#pragma unroll
                for (int nj = 0; nj < 4; nj++)
                    mma_f16(acc[mi][nj], ah[mi], bh[nj]);
        }
    }

    const int rfrag = lane >> 2;
    const int cpair = (lane & 3) * 2;
#pragma unroll
    for (int mi = 0; mi < 4; mi++) {
#pragma unroll
        for (int nj = 0; nj < 4; nj++) {
            int colg = blockIdx.x * 128 + wn * 32 + nj * 8 + cpair;
#pragma unroll
            for (int half = 0; half < 2; half++) {
                int rowg = blockIdx.y * 128 + wm * 64 + mi * 16 + rfrag + half * 8;
                *(float2*)(C + (size_t)rowg * N + colg) =
                    make_float2(acc[mi][nj][2 * half], acc[mi][nj][2 * half + 1]);
            }
        }
    }
}

// ---------------- RMSNorm + RoPE (+ fp16 outputs) ----------------
__global__ __launch_bounds__(128) void norm_rope(
    const float* __restrict__ qtmp, const float* __restrict__ ktmp,
    const float* __restrict__ cosb, const float* __restrict__ sinb,
    const float* __restrict__ qw, const float* __restrict__ kw,
    h16* __restrict__ qh, float* __restrict__ newK, h16* __restrict__ kh)
{
    const float QSC = 0.08838834764831845f * 1.44269504088896341f;
    int s = blockIdx.x;
    int hh = blockIdx.y;
    int t = threadIdx.x;

    const float* src;
    const float* w;
    if (hh < NH) {
        src = qtmp + (size_t)s * (NH * HD) + hh * HD;
        w = qw;
    } else {
        src = ktmp + (size_t)s * (NKV * HD) + (hh - NH) * HD;
        w = kw;
    }

    float x = src[t];
    float v = x * x;
#pragma unroll
    for (int o = 16; o; o >>= 1) v += __shfl_xor_sync(0xffffffffu, v, o);
    __shared__ float red[4];
    if ((t & 31) == 0) red[t >> 5] = v;
    __syncthreads();
    float sum = red[0] + red[1] + red[2] + red[3];
    float rs = rsqrtf(sum * (1.0f / HD) + KEPS);
    float xn = x * rs * w[t];

    __shared__ float sh[HD];
    sh[t] = xn;
    __syncthreads();
    float c = cosb[(size_t)s * HD + t];
    float si = sinb[(size_t)s * HD + t];
    float rot = (t < 64) ? -sh[t + 64] : sh[t - 64];
    float val = xn * c + rot * si;

    if (hh < NH) {
        qh[((size_t)hh * Q + s) * HD + t] = __float2half_rn(val * QSC);
    } else {
        int kv = hh - NH;
        newK[((size_t)kv * Q + s) * HD + t] = val;
        kh[((size_t)kv * KVLEN + PAST + s) * HD + t] = __float2half_rn(val);
    }
}

// ---------------- Flash attention: TQ=64, 128 threads, 2 CTAs/SM ----------------
#define AT_TQ 64
#define AT_TK 64
#define KVROW 272
#define KVPLANE (64 * KVROW)
#define TILEBUF (2 * KVPLANE)
#define AT_SMEM (2 * TILEBUF)

__global__ __launch_bounds__(128, 2) void attn_mma(
    const h16* __restrict__ qh,
    const h16* __restrict__ kch, const h16* __restrict__ vch,
    h16* __restrict__ aoh)
{
    extern __shared__ char asmem[];
    const int h = blockIdx.x;
    const int q0 = ((int)gridDim.y - 1 - (int)blockIdx.y) * AT_TQ;  // largest-first
    const int kvh = h >> 1;
    const int tid = threadIdx.x;
    const int lane = tid & 31;
    const int wid = tid >> 5;          // 0..3, each warp owns 16 q-rows
    const uint32_t sb = smem_u32(asmem);

    // stage Q (single plane, 64 rows) into buf0 region, extract fragments
    {
        const h16* qsrc = qh + ((size_t)h * Q + q0) * HD;
        for (int i = tid; i < 1024; i += 128) {
            int row = i >> 4, seg = i & 15;
            cp16(sb + row * KVROW + seg * 16, qsrc + (size_t)row * HD + seg * 8);
        }
        cpcommit();
        cpwait<0>();
        __syncthreads();
    }
    uint32_t aQh[8][4];
    {
        uint32_t a0 = sb + (wid * 16 + (lane & 15)) * KVROW + (lane >> 4) * 16;
#pragma unroll
        for (int kc = 0; kc < 8; kc++)
            ldsm4(aQh[kc], a0 + kc * 32);
    }
    __syncthreads();

    float oacc[16][4];
#pragma unroll
    for (int f = 0; f < 16; f++)
#pragma unroll
        for (int r = 0; r < 4; r++) oacc[f][r] = 0.0f;
    float m0 = -1e30f, m1 = -1e30f, l0 = 0.0f, l1 = 0.0f;

    const int nt = (PAST + q0 + AT_TQ) / AT_TK;
    const h16* ksrc = kch + (size_t)kvh * KVLEN * HD;
    const h16* vsrc = vch + (size_t)kvh * KVLEN * HD;

    // preload tile 0 into buf 0
    {
        for (int i = tid; i < 2048; i += 128) {
            int p = i >> 10, row = (i >> 4) & 63, seg = i & 15;
            const h16* s0 = p ? vsrc : ksrc;
            cp16(sb + p * KVPLANE + row * KVROW + seg * 16,
                 s0 + (size_t)row * HD + seg * 8);
        }
        cpcommit();
    }

    const int rowselB = (lane & 7) + (lane >> 4) * 8;
    const int halfB = (lane >> 3) & 1;
    const int rowV = lane & 15;
    const int halfV = (lane >> 4) * 16;

    for (int t = 0; t < nt; t++) {
        __syncthreads();
        if (t + 1 < nt) {
            int j1 = (t + 1) * AT_TK;
            uint32_t db = sb + ((t + 1) & 1) * TILEBUF;
            for (int i = tid; i < 2048; i += 128) {
                int p = i >> 10, row = (i >> 4) & 63, seg = i & 15;
                const h16* s0 = p ? vsrc : ksrc;
                cp16(db + p * KVPLANE + row * KVROW + seg * 16,
                     s0 + (size_t)(j1 + row) * HD + seg * 8);
            }
            cpcommit();
            cpwait<1>();
        } else {
            cpwait<0>();
        }
        __syncthreads();

        const uint32_t kb = sb + (t & 1) * TILEBUF;
        const int j0 = t * AT_TK;

        // ---- S = Q K^T ----
        float sacc[8][4];
#pragma unroll
        for (int j = 0; j < 8; j++)
#pragma unroll
            for (int r = 0; r < 4; r++) sacc[j][r] = 0.0f;
#pragma unroll
        for (int kc = 0; kc < 8; kc++) {
#pragma unroll
            for (int nj = 0; nj < 4; nj++) {
                uint32_t kh[4];
                ldsm4(kh, kb + (nj * 16 + rowselB) * KVROW + halfB * 16 + kc * 32);
                mma_f16(sacc[2 * nj],     aQh[kc], kh);
                mma_f16(sacc[2 * nj + 1], aQh[kc], kh + 2);
            }
        }

        if (j0 + AT_TK - 1 > PAST + q0 + wid * 16) {
            int r0g = PAST + q0 + wid * 16 + (lane >> 2);
#pragma unroll
            for (int j = 0; j < 8; j++) {
                int cg = j0 + j * 8 + (lane & 3) * 2;
                if (cg > r0g)     sacc[j][0] = -1e30f;
                if (cg + 1 > r0g) sacc[j][1] = -1e30f;
                if (cg > r0g + 8)     sacc[j][2] = -1e30f;
                if (cg + 1 > r0g + 8) sacc[j][3] = -1e30f;
            }
        }

        float t0 = -1e30f, t1 = -1e30f;
#pragma unroll
        for (int j = 0; j < 8; j++) {
            t0 = fmaxf(t0, fmaxf(sacc[j][0], sacc[j][1]));
            t1 = fmaxf(t1, fmaxf(sacc[j][2], sacc[j][3]));
        }
        t0 = fmaxf(t0, __shfl_xor_sync(0xffffffffu, t0, 1));
        t0 = fmaxf(t0, __shfl_xor_sync(0xffffffffu, t0, 2));
        t1 = fmaxf(t1, __shfl_xor_sync(0xffffffffu, t1, 1));
        t1 = fmaxf(t1, __shfl_xor_sync(0xffffffffu, t1, 2));
        float mn0 = fmaxf(m0, t0), mn1 = fmaxf(m1, t1);
        float c0 = ex2(m0 - mn0), c1 = ex2(m1 - mn1);
        m0 = mn0; m1 = mn1;
        float ps0 = 0.0f, ps1 = 0.0f;
#pragma unroll
        for (int j = 0; j < 8; j++) {
            sacc[j][0] = ex2(sacc[j][0] - mn0); ps0 += sacc[j][0];
            sacc[j][1] = ex2(sacc[j][1] - mn0); ps0 += sacc[j][1];
            sacc[j][2] = ex2(sacc[j][2] - mn1); ps1 += sacc[j][2];
            sacc[j][3] = ex2(sacc[j][3] - mn1); ps1 += sacc[j][3];
        }
        ps0 += __shfl_xor_sync(0xffffffffu, ps0, 1);
        ps0 += __shfl_xor_sync(0xffffffffu, ps0, 2);
        ps1 += __shfl_xor_sync(0xffffffffu, ps1, 1);
        ps1 += __shfl_xor_sync(0xffffffffu, ps1, 2);
        l0 = l0 * c0 + ps0;
        l1 = l1 * c1 + ps1;
#pragma unroll
        for (int f = 0; f < 16; f++) {
            oacc[f][0] *= c0; oacc[f][1] *= c0;
            oacc[f][2] *= c1; oacc[f][3] *= c1;
        }

        // ---- pack P single-plane ----
        uint32_t pP[4][4];
#pragma unroll
        for (int kc = 0; kc < 4; kc++) {
            pP[kc][0] = cvt2h(sacc[2 * kc][0],     sacc[2 * kc][1]);
            pP[kc][1] = cvt2h(sacc[2 * kc][2],     sacc[2 * kc][3]);
            pP[kc][2] = cvt2h(sacc[2 * kc + 1][0], sacc[2 * kc + 1][1]);
            pP[kc][3] = cvt2h(sacc[2 * kc + 1][2], sacc[2 * kc + 1][3]);
        }

        // ---- O += P V ----
        const uint32_t vb = kb + KVPLANE;
#pragma unroll
        for (int kc = 0; kc < 4; kc++) {
#pragma unroll
            for (int dj = 0; dj < 8; dj++) {
                uint32_t vh[4];
                ldsm4t(vh, vb + (kc * 16 + rowV) * KVROW + dj * 32 + halfV);
                mma_f16(oacc[2 * dj],     pP[kc], vh);
                mma_f16(oacc[2 * dj + 1], pP[kc], vh + 2);
            }
        }
    }

    float inv0 = 1.0f / l0, inv1 = 1.0f / l1;
    int r0 = q0 + wid * 16 + (lane >> 2);
#pragma unroll
    for (int f = 0; f < 16; f++) {
        int d = f * 8 + (lane & 3) * 2;
        size_t e0 = (size_t)r0 * (NH * HD) + h * HD + d;
        size_t e1 = e0 + (size_t)8 * (NH * HD);
        *(uint32_t*)(aoh + e0) = cvt2h(oacc[f][0] * inv0, oacc[f][1] * inv0);
        *(uint32_t*)(aoh + e1) = cvt2h(oacc[f][2] * inv1, oacc[f][3] * inv1);
    }
}

// ---------------- launch ----------------
extern "C" void kernel_launch(void* const* d_in, const int* in_sizes, int n_in,
                              void* d_out, int out_size)
{
    const float* hs    = (const float*)d_in[0];
    const float* cosb  = (const float*)d_in[1];
    const float* sinb  = (const float*)d_in[2];
    const float* pastK = (const float*)d_in[4];
    const float* pastV = (const float*)d_in[5];
    const float* Wq    = (const float*)d_in[6];
    const float* Wk    = (const float*)d_in[7];
    const float* Wv    = (const float*)d_in[8];
    const float* Wo    = (const float*)d_in[9];
    const float* qw    = (const float*)d_in[10];
    const float* kw    = (const float*)d_in[11];

    float* out  = (float*)d_out;
    float* newK = out + (size_t)Q * NH * HD;
    float* newV = newK + (size_t)NKV * Q * HD;

    float *qtmp, *ktmp;
    h16 *hsh, *wqh, *wql, *wkh, *wkl, *wvh, *woh;
    h16 *qph, *kph, *vph, *aoh;
    cudaGetSymbolAddress((void**)&qtmp, g_qtmp);
    cudaGetSymbolAddress((void**)&ktmp, g_ktmp);
    cudaGetSymbolAddress((void**)&hsh, g_hs_h);
    cudaGetSymbolAddress((void**)&wqh, g_wq_h);
    cudaGetSymbolAddress((void**)&wql, g_wq_l);
    cudaGetSymbolAddress((void**)&wkh, g_wk_h);
    cudaGetSymbolAddress((void**)&wkl, g_wk_l);
    cudaGetSymbolAddress((void**)&wvh, g_wv_h);
    cudaGetSymbolAddress((void**)&woh, g_wo_h);
    cudaGetSymbolAddress((void**)&qph, g_q_h);
    cudaGetSymbolAddress((void**)&kph, g_k_h);
    cudaGetSymbolAddress((void**)&vph, g_v_h);
    cudaGetSymbolAddress((void**)&aoh, g_ao_h);

    cudaFuncSetAttribute(hgemm_qkv, cudaFuncAttributeMaxDynamicSharedMemorySize, HG_SMEM);
    cudaFuncSetAttribute(hgemm_o, cudaFuncAttributeMaxDynamicSharedMemorySize, HO_SMEM);
    cudaFuncSetAttribute(attn_mma, cudaFuncAttributeMaxDynamicSharedMemorySize, AT_SMEM);

    // merged split (4 virtual blocks per real block)
    ksplit_all<<<5120, 256>>>(hs, hsh, Wq, wqh, wql, Wk, wkh, wkl,
                              Wv, wvh, Wo, woh, pastK, kph, pastV, vph);

    // fused QKV projection
    hgemm_qkv<<<dim3(32, Q / 128), 256, HG_SMEM>>>(
        hsh, wqh, wql, wkh, wkl, wvh, qtmp, ktmp, newV, vph);

    // rmsnorm + rope
    norm_rope<<<dim3(Q, NH + NKV), 128>>>(qtmp, ktmp, cosb, sinb, qw, kw,
                                          qph, newK, kph);

    // attention (TQ=64, 2 CTAs/SM)
    attn_mma<<<dim3(NH, Q / AT_TQ), 128, AT_SMEM>>>(qph, kph, vph, aoh);

    // output projection
    hgemm_o<<<dim3(NH * HD / 128, Q / 128), 256, HO_SMEM>>>(aoh, woh, out);
}

// round 12
// speedup vs baseline: 14.3128x; 1.2380x over previous
#include <cuda_runtime.h>
#include <cuda_fp16.h>
#include <cstdint>

#define Q    2048
#define H    2048
#define NH   16
#define NKV  8
#define HD   128
#define PAST 2048
#define KVLEN (PAST + Q)
#define KEPS 1e-6f

typedef __half h16;

// ---------------- scratch (no allocation allowed) ----------------
__device__ float g_qtmp[Q * NH * HD];
__device__ float g_ktmp[Q * NKV * HD];
__device__ h16 g_hs_h[Q * H];
__device__ h16 g_wq_h[NH * HD * H];
__device__ h16 g_wk_h[NKV * HD * H];
__device__ h16 g_wv_h[NKV * HD * H];
__device__ h16 g_wo_h[NH * HD * NH * HD];
__device__ h16 g_q_h[NH * Q * HD];
__device__ h16 g_k_h[NKV * KVLEN * HD];
__device__ h16 g_v_h[NKV * KVLEN * HD];
__device__ h16 g_ao_h[Q * NH * HD];

// ---------------- helpers ----------------
__device__ __forceinline__ uint32_t smem_u32(const void* p) {
    uint32_t a;
    asm("{ .reg .u64 t; cvta.to.shared.u64 t, %1; cvt.u32.u64 %0, t; }" : "=r"(a) : "l"(p));
    return a;
}
__device__ __forceinline__ uint32_t packh(h16 a, h16 b) {
    return (uint32_t)__half_as_ushort(a) | ((uint32_t)__half_as_ushort(b) << 16);
}
__device__ __forceinline__ uint32_t cvt2h(float a, float b) {
    return packh(__float2half_rn(a), __float2half_rn(b));
}
__device__ __forceinline__ void ldsm4(uint32_t* r, uint32_t addr) {
    asm volatile("ldmatrix.sync.aligned.m8n8.x4.shared.b16 {%0,%1,%2,%3}, [%4];"
                 : "=r"(r[0]), "=r"(r[1]), "=r"(r[2]), "=r"(r[3]) : "r"(addr));
}
__device__ __forceinline__ void ldsm4t(uint32_t* r, uint32_t addr) {
    asm volatile("ldmatrix.sync.aligned.m8n8.x4.trans.shared.b16 {%0,%1,%2,%3}, [%4];"
                 : "=r"(r[0]), "=r"(r[1]), "=r"(r[2]), "=r"(r[3]) : "r"(addr));
}
__device__ __forceinline__ void mma_f16(float* c, const uint32_t* a, const uint32_t* b) {
    asm volatile(
        "mma.sync.aligned.m16n8k16.row.col.f32.f16.f16.f32 "
        "{%0,%1,%2,%3}, {%4,%5,%6,%7}, {%8,%9}, {%0,%1,%2,%3};"
        : "+f"(c[0]), "+f"(c[1]), "+f"(c[2]), "+f"(c[3])
        : "r"(a[0]), "r"(a[1]), "r"(a[2]), "r"(a[3]), "r"(b[0]), "r"(b[1]));
}
__device__ __forceinline__ void cp16(uint32_t dst, const void* src) {
    asm volatile("cp.async.cg.shared.global [%0], [%1], 16;"
                 :: "r"(dst), "l"(__cvta_generic_to_global(src)));
}
__device__ __forceinline__ void cpcommit() { asm volatile("cp.async.commit_group;"); }
template <int N>
__device__ __forceinline__ void cpwait() {
    asm volatile("cp.async.wait_group %0;" :: "n"(N));
}
__device__ __forceinline__ float ex2(float x) {
    float y;
    asm("ex2.approx.f32 %0, %1;" : "=f"(y) : "f"(x));
    return y;
}

// ---------------- merged convert kernel (4 float4 / thread, all single-plane) ----------------
// virtual block ranges (1024 floats each):
// hs [0,4096) | wq [4096,8192) | wk [8192,10240) | wv [10240,12288)
// wo [12288,16384) | pastK [16384,18432) | pastV [18432,20480)
__device__ __forceinline__ void kconv_body(
    int b, int tid,
    const float* hs, h16* hsh, const float* wq, h16* wqh,
    const float* wk, h16* wkh, const float* wv, h16* wvh,
    const float* wo, h16* woh,
    const float* pk, h16* kch, const float* pv, h16* vch)
{
    if (b >= 16384) {   // caches (strided dst)
        b -= 16384;
        const float* x;
        h16* dst;
        if (b < 2048) { x = pk; dst = kch; }
        else          { x = pv; dst = vch; b -= 2048; }
        int i = b * 256 + tid;
        int e = i * 4;
        int kv = e / (PAST * HD);
        int rem = e - kv * (PAST * HD);
        size_t de = (size_t)kv * (KVLEN * HD) + rem;
        float4 v = ((const float4*)x)[i];
        *(uint32_t*)(dst + de)     = cvt2h(v.x, v.y);
        *(uint32_t*)(dst + de + 2) = cvt2h(v.z, v.w);
        return;
    }
    const float* src;
    h16* dst;
    int base;
    if (b < 4096)       { src = hs; dst = hsh; base = 0; }
    else if (b < 8192)  { src = wq; dst = wqh; base = 4096; }
    else if (b < 10240) { src = wk; dst = wkh; base = 8192; }
    else if (b < 12288) { src = wv; dst = wvh; base = 10240; }
    else                { src = wo; dst = woh; base = 12288; }
    int i = (b - base) * 256 + tid;
    float4 v = ((const float4*)src)[i];
    ((uint32_t*)dst)[2 * i]     = cvt2h(v.x, v.y);
    ((uint32_t*)dst)[2 * i + 1] = cvt2h(v.z, v.w);
}

__global__ __launch_bounds__(256) void kconv_all(
    const float* __restrict__ hs, h16* __restrict__ hsh,
    const float* __restrict__ wq, h16* __restrict__ wqh,
    const float* __restrict__ wk, h16* __restrict__ wkh,
    const float* __restrict__ wv, h16* __restrict__ wvh,
    const float* __restrict__ wo, h16* __restrict__ woh,
    const float* __restrict__ pk, h16* __restrict__ kch,
    const float* __restrict__ pv, h16* __restrict__ vch)
{
#pragma unroll
    for (int j = 0; j < 4; j++) {
        kconv_body(blockIdx.x * 4 + j, threadIdx.x,
                   hs, hsh, wq, wqh, wk, wkh, wv, wvh, wo, woh,
                   pk, kch, pv, vch);
    }
}

// ---------------- GEMM constants ----------------
#define ROWB   80
#define PLANEB 10240
#define STAGEB2 20480         // 2 planes (A, B)
#define HO_SMEM (2 * STAGEB2)

// ---------------- fused QKV projection GEMM (all single-plane) ----------------
// grid (32, 16): bx<16 -> Q cols, <24 -> K cols, else V cols
__global__ __launch_bounds__(256) void hgemm_qkv(
    const h16* __restrict__ hsh,
    const h16* __restrict__ wqh, const h16* __restrict__ wkh,
    const h16* __restrict__ wvh,
    float* __restrict__ qtmp, float* __restrict__ ktmp, float* __restrict__ newV,
    h16* __restrict__ vph)
{
    extern __shared__ char hsm[];
    const int bx = blockIdx.x;
    const int tid = threadIdx.x;
    const int lane = tid & 31;
    const int wid = tid >> 5;
    const int wm = wid >> 2;
    const int wn = wid & 3;
    const uint32_t base_u = smem_u32(hsm);
    const int K = H;

    const h16* Bh;
    int colb;
    if (bx < 16)      { Bh = wqh; colb = bx * 128; }
    else if (bx < 24) { Bh = wkh; colb = (bx - 16) * 128; }
    else              { Bh = wvh; colb = (bx - 24) * 128; }

    const h16* pl[2] = {
        hsh + (size_t)(blockIdx.y * 128) * K,
        Bh + (size_t)colb * K };

    const int rowselA = lane & 15;
    const int halfA = lane >> 4;
    const int rowselB = (lane & 7) + (lane >> 4) * 8;
    const int halfB = (lane >> 3) & 1;
    const uint32_t aoff0 = (uint32_t)((wm * 64 + rowselA) * ROWB + halfA * 16);
    const uint32_t boff0 = (uint32_t)((wn * 32 + rowselB) * ROWB + halfB * 16);

    float acc[4][4][4];
#pragma unroll
    for (int i = 0; i < 4; i++)
#pragma unroll
        for (int j = 0; j < 4; j++)
#pragma unroll
            for (int r = 0; r < 4; r++) acc[i][j][r] = 0.0f;

    const int nst = K / 32;
    {
        uint32_t dstb = base_u;
        for (int i = tid; i < 1024; i += 256) {
            int p = i >> 9, row = (i >> 2) & 127, seg = i & 3;
            cp16(dstb + p * PLANEB + row * ROWB + seg * 16,
                 pl[p] + (size_t)row * K + seg * 8);
        }
        cpcommit();
    }

    for (int s = 0; s < nst; s++) {
        cpwait<0>();
        __syncthreads();
        if (s + 1 < nst) {
            int kt = (s + 1) * 32;
            uint32_t dstb = base_u + ((s + 1) & 1) * STAGEB2;
            for (int i = tid; i < 1024; i += 256) {
                int p = i >> 9, row = (i >> 2) & 127, seg = i & 3;
                cp16(dstb + p * PLANEB + row * ROWB + seg * 16,
                     pl[p] + (size_t)row * K + kt + seg * 8);
            }
            cpcommit();
        }
        const uint32_t sb = base_u + (s & 1) * STAGEB2;
#pragma unroll
        for (int kc = 0; kc < 2; kc++) {
            uint32_t ah[4][4];
#pragma unroll
            for (int mi = 0; mi < 4; mi++)
                ldsm4(ah[mi], sb + aoff0 + mi * (16 * ROWB) + kc * 32);
            uint32_t bh[4][2];
#pragma unroll
            for (int p = 0; p < 2; p++) {
                uint32_t r[4];
                ldsm4(r, sb + PLANEB + boff0 + p * (16 * ROWB) + kc * 32);
                bh[2 * p][0] = r[0]; bh[2 * p][1] = r[1];
                bh[2 * p + 1][0] = r[2]; bh[2 * p + 1][1] = r[3];
            }
#pragma unroll
            for (int mi = 0; mi < 4; mi++)
#pragma unroll
                for (int nj = 0; nj < 4; nj++)
                    mma_f16(acc[mi][nj], ah[mi], bh[nj]);
        }
    }

    const int rfrag = lane >> 2;
    const int cpair = (lane & 3) * 2;
#pragma unroll
    for (int mi = 0; mi < 4; mi++) {
#pragma unroll
        for (int nj = 0; nj < 4; nj++) {
            int coll = colb + wn * 32 + nj * 8 + cpair;
#pragma unroll
            for (int half = 0; half < 2; half++) {
                int rowg = blockIdx.y * 128 + wm * 64 + mi * 16 + rfrag + half * 8;
                float2 v = make_float2(acc[mi][nj][2 * half], acc[mi][nj][2 * half + 1]);
                if (bx < 16) {
                    *(float2*)(qtmp + (size_t)rowg * (NH * HD) + coll) = v;
                } else if (bx < 24) {
                    *(float2*)(ktmp + (size_t)rowg * (NKV * HD) + coll) = v;
                } else {
                    int kv = coll >> 7, d = coll & 127;
                    *(float2*)(newV + (size_t)kv * (Q * HD) + (size_t)rowg * HD + d) = v;
                    size_t de = (size_t)kv * (KVLEN * HD) + (size_t)(PAST + rowg) * HD + d;
                    *(uint32_t*)(vph + de) = cvt2h(v.x, v.y);
                }
            }
        }
    }
}

// ---------------- output projection GEMM (single x single) ----------------
__global__ __launch_bounds__(256) void hgemm_o(
    const h16* __restrict__ Ah, const h16* __restrict__ Bh,
    float* __restrict__ C)
{
    extern __shared__ char hsm[];
    const int tid = threadIdx.x;
    const int lane = tid & 31;
    const int wid = tid >> 5;
    const int wm = wid >> 2;
    const int wn = wid & 3;
    const uint32_t base_u = smem_u32(hsm);
    const int K = NH * HD, N = NH * HD;

    const h16* pl[2] = {
        Ah + (size_t)(blockIdx.y * 128) * K,
        Bh + (size_t)(blockIdx.x * 128) * K };

    const int rowselA = lane & 15;
    const int halfA = lane >> 4;
    const int rowselB = (lane & 7) + (lane >> 4) * 8;
    const int halfB = (lane >> 3) & 1;
    const uint32_t aoff0 = (uint32_t)((wm * 64 + rowselA) * ROWB + halfA * 16);
    const uint32_t boff0 = (uint32_t)((wn * 32 + rowselB) * ROWB + halfB * 16);

    float acc[4][4][4];
#pragma unroll
    for (int i = 0; i < 4; i++)
#pragma unroll
        for (int j = 0; j < 4; j++)
#pragma unroll
            for (int r = 0; r < 4; r++) acc[i][j][r] = 0.0f;

    const int nst = K / 32;
    {
        uint32_t dstb = base_u;
        for (int i = tid; i < 1024; i += 256) {
            int p = i >> 9, row = (i >> 2) & 127, seg = i & 3;
            cp16(dstb + p * PLANEB + row * ROWB + seg * 16,
                 pl[p] + (size_t)row * K + seg * 8);
        }
        cpcommit();
    }

    for (int s = 0; s < nst; s++) {
        cpwait<0>();
        __syncthreads();
        if (s + 1 < nst) {
            int kt = (s + 1) * 32;
            uint32_t dstb = base_u + ((s + 1) & 1) * STAGEB2;
            for (int i = tid; i < 1024; i += 256) {
                int p = i >> 9, row = (i >> 2) & 127, seg = i & 3;
                cp16(dstb + p * PLANEB + row * ROWB + seg * 16,
                     pl[p] + (size_t)row * K + kt + seg * 8);
            }
            cpcommit();
        }
        const uint32_t sb = base_u + (s & 1) * STAGEB2;
#pragma unroll
        for (int kc = 0; kc < 2; kc++) {
            uint32_t ah[4][4];
#pragma unroll
            for (int mi = 0; mi < 4; mi++)
                ldsm4(ah[mi], sb + aoff0 + mi * (16 * ROWB) + kc * 32);
            uint32_t bh[4][2];
#pragma unroll
            for (int p = 0; p < 2; p++) {
                uint32_t r[4];
                ldsm4(r, sb + PLANEB + boff0 + p * (16 * ROWB) + kc * 32);
                bh[2 * p][0] = r[0]; bh[2 * p][1] = r[1];
                bh[2 * p + 1][0] = r[2]; bh[2 * p + 1][1] = r[3];
            }
#pragma unroll
            for (int mi = 0; mi < 4; mi++)
#pragma unroll
                for (int nj = 0; nj < 4; nj++)
                    mma_f16(acc[mi][nj], ah[mi], bh[nj]);
        }
    }

    const int rfrag = lane >> 2;
    const int cpair = (lane & 3) * 2;
#pragma unroll
    for (int mi = 0; mi < 4; mi++) {
#pragma unroll
        for (int nj = 0; nj < 4; nj++) {
            int colg = blockIdx.x * 128 + wn * 32 + nj * 8 + cpair;
#pragma unroll
            for (int half = 0; half < 2; half++) {
                int rowg = blockIdx.y * 128 + wm * 64 + mi * 16 + rfrag + half * 8;
                *(float2*)(C + (size_t)rowg * N + colg) =
                    make_float2(acc[mi][nj][2 * half], acc[mi][nj][2 * half + 1]);
            }
        }
    }
}

// ---------------- RMSNorm + RoPE: warp-per-row, shuffle-only ----------------
// grid = 49152/8 blocks, 256 threads (8 warps, 1 row each)
__global__ __launch_bounds__(256) void norm_rope(
    const float* __restrict__ qtmp, const float* __restrict__ ktmp,
    const float* __restrict__ cosb, const float* __restrict__ sinb,
    const float* __restrict__ qw, const float* __restrict__ kw,
    h16* __restrict__ qh, float* __restrict__ newK, h16* __restrict__ kh)
{
    const float QSC = 0.08838834764831845f * 1.44269504088896341f;
    int gr = blockIdx.x * 8 + (threadIdx.x >> 5);
    int lane = threadIdx.x & 31;
    int s = gr & (Q - 1);
    int hh = gr >> 11;           // 0..23

    const float* src;
    const float* w;
    if (hh < NH) {
        src = qtmp + (size_t)s * (NH * HD) + hh * HD;
        w = qw;
    } else {
        src = ktmp + (size_t)s * (NKV * HD) + (hh - NH) * HD;
        w = kw;
    }

    float4 x = ((const float4*)src)[lane];
    float v = x.x * x.x + x.y * x.y + x.z * x.z + x.w * x.w;
#pragma unroll
    for (int o = 16; o; o >>= 1) v += __shfl_xor_sync(0xffffffffu, v, o);
    float rs = rsqrtf(v * (1.0f / HD) + KEPS);

    float4 w4 = ((const float4*)w)[lane];
    float4 xn = make_float4(x.x * rs * w4.x, x.y * rs * w4.y,
                            x.z * rs * w4.z, x.w * rs * w4.w);

    // RoPE partner: lane l <-> lane l^16 (elements +/-64)
    float4 pr;
    pr.x = __shfl_xor_sync(0xffffffffu, xn.x, 16);
    pr.y = __shfl_xor_sync(0xffffffffu, xn.y, 16);
    pr.z = __shfl_xor_sync(0xffffffffu, xn.z, 16);
    pr.w = __shfl_xor_sync(0xffffffffu, xn.w, 16);
    float sgn = (lane < 16) ? -1.0f : 1.0f;

    float4 c4 = ((const float4*)(cosb + (size_t)s * HD))[lane];
    float4 s4 = ((const float4*)(sinb + (size_t)s * HD))[lane];
    float4 val = make_float4(xn.x * c4.x + sgn * pr.x * s4.x,
                             xn.y * c4.y + sgn * pr.y * s4.y,
                             xn.z * c4.z + sgn * pr.z * s4.z,
                             xn.w * c4.w + sgn * pr.w * s4.w);

    if (hh < NH) {
        uint2 o;
        o.x = cvt2h(val.x * QSC, val.y * QSC);
        o.y = cvt2h(val.z * QSC, val.w * QSC);
        *(uint2*)(qh + ((size_t)hh * Q + s) * HD + lane * 4) = o;
    } else {
        int kv = hh - NH;
        ((float4*)(newK + ((size_t)kv * Q + s) * HD))[lane] = val;
        uint2 o;
        o.x = cvt2h(val.x, val.y);
        o.y = cvt2h(val.z, val.w);
        *(uint2*)(kh + ((size_t)kv * KVLEN + PAST + s) * HD + lane * 4) = o;
    }
}

// ---------------- Flash attention: TQ=64, 128 threads, 2 CTAs/SM ----------------
#define AT_TQ 64
#define AT_TK 64
#define KVROW 272
#define KVPLANE (64 * KVROW)
#define TILEBUF (2 * KVPLANE)
#define AT_SMEM (2 * TILEBUF)

__global__ __launch_bounds__(128, 2) void attn_mma(
    const h16* __restrict__ qh,
    const h16* __restrict__ kch, const h16* __restrict__ vch,
    h16* __restrict__ aoh)
{
    extern __shared__ char asmem[];
    const int h = blockIdx.x;
    const int q0 = ((int)gridDim.y - 1 - (int)blockIdx.y) * AT_TQ;  // largest-first
    const int kvh = h >> 1;
    const int tid = threadIdx.x;
    const int lane = tid & 31;
    const int wid = tid >> 5;
    const uint32_t sb = smem_u32(asmem);

    {
        const h16* qsrc = qh + ((size_t)h * Q + q0) * HD;
        for (int i = tid; i < 1024; i += 128) {
            int row = i >> 4, seg = i & 15;
            cp16(sb + row * KVROW + seg * 16, qsrc + (size_t)row * HD + seg * 8);
        }
        cpcommit();
        cpwait<0>();
        __syncthreads();
    }
    uint32_t aQh[8][4];
    {
        uint32_t a0 = sb + (wid * 16 + (lane & 15)) * KVROW + (lane >> 4) * 16;
#pragma unroll
        for (int kc = 0; kc < 8; kc++)
            ldsm4(aQh[kc], a0 + kc * 32);
    }
    __syncthreads();

    float oacc[16][4];
#pragma unroll
    for (int f = 0; f < 16; f++)
#pragma unroll
        for (int r = 0; r < 4; r++) oacc[f][r] = 0.0f;
    float m0 = -1e30f, m1 = -1e30f, l0 = 0.0f, l1 = 0.0f;

    const int nt = (PAST + q0 + AT_TQ) / AT_TK;
    const h16* ksrc = kch + (size_t)kvh * KVLEN * HD;
    const h16* vsrc = vch + (size_t)kvh * KVLEN * HD;

    {
        for (int i = tid; i < 2048; i += 128) {
            int p = i >> 10, row = (i >> 4) & 63, seg = i & 15;
            const h16* s0 = p ? vsrc : ksrc;
            cp16(sb + p * KVPLANE + row * KVROW + seg * 16,
                 s0 + (size_t)row * HD + seg * 8);
        }
        cpcommit();
    }

    const int rowselB = (lane & 7) + (lane >> 4) * 8;
    const int halfB = (lane >> 3) & 1;
    const int rowV = lane & 15;
    const int halfV = (lane >> 4) * 16;

    for (int t = 0; t < nt; t++) {
        __syncthreads();
        if (t + 1 < nt) {
            int j1 = (t + 1) * AT_TK;
            uint32_t db = sb + ((t + 1) & 1) * TILEBUF;
            for (int i = tid; i < 2048; i += 128) {
                int p = i >> 10, row = (i >> 4) & 63, seg = i & 15;
                const h16* s0 = p ? vsrc : ksrc;
                cp16(db + p * KVPLANE + row * KVROW + seg * 16,
                     s0 + (size_t)(j1 + row) * HD + seg * 8);
            }
            cpcommit();
            cpwait<1>();
        } else {
            cpwait<0>();
        }
        __syncthreads();

        const uint32_t kb = sb + (t & 1) * TILEBUF;
        const int j0 = t * AT_TK;

        float sacc[8][4];
#pragma unroll
        for (int j = 0; j < 8; j++)
#pragma unroll
            for (int r = 0; r < 4; r++) sacc[j][r] = 0.0f;
#pragma unroll
        for (int kc = 0; kc < 8; kc++) {
#pragma unroll
            for (int nj = 0; nj < 4; nj++) {
                uint32_t kh[4];
                ldsm4(kh, kb + (nj * 16 + rowselB) * KVROW + halfB * 16 + kc * 32);
                mma_f16(sacc[2 * nj],     aQh[kc], kh);
                mma_f16(sacc[2 * nj + 1], aQh[kc], kh + 2);
            }
        }

        if (j0 + AT_TK - 1 > PAST + q0 + wid * 16) {
            int r0g = PAST + q0 + wid * 16 + (lane >> 2);
#pragma unroll
            for (int j = 0; j < 8; j++) {
                int cg = j0 + j * 8 + (lane & 3) * 2;
                if (cg > r0g)     sacc[j][0] = -1e30f;
                if (cg + 1 > r0g) sacc[j][1] = -1e30f;
                if (cg > r0g + 8)     sacc[j][2] = -1e30f;
                if (cg + 1 > r0g + 8) sacc[j][3] = -1e30f;
            }
        }

        float t0 = -1e30f, t1 = -1e30f;
#pragma unroll
        for (int j = 0; j < 8; j++) {
            t0 = fmaxf(t0, fmaxf(sacc[j][0], sacc[j][1]));
            t1 = fmaxf(t1, fmaxf(sacc[j][2], sacc[j][3]));
        }
        t0 = fmaxf(t0, __shfl_xor_sync(0xffffffffu, t0, 1));
        t0 = fmaxf(t0, __shfl_xor_sync(0xffffffffu, t0, 2));
        t1 = fmaxf(t1, __shfl_xor_sync(0xffffffffu, t1, 1));
        t1 = fmaxf(t1, __shfl_xor_sync(0xffffffffu, t1, 2));
        float mn0 = fmaxf(m0, t0), mn1 = fmaxf(m1, t1);
        float c0 = ex2(m0 - mn0), c1 = ex2(m1 - mn1);
        m0 = mn0; m1 = mn1;
        float ps0 = 0.0f, ps1 = 0.0f;
#pragma unroll
        for (int j = 0; j < 8; j++) {
            sacc[j][0] = ex2(sacc[j][0] - mn0); ps0 += sacc[j][0];
            sacc[j][1] = ex2(sacc[j][1] - mn0); ps0 += sacc[j][1];
            sacc[j][2] = ex2(sacc[j][2] - mn1); ps1 += sacc[j][2];
            sacc[j][3] = ex2(sacc[j][3] - mn1); ps1 += sacc[j][3];
        }
        ps0 += __shfl_xor_sync(0xffffffffu, ps0, 1);
        ps0 += __shfl_xor_sync(0xffffffffu, ps0, 2);
        ps1 += __shfl_xor_sync(0xffffffffu, ps1, 1);
        ps1 += __shfl_xor_sync(0xffffffffu, ps1, 2);
        l0 = l0 * c0 + ps0;
        l1 = l1 * c1 + ps1;
#pragma unroll
        for (int f = 0; f < 16; f++) {
            oacc[f][0] *= c0; oacc[f][1] *= c0;
            oacc[f][2] *= c1; oacc[f][3] *= c1;
        }

        uint32_t pP[4][4];
#pragma unroll
        for (int kc = 0; kc < 4; kc++) {
            pP[kc][0] = cvt2h(sacc[2 * kc][0],     sacc[2 * kc][1]);
            pP[kc][1] = cvt2h(sacc[2 * kc][2],     sacc[2 * kc][3]);
            pP[kc][2] = cvt2h(sacc[2 * kc + 1][0], sacc[2 * kc + 1][1]);
            pP[kc][3] = cvt2h(sacc[2 * kc + 1][2], sacc[2 * kc + 1][3]);
        }

        const uint32_t vb = kb + KVPLANE;
#pragma unroll
        for (int kc = 0; kc < 4; kc++) {
#pragma unroll
            for (int dj = 0; dj < 8; dj++) {
                uint32_t vh[4];
                ldsm4t(vh, vb + (kc * 16 + rowV) * KVROW + dj * 32 + halfV);
                mma_f16(oacc[2 * dj],     pP[kc], vh);
                mma_f16(oacc[2 * dj + 1], pP[kc], vh + 2);
            }
        }
    }

    float inv0 = 1.0f / l0, inv1 = 1.0f / l1;
    int r0 = q0 + wid * 16 + (lane >> 2);
#pragma unroll
    for (int f = 0; f < 16; f++) {
        int d = f * 8 + (lane & 3) * 2;
        size_t e0 = (size_t)r0 * (NH * HD) + h * HD + d;
        size_t e1 = e0 + (size_t)8 * (NH * HD);
        *(uint32_t*)(aoh + e0) = cvt2h(oacc[f][0] * inv0, oacc[f][1] * inv0);
        *(uint32_t*)(aoh + e1) = cvt2h(oacc[f][2] * inv1, oacc[f][3] * inv1);
    }
}

// ---------------- launch ----------------
extern "C" void kernel_launch(void* const* d_in, const int* in_sizes, int n_in,
                              void* d_out, int out_size)
{
    const float* hs    = (const float*)d_in[0];
    const float* cosb  = (const float*)d_in[1];
    const float* sinb  = (const float*)d_in[2];
    const float* pastK = (const float*)d_in[4];
    const float* pastV = (const float*)d_in[5];
    const float* Wq    = (const float*)d_in[6];
    const float* Wk    = (const float*)d_in[7];
    const float* Wv    = (const float*)d_in[8];
    const float* Wo    = (const float*)d_in[9];
    const float* qw    = (const float*)d_in[10];
    const float* kw    = (const float*)d_in[11];

    float* out  = (float*)d_out;
    float* newK = out + (size_t)Q * NH * HD;
    float* newV = newK + (size_t)NKV * Q * HD;

    float *qtmp, *ktmp;
    h16 *hsh, *wqh, *wkh, *wvh, *woh;
    h16 *qph, *kph, *vph, *aoh;
    cudaGetSymbolAddress((void**)&qtmp, g_qtmp);
    cudaGetSymbolAddress((void**)&ktmp, g_ktmp);
    cudaGetSymbolAddress((void**)&hsh, g_hs_h);
    cudaGetSymbolAddress((void**)&wqh, g_wq_h);
    cudaGetSymbolAddress((void**)&wkh, g_wk_h);
    cudaGetSymbolAddress((void**)&wvh, g_wv_h);
    cudaGetSymbolAddress((void**)&woh, g_wo_h);
    cudaGetSymbolAddress((void**)&qph, g_q_h);
    cudaGetSymbolAddress((void**)&kph, g_k_h);
    cudaGetSymbolAddress((void**)&vph, g_v_h);
    cudaGetSymbolAddress((void**)&aoh, g_ao_h);

    cudaFuncSetAttribute(hgemm_qkv, cudaFuncAttributeMaxDynamicSharedMemorySize, HO_SMEM);
    cudaFuncSetAttribute(hgemm_o, cudaFuncAttributeMaxDynamicSharedMemorySize, HO_SMEM);
    cudaFuncSetAttribute(attn_mma, cudaFuncAttributeMaxDynamicSharedMemorySize, AT_SMEM);

    // merged convert (4 virtual blocks per real block)
    kconv_all<<<5120, 256>>>(hs, hsh, Wq, wqh, Wk, wkh, Wv, wvh, Wo, woh,
                             pastK, kph, pastV, vph);

    // fused QKV projection (all single-plane)
    hgemm_qkv<<<dim3(32, Q / 128), 256, HO_SMEM>>>(
        hsh, wqh, wkh, wvh, qtmp, ktmp, newV, vph);

    // rmsnorm + rope (warp-per-row)
    norm_rope<<<(Q * (NH + NKV)) / 8, 256>>>(qtmp, ktmp, cosb, sinb, qw, kw,
                                             qph, newK, kph);

    // attention (TQ=64, 2 CTAs/SM)
    attn_mma<<<dim3(NH, Q / AT_TQ), 128, AT_SMEM>>>(qph, kph, vph, aoh);

    // output projection
    hgemm_o<<<dim3(NH * HD / 128, Q / 128), 256, HO_SMEM>>>(aoh, woh, out);
}

// round 14
// speedup vs baseline: 14.5361x; 1.0156x over previous
#include <cuda_runtime.h>
#include <cuda_fp16.h>
#include <cstdint>

#define Q    2048
#define H    2048
#define NH   16
#define NKV  8
#define HD   128
#define PAST 2048
#define KVLEN (PAST + Q)
#define KEPS 1e-6f

typedef __half h16;

// ---------------- scratch (no allocation allowed) ----------------
__device__ h16 g_hs_h[Q * H];
__device__ h16 g_wq_h[NH * HD * H];
__device__ h16 g_wk_h[NKV * HD * H];
__device__ h16 g_wv_h[NKV * HD * H];
__device__ h16 g_wo_h[NH * HD * NH * HD];
__device__ h16 g_q_h[NH * Q * HD];
__device__ h16 g_k_h[NKV * KVLEN * HD];
__device__ h16 g_v_h[NKV * KVLEN * HD];
__device__ h16 g_ao_h[Q * NH * HD];

// ---------------- helpers ----------------
__device__ __forceinline__ uint32_t smem_u32(const void* p) {
    uint32_t a;
    asm("{ .reg .u64 t; cvta.to.shared.u64 t, %1; cvt.u32.u64 %0, t; }" : "=r"(a) : "l"(p));
    return a;
}
__device__ __forceinline__ uint32_t packh(h16 a, h16 b) {
    return (uint32_t)__half_as_ushort(a) | ((uint32_t)__half_as_ushort(b) << 16);
}
__device__ __forceinline__ uint32_t cvt2h(float a, float b) {
    return packh(__float2half_rn(a), __float2half_rn(b));
}
__device__ __forceinline__ void ldsm4(uint32_t* r, uint32_t addr) {
    asm volatile("ldmatrix.sync.aligned.m8n8.x4.shared.b16 {%0,%1,%2,%3}, [%4];"
                 : "=r"(r[0]), "=r"(r[1]), "=r"(r[2]), "=r"(r[3]) : "r"(addr));
}
__device__ __forceinline__ void ldsm4t(uint32_t* r, uint32_t addr) {
    asm volatile("ldmatrix.sync.aligned.m8n8.x4.trans.shared.b16 {%0,%1,%2,%3}, [%4];"
                 : "=r"(r[0]), "=r"(r[1]), "=r"(r[2]), "=r"(r[3]) : "r"(addr));
}
__device__ __forceinline__ void mma_f16(float* c, const uint32_t* a, const uint32_t* b) {
    asm volatile(
        "mma.sync.aligned.m16n8k16.row.col.f32.f16.f16.f32 "
        "{%0,%1,%2,%3}, {%4,%5,%6,%7}, {%8,%9}, {%0,%1,%2,%3};"
        : "+f"(c[0]), "+f"(c[1]), "+f"(c[2]), "+f"(c[3])
        : "r"(a[0]), "r"(a[1]), "r"(a[2]), "r"(a[3]), "r"(b[0]), "r"(b[1]));
}
__device__ __forceinline__ void cp16(uint32_t dst, const void* src) {
    asm volatile("cp.async.cg.shared.global [%0], [%1], 16;"
                 :: "r"(dst), "l"(__cvta_generic_to_global(src)));
}
__device__ __forceinline__ void cpcommit() { asm volatile("cp.async.commit_group;"); }
template <int N>
__device__ __forceinline__ void cpwait() {
    asm volatile("cp.async.wait_group %0;" :: "n"(N));
}
__device__ __forceinline__ float ex2(float x) {
    float y;
    asm("ex2.approx.f32 %0, %1;" : "=f"(y) : "f"(x));
    return y;
}

// ---------------- merged convert kernel (8 float4 / thread, all single-plane) ----------------
__device__ __forceinline__ void kconv_body(
    int b, int tid,
    const float* hs, h16* hsh, const float* wq, h16* wqh,
    const float* wk, h16* wkh, const float* wv, h16* wvh,
    const float* wo, h16* woh,
    const float* pk, h16* kch, const float* pv, h16* vch)
{
    if (b >= 16384) {   // caches (strided dst)
        b -= 16384;
        const float* x;
        h16* dst;
        if (b < 2048) { x = pk; dst = kch; }
        else          { x = pv; dst = vch; b -= 2048; }
        int i = b * 256 + tid;
        int e = i * 4;
        int kv = e / (PAST * HD);
        int rem = e - kv * (PAST * HD);
        size_t de = (size_t)kv * (KVLEN * HD) + rem;
        float4 v = ((const float4*)x)[i];
        *(uint32_t*)(dst + de)     = cvt2h(v.x, v.y);
        *(uint32_t*)(dst + de + 2) = cvt2h(v.z, v.w);
        return;
    }
    const float* src;
    h16* dst;
    int base;
    if (b < 4096)       { src = hs; dst = hsh; base = 0; }
    else if (b < 8192)  { src = wq; dst = wqh; base = 4096; }
    else if (b < 10240) { src = wk; dst = wkh; base = 8192; }
    else if (b < 12288) { src = wv; dst = wvh; base = 10240; }
    else                { src = wo; dst = woh; base = 12288; }
    int i = (b - base) * 256 + tid;
    float4 v = ((const float4*)src)[i];
    ((uint32_t*)dst)[2 * i]     = cvt2h(v.x, v.y);
    ((uint32_t*)dst)[2 * i + 1] = cvt2h(v.z, v.w);
}

__global__ __launch_bounds__(256) void kconv_all(
    const float* __restrict__ hs, h16* __restrict__ hsh,
    const float* __restrict__ wq, h16* __restrict__ wqh,
    const float* __restrict__ wk, h16* __restrict__ wkh,
    const float* __restrict__ wv, h16* __restrict__ wvh,
    const float* __restrict__ wo, h16* __restrict__ woh,
    const float* __restrict__ pk, h16* __restrict__ kch,
    const float* __restrict__ pv, h16* __restrict__ vch)
{
#pragma unroll
    for (int j = 0; j < 8; j++) {
        kconv_body(blockIdx.x * 8 + j, threadIdx.x,
                   hs, hsh, wq, wqh, wk, wkh, wv, wvh, wo, woh,
                   pk, kch, pv, vch);
    }
}

// ---------------- GEMM constants ----------------
#define ROWB   80
#define PLANEB 10240
#define STAGEB2 20480                 // 2 planes (A, B)
#define HO_SMEM (2 * STAGEB2)         // 40960
#define QKV_SMEM (2048 + 128 * 132 * 4)   // red + xs = 69632 (> 2*STAGEB2)

// ---------------- fused QKV projection GEMM + RMSNorm + RoPE epilogue ----------------
// grid (32, 16): bx<16 -> Q head bx, <24 -> K head bx-16, else V head bx-24
__global__ __launch_bounds__(256) void hgemm_qkv(
    const h16* __restrict__ hsh,
    const h16* __restrict__ wqh, const h16* __restrict__ wkh,
    const h16* __restrict__ wvh,
    const float* __restrict__ cosb, const float* __restrict__ sinb,
    const float* __restrict__ qw, const float* __restrict__ kw,
    h16* __restrict__ qh, h16* __restrict__ kh, float* __restrict__ newK,
    float* __restrict__ newV, h16* __restrict__ vph)
{
    extern __shared__ char hsm[];
    const int bx = blockIdx.x;
    const int tid = threadIdx.x;
    const int lane = tid & 31;
    const int wid = tid >> 5;
    const int wm = wid >> 2;
    const int wn = wid & 3;
    const uint32_t base_u = smem_u32(hsm);
    const int K = H;

    const h16* Bh;
    int colb;
    if (bx < 16)      { Bh = wqh; colb = bx * 128; }
    else if (bx < 24) { Bh = wkh; colb = (bx - 16) * 128; }
    else              { Bh = wvh; colb = (bx - 24) * 128; }

    const h16* pl[2] = {
        hsh + (size_t)(blockIdx.y * 128) * K,
        Bh + (size_t)colb * K };

    const int rowselA = lane & 15;
    const int halfA = lane >> 4;
    const int rowselB = (lane & 7) + (lane >> 4) * 8;
    const int halfB = (lane >> 3) & 1;
    const uint32_t aoff0 = (uint32_t)((wm * 64 + rowselA) * ROWB + halfA * 16);
    const uint32_t boff0 = (uint32_t)((wn * 32 + rowselB) * ROWB + halfB * 16);

    float acc[4][4][4];
#pragma unroll
    for (int i = 0; i < 4; i++)
#pragma unroll
        for (int j = 0; j < 4; j++)
#pragma unroll
            for (int r = 0; r < 4; r++) acc[i][j][r] = 0.0f;

    const int nst = K / 32;
    {
        uint32_t dstb = base_u;
        for (int i = tid; i < 1024; i += 256) {
            int p = i >> 9, row = (i >> 2) & 127, seg = i & 3;
            cp16(dstb + p * PLANEB + row * ROWB + seg * 16,
                 pl[p] + (size_t)row * K + seg * 8);
        }
        cpcommit();
    }

    for (int s = 0; s < nst; s++) {
        cpwait<0>();
        __syncthreads();
        if (s + 1 < nst) {
            int kt = (s + 1) * 32;
            uint32_t dstb = base_u + ((s + 1) & 1) * STAGEB2;
            for (int i = tid; i < 1024; i += 256) {
                int p = i >> 9, row = (i >> 2) & 127, seg = i & 3;
                cp16(dstb + p * PLANEB + row * ROWB + seg * 16,
                     pl[p] + (size_t)row * K + kt + seg * 8);
            }
            cpcommit();
        }
        const uint32_t sb = base_u + (s & 1) * STAGEB2;
#pragma unroll
        for (int kc = 0; kc < 2; kc++) {
            uint32_t ah[4][4];
#pragma unroll
            for (int mi = 0; mi < 4; mi++)
                ldsm4(ah[mi], sb + aoff0 + mi * (16 * ROWB) + kc * 32);
            uint32_t bh[4][2];
#pragma unroll
            for (int p = 0; p < 2; p++) {
                uint32_t r[4];
                ldsm4(r, sb + PLANEB + boff0 + p * (16 * ROWB) + kc * 32);
                bh[2 * p][0] = r[0]; bh[2 * p][1] = r[1];
                bh[2 * p + 1][0] = r[2]; bh[2 * p + 1][1] = r[3];
            }
#pragma unroll
            for (int mi = 0; mi < 4; mi++)
#pragma unroll
                for (int nj = 0; nj < 4; nj++)
                    mma_f16(acc[mi][nj], ah[mi], bh[nj]);
        }
    }

    const int rfrag = lane >> 2;
    const int cpair = (lane & 3) * 2;

    if (bx < 24) {
        // ---- fused RMSNorm + RoPE epilogue (one head per CTA col-block) ----
        __syncthreads();   // done with stage buffers; reuse smem
        float* red = (float*)hsm;               // [128][4] = 2048 B
        float* xs  = (float*)(hsm + 2048);      // [128] rows, stride 132 floats
        const float* w = (bx < 16) ? qw : kw;

        // phase 1: per-row partial sum of squares (reduce over lane&3)
#pragma unroll
        for (int mi = 0; mi < 4; mi++) {
#pragma unroll
            for (int half = 0; half < 2; half++) {
                float sq = 0.0f;
#pragma unroll
                for (int nj = 0; nj < 4; nj++) {
                    float a0 = acc[mi][nj][2 * half], a1 = acc[mi][nj][2 * half + 1];
                    sq += a0 * a0 + a1 * a1;
                }
                sq += __shfl_xor_sync(0xffffffffu, sq, 1);
                sq += __shfl_xor_sync(0xffffffffu, sq, 2);
                if ((lane & 3) == 0) {
                    int rloc = wm * 64 + mi * 16 + half * 8 + rfrag;
                    red[rloc * 4 + wn] = sq;
                }
            }
        }
        __syncthreads();

        // phase 2/3: normalize + weight, stash to xs for the RoPE partner exchange
#pragma unroll
        for (int mi = 0; mi < 4; mi++) {
#pragma unroll
            for (int half = 0; half < 2; half++) {
                int rloc = wm * 64 + mi * 16 + half * 8 + rfrag;
                float sum = red[rloc * 4 + 0] + red[rloc * 4 + 1]
                          + red[rloc * 4 + 2] + red[rloc * 4 + 3];
                float rs = rsqrtf(sum * (1.0f / HD) + KEPS);
#pragma unroll
                for (int nj = 0; nj < 4; nj++) {
                    int d = wn * 32 + nj * 8 + cpair;
                    float v0 = acc[mi][nj][2 * half]     * rs * w[d];
                    float v1 = acc[mi][nj][2 * half + 1] * rs * w[d + 1];
                    acc[mi][nj][2 * half]     = v0;
                    acc[mi][nj][2 * half + 1] = v1;
                    xs[rloc * 132 + d]     = v0;
                    xs[rloc * 132 + d + 1] = v1;
                }
            }
        }
        __syncthreads();

        // phase 4: RoPE + write
        const float QSC = 0.08838834764831845f * 1.44269504088896341f;
#pragma unroll
        for (int mi = 0; mi < 4; mi++) {
#pragma unroll
            for (int half = 0; half < 2; half++) {
                int rloc = wm * 64 + mi * 16 + half * 8 + rfrag;
                int srow = blockIdx.y * 128 + rloc;
#pragma unroll
                for (int nj = 0; nj < 4; nj++) {
                    int d = wn * 32 + nj * 8 + cpair;
                    float2 cc = *(const float2*)(cosb + (size_t)srow * HD + d);
                    float2 ss = *(const float2*)(sinb + (size_t)srow * HD + d);
                    float p0 = xs[rloc * 132 + (d ^ 64)];
                    float p1 = xs[rloc * 132 + ((d ^ 64) + 1)];
                    float sgn = (d < 64) ? -1.0f : 1.0f;
                    float o0 = acc[mi][nj][2 * half]     * cc.x + sgn * p0 * ss.x;
                    float o1 = acc[mi][nj][2 * half + 1] * cc.y + sgn * p1 * ss.y;
                    if (bx < 16) {
                        *(uint32_t*)(qh + ((size_t)bx * Q + srow) * HD + d) =
                            cvt2h(o0 * QSC, o1 * QSC);
                    } else {
                        int kv = bx - 16;
                        *(float2*)(newK + ((size_t)kv * Q + srow) * HD + d) =
                            make_float2(o0, o1);
                        *(uint32_t*)(kh + ((size_t)kv * KVLEN + PAST + srow) * HD + d) =
                            cvt2h(o0, o1);
                    }
                }
            }
        }
    } else {
        // ---- V epilogue ----
#pragma unroll
        for (int mi = 0; mi < 4; mi++) {
#pragma unroll
            for (int nj = 0; nj < 4; nj++) {
                int d = wn * 32 + nj * 8 + cpair;
#pragma unroll
                for (int half = 0; half < 2; half++) {
                    int rowg = blockIdx.y * 128 + wm * 64 + mi * 16 + rfrag + half * 8;
                    float2 v = make_float2(acc[mi][nj][2 * half], acc[mi][nj][2 * half + 1]);
                    int kv = bx - 24;
                    *(float2*)(newV + (size_t)kv * (Q * HD) + (size_t)rowg * HD + d) = v;
                    size_t de = (size_t)kv * (KVLEN * HD) + (size_t)(PAST + rowg) * HD + d;
                    *(uint32_t*)(vph + de) = cvt2h(v.x, v.y);
                }
            }
        }
    }
}

// ---------------- output projection GEMM (single x single) ----------------
__global__ __launch_bounds__(256) void hgemm_o(
    const h16* __restrict__ Ah, const h16* __restrict__ Bh,
    float* __restrict__ C)
{
    extern __shared__ char hsm[];
    const int tid = threadIdx.x;
    const int lane = tid & 31;
    const int wid = tid >> 5;
    const int wm = wid >> 2;
    const int wn = wid & 3;
    const uint32_t base_u = smem_u32(hsm);
    const int K = NH * HD, N = NH * HD;

    const h16* pl[2] = {
        Ah + (size_t)(blockIdx.y * 128) * K,
        Bh + (size_t)(blockIdx.x * 128) * K };

    const int rowselA = lane & 15;
    const int halfA = lane >> 4;
    const int rowselB = (lane & 7) + (lane >> 4) * 8;
    const int halfB = (lane >> 3) & 1;
    const uint32_t aoff0 = (uint32_t)((wm * 64 + rowselA) * ROWB + halfA * 16);
    const uint32_t boff0 = (uint32_t)((wn * 32 + rowselB) * ROWB + halfB * 16);

    float acc[4][4][4];
#pragma unroll
    for (int i = 0; i < 4; i++)
#pragma unroll
        for (int j = 0; j < 4; j++)
#pragma unroll
            for (int r = 0; r < 4; r++) acc[i][j][r] = 0.0f;

    const int nst = K / 32;
    {
        uint32_t dstb = base_u;
        for (int i = tid; i < 1024; i += 256) {
            int p = i >> 9, row = (i >> 2) & 127, seg = i & 3;
            cp16(dstb + p * PLANEB + row * ROWB + seg * 16,
                 pl[p] + (size_t)row * K + seg * 8);
        }
        cpcommit();
    }

    for (int s = 0; s < nst; s++) {
        cpwait<0>();
        __syncthreads();
        if (s + 1 < nst) {
            int kt = (s + 1) * 32;
            uint32_t dstb = base_u + ((s + 1) & 1) * STAGEB2;
            for (int i = tid; i < 1024; i += 256) {
                int p = i >> 9, row = (i >> 2) & 127, seg = i & 3;
                cp16(dstb + p * PLANEB + row * ROWB + seg * 16,
                     pl[p] + (size_t)row * K + kt + seg * 8);
            }
            cpcommit();
        }
        const uint32_t sb = base_u + (s & 1) * STAGEB2;
#pragma unroll
        for (int kc = 0; kc < 2; kc++) {
            uint32_t ah[4][4];
#pragma unroll
            for (int mi = 0; mi < 4; mi++)
                ldsm4(ah[mi], sb + aoff0 + mi * (16 * ROWB) + kc * 32);
            uint32_t bh[4][2];
#pragma unroll
            for (int p = 0; p < 2; p++) {
                uint32_t r[4];
                ldsm4(r, sb + PLANEB + boff0 + p * (16 * ROWB) + kc * 32);
                bh[2 * p][0] = r[0]; bh[2 * p][1] = r[1];
                bh[2 * p + 1][0] = r[2]; bh[2 * p + 1][1] = r[3];
            }
#pragma unroll
            for (int mi = 0; mi < 4; mi++)
#pragma unroll
                for (int nj = 0; nj < 4; nj++)
                    mma_f16(acc[mi][nj], ah[mi], bh[nj]);
        }
    }

    const int rfrag = lane >> 2;
    const int cpair = (lane & 3) * 2;
#pragma unroll
    for (int mi = 0; mi < 4; mi++) {
#pragma unroll
        for (int nj = 0; nj < 4; nj++) {
            int colg = blockIdx.x * 128 + wn * 32 + nj * 8 + cpair;
#pragma unroll
            for (int half = 0; half < 2; half++) {
                int rowg = blockIdx.y * 128 + wm * 64 + mi * 16 + rfrag + half * 8;
                *(float2*)(C + (size_t)rowg * N + colg) =
                    make_float2(acc[mi][nj][2 * half], acc[mi][nj][2 * half + 1]);
            }
        }
    }
}

// ---------------- Flash attention: TQ=64, 128 threads, 2 CTAs/SM ----------------
#define AT_TQ 64
#define AT_TK 64
#define KVROW 272
#define KVPLANE (64 * KVROW)
#define TILEBUF (2 * KVPLANE)
#define AT_SMEM (2 * TILEBUF)

__global__ __launch_bounds__(128, 2) void attn_mma(
    const h16* __restrict__ qh,
    const h16* __restrict__ kch, const h16* __restrict__ vch,
    h16* __restrict__ aoh)
{
    extern __shared__ char asmem[];
    const int h = blockIdx.x;
    const int q0 = ((int)gridDim.y - 1 - (int)blockIdx.y) * AT_TQ;  // largest-first
    const int kvh = h >> 1;
    const int tid = threadIdx.x;
    const int lane = tid & 31;
    const int wid = tid >> 5;
    const uint32_t sb = smem_u32(asmem);

    {
        const h16* qsrc = qh + ((size_t)h * Q + q0) * HD;
        for (int i = tid; i < 1024; i += 128) {
            int row = i >> 4, seg = i & 15;
            cp16(sb + row * KVROW + seg * 16, qsrc + (size_t)row * HD + seg * 8);
        }
        cpcommit();
        cpwait<0>();
        __syncthreads();
    }
    uint32_t aQh[8][4];
    {
        uint32_t a0 = sb + (wid * 16 + (lane & 15)) * KVROW + (lane >> 4) * 16;
#pragma unroll
        for (int kc = 0; kc < 8; kc++)
            ldsm4(aQh[kc], a0 + kc * 32);
    }
    __syncthreads();

    float oacc[16][4];
#pragma unroll
    for (int f = 0; f < 16; f++)
#pragma unroll
        for (int r = 0; r < 4; r++) oacc[f][r] = 0.0f;
    float m0 = -1e30f, m1 = -1e30f, l0 = 0.0f, l1 = 0.0f;

    const int nt = (PAST + q0 + AT_TQ) / AT_TK;
    const h16* ksrc = kch + (size_t)kvh * KVLEN * HD;
    const h16* vsrc = vch + (size_t)kvh * KVLEN * HD;

    {
        for (int i = tid; i < 2048; i += 128) {
            int p = i >> 10, row = (i >> 4) & 63, seg = i & 15;
            const h16* s0 = p ? vsrc : ksrc;
            cp16(sb + p * KVPLANE + row * KVROW + seg * 16,
                 s0 + (size_t)row * HD + seg * 8);
        }
        cpcommit();
    }

    const int rowselB = (lane & 7) + (lane >> 4) * 8;
    const int halfB = (lane >> 3) & 1;
    const int rowV = lane & 15;
    const int halfV = (lane >> 4) * 16;

    for (int t = 0; t < nt; t++) {
        __syncthreads();
        if (t + 1 < nt) {
            int j1 = (t + 1) * AT_TK;
            uint32_t db = sb + ((t + 1) & 1) * TILEBUF;
            for (int i = tid; i < 2048; i += 128) {
                int p = i >> 10, row = (i >> 4) & 63, seg = i & 15;
                const h16* s0 = p ? vsrc : ksrc;
                cp16(db + p * KVPLANE + row * KVROW + seg * 16,
                     s0 + (size_t)(j1 + row) * HD + seg * 8);
            }
            cpcommit();
            cpwait<1>();
        } else {
            cpwait<0>();
        }
        __syncthreads();

        const uint32_t kb = sb + (t & 1) * TILEBUF;
        const int j0 = t * AT_TK;

        float sacc[8][4];
#pragma unroll
        for (int j = 0; j < 8; j++)
#pragma unroll
            for (int r = 0; r < 4; r++) sacc[j][r] = 0.0f;
#pragma unroll
        for (int kc = 0; kc < 8; kc++) {
#pragma unroll
            for (int nj = 0; nj < 4; nj++) {
                uint32_t kh[4];
                ldsm4(kh, kb + (nj * 16 + rowselB) * KVROW + halfB * 16 + kc * 32);
                mma_f16(sacc[2 * nj],     aQh[kc], kh);
                mma_f16(sacc[2 * nj + 1], aQh[kc], kh + 2);
            }
        }

        if (j0 + AT_TK - 1 > PAST + q0 + wid * 16) {
            int r0g = PAST + q0 + wid * 16 + (lane >> 2);
#pragma unroll
            for (int j = 0; j < 8; j++) {
                int cg = j0 + j * 8 + (lane & 3) * 2;
                if (cg > r0g)     sacc[j][0] = -1e30f;
                if (cg + 1 > r0g) sacc[j][1] = -1e30f;
                if (cg > r0g + 8)     sacc[j][2] = -1e30f;
                if (cg + 1 > r0g + 8) sacc[j][3] = -1e30f;
            }
        }

        float t0 = -1e30f, t1 = -1e30f;
#pragma unroll
        for (int j = 0; j < 8; j++) {
            t0 = fmaxf(t0, fmaxf(sacc[j][0], sacc[j][1]));
            t1 = fmaxf(t1, fmaxf(sacc[j][2], sacc[j][3]));
        }
        t0 = fmaxf(t0, __shfl_xor_sync(0xffffffffu, t0, 1));
        t0 = fmaxf(t0, __shfl_xor_sync(0xffffffffu, t0, 2));
        t1 = fmaxf(t1, __shfl_xor_sync(0xffffffffu, t1, 1));
        t1 = fmaxf(t1, __shfl_xor_sync(0xffffffffu, t1, 2));
        float mn0 = fmaxf(m0, t0), mn1 = fmaxf(m1, t1);
        float c0 = ex2(m0 - mn0), c1 = ex2(m1 - mn1);
        m0 = mn0; m1 = mn1;
        float ps0 = 0.0f, ps1 = 0.0f;
#pragma unroll
        for (int j = 0; j < 8; j++) {
            sacc[j][0] = ex2(sacc[j][0] - mn0); ps0 += sacc[j][0];
            sacc[j][1] = ex2(sacc[j][1] - mn0); ps0 += sacc[j][1];
            sacc[j][2] = ex2(sacc[j][2] - mn1); ps1 += sacc[j][2];
            sacc[j][3] = ex2(sacc[j][3] - mn1); ps1 += sacc[j][3];
        }
        ps0 += __shfl_xor_sync(0xffffffffu, ps0, 1);
        ps0 += __shfl_xor_sync(0xffffffffu, ps0, 2);
        ps1 += __shfl_xor_sync(0xffffffffu, ps1, 1);
        ps1 += __shfl_xor_sync(0xffffffffu, ps1, 2);
        l0 = l0 * c0 + ps0;
        l1 = l1 * c1 + ps1;

        // skip rescale when no row-max moved (bit-identical: x*1.0 == x)
        unsigned need = __ballot_sync(0xffffffffu, (c0 != 1.0f) || (c1 != 1.0f));
        if (need) {
#pragma unroll
            for (int f = 0; f < 16; f++) {
                oacc[f][0] *= c0; oacc[f][1] *= c0;
                oacc[f][2] *= c1; oacc[f][3] *= c1;
            }
        }

        uint32_t pP[4][4];
#pragma unroll
        for (int kc = 0; kc < 4; kc++) {
            pP[kc][0] = cvt2h(sacc[2 * kc][0],     sacc[2 * kc][1]);
            pP[kc][1] = cvt2h(sacc[2 * kc][2],     sacc[2 * kc][3]);
            pP[kc][2] = cvt2h(sacc[2 * kc + 1][0], sacc[2 * kc + 1][1]);
            pP[kc][3] = cvt2h(sacc[2 * kc + 1][2], sacc[2 * kc + 1][3]);
        }

        const uint32_t vb = kb + KVPLANE;
#pragma unroll
        for (int kc = 0; kc < 4; kc++) {
#pragma unroll
            for (int dj = 0; dj < 8; dj++) {
                uint32_t vh[4];
                ldsm4t(vh, vb + (kc * 16 + rowV) * KVROW + dj * 32 + halfV);
                mma_f16(oacc[2 * dj],     pP[kc], vh);
                mma_f16(oacc[2 * dj + 1], pP[kc], vh + 2);
            }
        }
    }

    float inv0 = 1.0f / l0, inv1 = 1.0f / l1;
    int r0 = q0 + wid * 16 + (lane >> 2);
#pragma unroll
    for (int f = 0; f < 16; f++) {
        int d = f * 8 + (lane & 3) * 2;
        size_t e0 = (size_t)r0 * (NH * HD) + h * HD + d;
        size_t e1 = e0 + (size_t)8 * (NH * HD);
        *(uint32_t*)(aoh + e0) = cvt2h(oacc[f][0] * inv0, oacc[f][1] * inv0);
        *(uint32_t*)(aoh + e1) = cvt2h(oacc[f][2] * inv1, oacc[f][3] * inv1);
    }
}

// ---------------- launch ----------------
extern "C" void kernel_launch(void* const* d_in, const int* in_sizes, int n_in,
                              void* d_out, int out_size)
{
    const float* hs    = (const float*)d_in[0];
    const float* cosb  = (const float*)d_in[1];
    const float* sinb  = (const float*)d_in[2];
    const float* pastK = (const float*)d_in[4];
    const float* pastV = (const float*)d_in[5];
    const float* Wq    = (const float*)d_in[6];
    const float* Wk    = (const float*)d_in[7];
    const float* Wv    = (const float*)d_in[8];
    const float* Wo    = (const float*)d_in[9];
    const float* qw    = (const float*)d_in[10];
    const float* kw    = (const float*)d_in[11];

    float* out  = (float*)d_out;
    float* newK = out + (size_t)Q * NH * HD;
    float* newV = newK + (size_t)NKV * Q * HD;

    h16 *hsh, *wqh, *wkh, *wvh, *woh;
    h16 *qph, *kph, *vph, *aoh;
    cudaGetSymbolAddress((void**)&hsh, g_hs_h);
    cudaGetSymbolAddress((void**)&wqh, g_wq_h);
    cudaGetSymbolAddress((void**)&wkh, g_wk_h);
    cudaGetSymbolAddress((void**)&wvh, g_wv_h);
    cudaGetSymbolAddress((void**)&woh, g_wo_h);
    cudaGetSymbolAddress((void**)&qph, g_q_h);
    cudaGetSymbolAddress((void**)&kph, g_k_h);
    cudaGetSymbolAddress((void**)&vph, g_v_h);
    cudaGetSymbolAddress((void**)&aoh, g_ao_h);

    cudaFuncSetAttribute(hgemm_qkv, cudaFuncAttributeMaxDynamicSharedMemorySize, QKV_SMEM);
    cudaFuncSetAttribute(hgemm_o, cudaFuncAttributeMaxDynamicSharedMemorySize, HO_SMEM);
    cudaFuncSetAttribute(attn_mma, cudaFuncAttributeMaxDynamicSharedMemorySize, AT_SMEM);

    // merged convert (8 virtual blocks per real block)
    kconv_all<<<2560, 256>>>(hs, hsh, Wq, wqh, Wk, wkh, Wv, wvh, Wo, woh,
                             pastK, kph, pastV, vph);

    // fused QKV projection + RMSNorm + RoPE
    hgemm_qkv<<<dim3(32, Q / 128), 256, QKV_SMEM>>>(
        hsh, wqh, wkh, wvh, cosb, sinb, qw, kw, qph, kph, newK, newV, vph);

    // attention (TQ=64, 2 CTAs/SM)
    attn_mma<<<dim3(NH, Q / AT_TQ), 128, AT_SMEM>>>(qph, kph, vph, aoh);

    // output projection
    hgemm_o<<<dim3(NH * HD / 128, Q / 128), 256, HO_SMEM>>>(aoh, woh, out);
}